// round 9
// baseline (speedup 1.0000x reference)
#include <cuda_runtime.h>
#include <cuda_fp16.h>
#include <math.h>
#include <stdint.h>

#define NE 42
#define NM 8
#define LL 1024
#define DD 768
#define HH 12
#define KK 97
#define FF 256
#define RR 256
#define BBS 4
#define NP 512   /* bs * P */

// ---------------- scratch (device globals; no allocs) ----------------
__device__ float g_emb [BBS*NE*NM*DD];
__device__ float g_as  [BBS*NE*LL*HH];     // TRANSPOSED: [be][l][h]
__device__ float g_t1  [BBS*NE*NM*RR];
__device__ float g_anT [RR*128];
__device__ float g_w   [BBS*NE*KK*NM];
__device__ float g_Th  [BBS*NE*NM*DD];
__device__ float g_Tt  [BBS*NE*NM*DD];
__device__ float g_S3  [BBS*LL*3];
__device__ float g_x   [BBS*NE*NE*3];
__device__ float g_htss[NP*FF];
__device__ float g_Rh  [NP*DD];
__device__ float g_Rt  [NP*DD];
__device__ __align__(16) __half g_hsh [NP*KK*DD];
__device__ __align__(16) __half g_tshi[NP*KK*DD];
__device__ __align__(16) __half g_Bhi [KK*DD*DD];
__device__ float g_part[6*NP*KK];

__device__ __forceinline__ float ftanh(float x)
{
    float e = __expf(2.0f * x);
    return 1.0f - 2.0f / (e + 1.0f);
}

__device__ __forceinline__ void cp16(uint32_t dst, const void* src)
{
    asm volatile("cp.async.cg.shared.global [%0], [%1], 16;" :: "r"(dst), "l"(src));
}

// ---------------- K1: fused prep: gather emb+as (transposed) | antr | S3 ----------------
#define GATHER_BLKS (BBS*NE)
#define ANTR_BLKS   128
#define S3_BLKS     ((BBS*LL)/2)

__global__ __launch_bounds__(256) void k_prep(const float* __restrict__ seq,
                                              const float* __restrict__ att,
                                              const float* __restrict__ mask,
                                              const int* __restrict__ mpos,
                                              const float* __restrict__ attn_net,
                                              const float* __restrict__ Wlin)
{
    int bid = blockIdx.x;
    int tid = threadIdx.x;
    if (bid < GATHER_BLKS) {
        int be = bid;
        int b  = be / NE;
        __shared__ int   spos[NM];
        __shared__ float smk [NM];
        __shared__ float sinv;
        if (tid < NM) {
            int p = mpos[be*NM + tid] + 1;
            p = max(0, min(p, LL-1));
            spos[tid] = p;
            smk[tid]  = mask[be*NM + tid];
        }
        __syncthreads();
        if (tid == 0) {
            float c = 0.f;
            #pragma unroll
            for (int m = 0; m < NM; m++) c += smk[m];
            sinv = 1.0f / fmaxf(c, 1.0f);
        }
        __syncthreads();
        for (int idx = tid; idx < NM*DD; idx += 256) {
            int m = idx / DD, d = idx - m*DD;
            g_emb[be*NM*DD + idx] = seq[(b*LL + spos[m])*DD + d] * smk[m];
        }
        for (int idx = tid; idx < HH*LL; idx += 256) {
            int h = idx / LL, l = idx - h*LL;
            float acc = 0.f;
            #pragma unroll
            for (int m = 0; m < NM; m++)
                acc += att[((b*HH + h)*LL + spos[m])*LL + l] * smk[m];
            g_as[((size_t)be*LL + l)*HH + h] = acc * sinv;
        }
    } else if (bid < GATHER_BLKS + ANTR_BLKS) {
        int idx = (bid - GATHER_BLKS)*256 + tid;
        int j = idx >> 7, k = idx & 127;
        g_anT[idx] = (k < KK) ? attn_net[k*RR + j] : 0.f;
    } else {
        int rp = bid - GATHER_BLKS - ANTR_BLKS;
        int half = tid >> 7;
        int t2 = tid & 127;
        int row = rp*2 + half;
        const float* s = seq + (size_t)row*DD;
        float a0 = 0.f, a1 = 0.f, a2 = 0.f;
        for (int j = t2; j < DD; j += 128) {
            float v = s[j];
            a0 += v*Wlin[j*3+0]; a1 += v*Wlin[j*3+1]; a2 += v*Wlin[j*3+2];
        }
        __shared__ float red[2][3][128];
        red[half][0][t2] = a0; red[half][1][t2] = a1; red[half][2][t2] = a2;
        __syncthreads();
        for (int s2 = 64; s2 > 0; s2 >>= 1) {
            if (t2 < s2) {
                red[half][0][t2] += red[half][0][t2+s2];
                red[half][1][t2] += red[half][1][t2+s2];
                red[half][2][t2] += red[half][2][t2+s2];
            }
            __syncthreads();
        }
        if (t2 < 3) g_S3[row*3 + t2] = red[half][t2][0];
    }
}

// ---------------- cp.async double-buffered SGEMM (64x64x32) — for t1 ----------------
__global__ __launch_bounds__(256) void sgemm_ca(const float* __restrict__ A, int lda,
                                                const float* __restrict__ B, int ldb,
                                                const float* __restrict__ bias,
                                                float* __restrict__ C, int ldc,
                                                int Kd, int act)
{
    __shared__ float As[2][64][32];
    __shared__ float Bs[2][32][68];
    int m0 = blockIdx.y * 64, n0 = blockIdx.x * 64;
    int tid = threadIdx.x;
    int ty = tid >> 4, tx = tid & 15;
    uint32_t sA = (uint32_t)__cvta_generic_to_shared(&As[0][0][0]);
    uint32_t sB = (uint32_t)__cvta_generic_to_shared(&Bs[0][0][0]);
    float acc[4][4];
    #pragma unroll
    for (int i = 0; i < 4; i++)
        #pragma unroll
        for (int j = 0; j < 4; j++) acc[i][j] = 0.f;

    int nstage = Kd >> 5;
    auto fill = [&](int s, int k0) {
        #pragma unroll
        for (int j = 0; j < 2; j++) {
            int c = tid + j*256;
            int r = c >> 3, q = c & 7;
            cp16(sA + (uint32_t)(s*64*32 + r*32 + q*4)*4,
                 A + (size_t)(m0 + r)*lda + k0 + q*4);
            int rb = c >> 4, qb = c & 15;
            cp16(sB + (uint32_t)(s*32*68 + rb*68 + qb*4)*4,
                 B + (size_t)(k0 + rb)*ldb + n0 + qb*4);
        }
        asm volatile("cp.async.commit_group;");
    };

    fill(0, 0);
    for (int s = 0; s < nstage; s++) {
        if (s + 1 < nstage) {
            fill((s + 1) & 1, (s + 1) << 5);
            asm volatile("cp.async.wait_group 1;");
        } else {
            asm volatile("cp.async.wait_group 0;");
        }
        __syncthreads();
        int bs = s & 1;
        #pragma unroll
        for (int kk = 0; kk < 32; kk++) {
            float a[4], bv[4];
            #pragma unroll
            for (int i = 0; i < 4; i++) a[i]  = As[bs][ty*4 + i][kk];
            #pragma unroll
            for (int j = 0; j < 4; j++) bv[j] = Bs[bs][kk][tx*4 + j];
            #pragma unroll
            for (int i = 0; i < 4; i++)
                #pragma unroll
                for (int j = 0; j < 4; j++) acc[i][j] += a[i]*bv[j];
        }
        __syncthreads();
    }
    #pragma unroll
    for (int i = 0; i < 4; i++) {
        int row = m0 + ty*4 + i;
        #pragma unroll
        for (int j = 0; j < 4; j++) {
            int col = n0 + tx*4 + j;
            float v = acc[i][j];
            if (bias) v += bias[col];
            if (act)  v = ftanh(v);
            C[(size_t)row*ldc + col] = v;
        }
    }
}

// ---------------- dual 64x128 SGEMM, 4x8/thread, swizzled A smem ----------------
// dynamic smem: As 2*64*32 floats (XOR-swizzled cols), Bs 2*32*132 floats
#define DUAL_AS_FLOATS (2*64*32)
#define DUAL_BS_FLOATS (2*32*132)
#define DUAL_SMEM ((DUAL_AS_FLOATS + DUAL_BS_FLOATS)*4)

__global__ __launch_bounds__(256) void sgemm_dual128(const float* __restrict__ A, int lda,
                                                     const float* __restrict__ B0,
                                                     const float* __restrict__ B1, int ldb,
                                                     const float* __restrict__ bias0,
                                                     const float* __restrict__ bias1,
                                                     float* __restrict__ C0,
                                                     float* __restrict__ C1, int ldc,
                                                     int Kd)
{
    extern __shared__ float dsm_f[];
    float* As = dsm_f;                         // [2][64][32] swizzled
    float* Bs = dsm_f + DUAL_AS_FLOATS;        // [2][32][132]
    uint32_t sA = (uint32_t)__cvta_generic_to_shared(As);
    uint32_t sB = (uint32_t)__cvta_generic_to_shared(Bs);

    int hx = gridDim.x >> 1;
    int half = blockIdx.x >= hx;
    const float* B    = half ? B1    : B0;
    const float* bias = half ? bias1 : bias0;
    float*       C    = half ? C1    : C0;
    int n0 = (blockIdx.x - half*hx) * 128;
    int m0 = blockIdx.y * 64;
    int tid = threadIdx.x;
    int ty = tid >> 4, tx = tid & 15;

    float acc[4][8];
    #pragma unroll
    for (int i = 0; i < 4; i++)
        #pragma unroll
        for (int j = 0; j < 8; j++) acc[i][j] = 0.f;

    int nstage = Kd >> 5;
    auto fill = [&](int s, int k0) {
        // A: 64x32 = 512 float4, 2/thread, col swizzled by (r&7)<<2
        #pragma unroll
        for (int j = 0; j < 2; j++) {
            int c = tid + j*256;
            int r = c >> 3, q = c & 7;
            int col = (q*4) ^ ((r & 7) << 2);
            cp16(sA + (uint32_t)(s*64*32 + r*32 + col)*4,
                 A + (size_t)(m0 + r)*lda + k0 + q*4);
        }
        // B: 32x128 = 1024 float4, 4/thread
        #pragma unroll
        for (int j = 0; j < 4; j++) {
            int c = tid + j*256;
            int rb = c >> 5, qb = c & 31;
            cp16(sB + (uint32_t)(s*32*132 + rb*132 + qb*4)*4,
                 B + (size_t)(k0 + rb)*ldb + n0 + qb*4);
        }
        asm volatile("cp.async.commit_group;");
    };

    fill(0, 0);
    for (int s = 0; s < nstage; s++) {
        if (s + 1 < nstage) {
            fill((s + 1) & 1, (s + 1) << 5);
            asm volatile("cp.async.wait_group 1;");
        } else {
            asm volatile("cp.async.wait_group 0;");
        }
        __syncthreads();
        int bs = s & 1;
        #pragma unroll
        for (int kk = 0; kk < 32; kk++) {
            float a[4], bv[8];
            #pragma unroll
            for (int i = 0; i < 4; i++) {
                int row = ty*4 + i;
                a[i] = As[bs*64*32 + row*32 + (kk ^ ((row & 7) << 2))];
            }
            #pragma unroll
            for (int j = 0; j < 8; j++) bv[j] = Bs[bs*32*132 + kk*132 + tx*8 + j];
            #pragma unroll
            for (int i = 0; i < 4; i++)
                #pragma unroll
                for (int j = 0; j < 8; j++) acc[i][j] += a[i]*bv[j];
        }
        __syncthreads();
    }
    #pragma unroll
    for (int i = 0; i < 4; i++) {
        int row = m0 + ty*4 + i;
        #pragma unroll
        for (int j = 0; j < 8; j++) {
            int col = n0 + tx*8 + j;
            float v = acc[i][j];
            if (bias) v += bias[col];
            C[(size_t)row*ldc + col] = v;
        }
    }
}

// ---------------- fused scores + softmax over mentions ----------------
__global__ __launch_bounds__(128) void k_scsm(const float* __restrict__ mask)
{
    int be = blockIdx.x;
    int tid = threadIdx.x;
    __shared__ float st[NM*RR];
    for (int i = tid; i < NM*RR/4; i += 128)
        *(float4*)&st[i*4] = *(const float4*)&g_t1[(size_t)be*NM*RR + i*4];
    __syncthreads();
    if (tid >= KK) return;
    float sc[NM];
    #pragma unroll
    for (int m = 0; m < NM; m++)
        sc[m] = (1.0f - mask[be*NM + m]) * (-1e6f);
    for (int j = 0; j < RR; j++) {
        float a = g_anT[j*128 + tid];
        #pragma unroll
        for (int m = 0; m < NM; m++) sc[m] += st[m*RR + j] * a;
    }
    float mx = sc[0];
    #pragma unroll
    for (int m = 1; m < NM; m++) mx = fmaxf(mx, sc[m]);
    float ssum = 0.f;
    #pragma unroll
    for (int m = 0; m < NM; m++) { sc[m] = expf(sc[m] - mx); ssum += sc[m]; }
    float inv = 1.0f / ssum;
    #pragma unroll
    for (int m = 0; m < NM; m++) g_w[(be*KK + tid)*NM + m] = sc[m]*inv;
}

// ---------------- K7: ht + norm + x; idle blocks convert B->fp16 ----------------
#define BCONV_BLOCKS (861*BBS)
#define BCONV_N4     ((size_t)KK*DD*DD/4)
#define BCONV_CHUNK  ((BCONV_N4 + BCONV_BLOCKS - 1)/BCONV_BLOCKS)

__global__ __launch_bounds__(256) void k_htx(const float* __restrict__ blin,
                                             const float* __restrict__ bil)
{
    int b = blockIdx.y;
    int i = blockIdx.x / NE, j = blockIdx.x % NE;
    int tid = threadIdx.x;
    if (j < i) {
        size_t q = (size_t)b*861 + (size_t)i*(i-1)/2 + j;
        size_t beg = q*BCONV_CHUNK;
        size_t end = beg + BCONV_CHUNK;
        if (end > BCONV_N4) end = BCONV_N4;
        __half2* ph = (__half2*)g_Bhi;
        for (size_t i4 = beg + tid; i4 < end; i4 += 256) {
            float4 v = ((const float4*)bil)[i4];
            ph[i4*2+0] = __floats2half2_rn(v.x, v.y);
            ph[i4*2+1] = __floats2half2_rn(v.z, v.w);
        }
        return;
    }
    const float* ai = g_as + ((size_t)(b*NE + i))*LL*HH;
    const float* aj = g_as + ((size_t)(b*NE + j))*LL*HH;
    const float* s3 = g_S3 + b*LL*3;
    float sum = 0.f, x0 = 0.f, x1 = 0.f, x2 = 0.f;
    for (int l = tid; l < LL; l += 256) {
        float4 u0 = *(const float4*)&ai[l*HH + 0];
        float4 u1 = *(const float4*)&ai[l*HH + 4];
        float4 u2 = *(const float4*)&ai[l*HH + 8];
        float4 v0 = *(const float4*)&aj[l*HH + 0];
        float4 v1 = *(const float4*)&aj[l*HH + 4];
        float4 v2 = *(const float4*)&aj[l*HH + 8];
        float acc = u0.x*v0.x + u0.y*v0.y + u0.z*v0.z + u0.w*v0.w
                  + u1.x*v1.x + u1.y*v1.y + u1.z*v1.z + u1.w*v1.w
                  + u2.x*v2.x + u2.y*v2.y + u2.z*v2.z + u2.w*v2.w;
        acc *= (1.0f / HH);
        sum += acc;
        x0 += acc * s3[l*3+0];
        x1 += acc * s3[l*3+1];
        x2 += acc * s3[l*3+2];
    }
    __shared__ float red[4][256];
    red[0][tid] = sum; red[1][tid] = x0; red[2][tid] = x1; red[3][tid] = x2;
    __syncthreads();
    for (int s2 = 128; s2 > 0; s2 >>= 1) {
        if (tid < s2) {
            red[0][tid] += red[0][tid+s2];
            red[1][tid] += red[1][tid+s2];
            red[2][tid] += red[2][tid+s2];
            red[3][tid] += red[3][tid+s2];
        }
        __syncthreads();
    }
    if (tid == 0) {
        float inv = 1.0f / (red[0][0] + 1e-5f);
        float v0 = red[1][0]*inv + blin[0];
        float v1 = red[2][0]*inv + blin[1];
        float v2 = red[3][0]*inv + blin[2];
        float* xo = g_x + ((b*NE + i)*NE + j)*3;
        xo[0] = v0; xo[1] = v1; xo[2] = v2;
        float* xm = g_x + ((b*NE + j)*NE + i)*3;
        xm[0] = v0; xm[1] = v1; xm[2] = v2;
    }
}

// ---------------- K8: 3x3 conv + relu at pair positions ----------------
__global__ void k_htss(const int* __restrict__ pairs, const float* __restrict__ Wseg,
                       const float* __restrict__ bseg)
{
    int n = blockIdx.x;
    int b = n >> 7;
    int tid = threadIdx.x;
    __shared__ int shi, sti;
    __shared__ float sx[27];
    if (tid == 0) { shi = pairs[n*2]; sti = pairs[n*2+1]; }
    __syncthreads();
    if (tid < 27) {
        int dy = tid / 9, dx = (tid / 3) % 3, c = tid % 3;
        int ii = shi + dy - 1, jj = sti + dx - 1;
        sx[tid] = (ii >= 0 && ii < NE && jj >= 0 && jj < NE)
                  ? g_x[((b*NE + ii)*NE + jj)*3 + c] : 0.f;
    }
    __syncthreads();
    float acc = bseg[tid];
    #pragma unroll
    for (int t = 0; t < 27; t++) acc += sx[t] * Wseg[t*FF + tid];
    g_htss[n*FF + tid] = fmaxf(acc, 0.f);
}

// ---------------- K10: hs,ts -> fp16 ----------------
__global__ __launch_bounds__(256) void k_hsts(const int* __restrict__ pairs)
{
    int n = blockIdx.x;
    int b = n >> 7;
    int tid = threadIdx.x;
    __shared__ float sT[2*NM*DD];
    int hi = pairs[n*2], ti = pairs[n*2+1];
    const float* Th = g_Th + (b*NE + hi)*NM*DD;
    const float* Tt = g_Tt + (b*NE + ti)*NM*DD;
    for (int idx = tid; idx < NM*DD; idx += 256) {
        sT[idx]         = Th[idx];
        sT[NM*DD + idx] = Tt[idx];
    }
    float rh[3], rt[3];
    #pragma unroll
    for (int i2 = 0; i2 < 3; i2++) {
        rh[i2] = g_Rh[n*DD + tid + i2*256];
        rt[i2] = g_Rt[n*DD + tid + i2*256];
    }
    __syncthreads();
    const float* wh = g_w + (b*NE + hi)*KK*NM;
    const float* wt = g_w + (b*NE + ti)*KK*NM;
    for (int k = 0; k < KK; k++) {
        float whr[NM], wtr[NM];
        #pragma unroll
        for (int m = 0; m < NM; m++) {
            whr[m] = __ldg(&wh[k*NM + m]);
            wtr[m] = __ldg(&wt[k*NM + m]);
        }
        #pragma unroll
        for (int i2 = 0; i2 < 3; i2++) {
            int d = tid + i2*256;
            float ah = rh[i2], at2 = rt[i2];
            #pragma unroll
            for (int m = 0; m < NM; m++) {
                ah  += whr[m] * sT[m*DD + d];
                at2 += wtr[m] * sT[NM*DD + m*DD + d];
            }
            size_t o = (size_t)(n*KK + k)*DD + d;
            g_hsh[o]  = __float2half_rn(ftanh(ah));
            g_tshi[o] = __float2half_rn(ftanh(at2));
        }
    }
}

// ================= HMMA bilinear core, 3-stage pipeline =================
#define SW128(o) ((o) ^ (((o) >> 3) & 0x70))
#define TILE_BYTES 16384
#define SH_PITCH 132
#define SMEM_DYN (3*2*TILE_BYTES + 1024)

__device__ __forceinline__ void ldm4(uint32_t* r, uint32_t addr)
{
    asm volatile("ldmatrix.sync.aligned.m8n8.x4.shared.b16 {%0,%1,%2,%3}, [%4];"
                 : "=r"(r[0]), "=r"(r[1]), "=r"(r[2]), "=r"(r[3]) : "r"(addr));
}
__device__ __forceinline__ void mma16816(float* c, const uint32_t* a, const uint32_t* b)
{
    asm volatile("mma.sync.aligned.m16n8k16.row.col.f32.f16.f16.f32 "
                 "{%0,%1,%2,%3}, {%4,%5,%6,%7}, {%8,%9}, {%0,%1,%2,%3};"
                 : "+f"(c[0]), "+f"(c[1]), "+f"(c[2]), "+f"(c[3])
                 : "r"(a[0]), "r"(a[1]), "r"(a[2]), "r"(a[3]), "r"(b[0]), "r"(b[1]));
}

__global__ __launch_bounds__(256) void k_bilinear_mma()
{
    extern __shared__ char dsm[];
    char* smem = (char*)((((uintptr_t)dsm) + 1023) & ~(uintptr_t)1023);
    uint32_t sbase = (uint32_t)__cvta_generic_to_shared(smem);

    const int k  = blockIdx.y;
    const int nt = blockIdx.x & 3;
    const int dt = blockIdx.x >> 2;
    const int n0 = nt * 128, d0 = dt * 128;
    const int tid = threadIdx.x;
    const int lane = tid & 31, wid = tid >> 5;
    const int wm = (wid & 3) * 32;
    const int wn = (wid >> 2) * 64;

    const __half* Abase = g_tshi + ((size_t)n0 * KK + k) * DD;
    const __half* Bbase = g_Bhi + ((size_t)k * DD + d0) * DD;

    float acc[2][8][4];
    #pragma unroll
    for (int mi = 0; mi < 2; mi++)
        #pragma unroll
        for (int ni = 0; ni < 8; ni++)
            #pragma unroll
            for (int j = 0; j < 4; j++) acc[mi][ni][j] = 0.f;

    auto fill = [&](int it, int buf) {
        int k0 = it * 64;
        uint32_t abase = sbase + buf*2*TILE_BYTES;
        uint32_t bbase = abase + TILE_BYTES;
        #pragma unroll
        for (int j = 0; j < 8; j++) {
            int c = tid + j*256;
            if (c < 1024) {
                int r = c >> 3, q = c & 7;
                cp16(abase + SW128(r*128 + q*16), Abase + (size_t)r*(KK*DD) + k0 + q*8);
            } else {
                int c2 = c - 1024;
                int r = c2 >> 3, q = c2 & 7;
                cp16(bbase + SW128(r*128 + q*16), Bbase + (size_t)r*DD + k0 + q*8);
            }
        }
        asm volatile("cp.async.commit_group;");
    };

    fill(0, 0);
    fill(1, 1);

    for (int i = 0; i < 12; i++) {
        if (i < 11) {
            asm volatile("cp.async.wait_group 1;");
        } else {
            asm volatile("cp.async.wait_group 0;");
        }
        __syncthreads();               // stage i visible; buffer (i+2)%3 free
        if (i + 2 < 12) fill(i + 2, (i + 2) % 3);

        uint32_t abase = sbase + (uint32_t)((i % 3)*2*TILE_BYTES);
        uint32_t bbase = abase + TILE_BYTES;
        #pragma unroll
        for (int ks = 0; ks < 4; ks++) {
            uint32_t af[2][4];
            #pragma unroll
            for (int mi = 0; mi < 2; mi++) {
                int row = wm + mi*16 + ((lane >> 3) & 1)*8 + (lane & 7);
                int cb  = ks*32 + (lane >> 4)*16;
                ldm4(af[mi], abase + SW128(row*128 + cb));
            }
            uint32_t bf[8][2];
            #pragma unroll
            for (int q = 0; q < 4; q++) {
                uint32_t r[4];
                int nrow = wn + (2*q + (lane >> 4))*8 + (lane & 7);
                int cb   = ks*32 + ((lane >> 3) & 1)*16;
                ldm4(r, bbase + SW128(nrow*128 + cb));
                bf[2*q+0][0] = r[0]; bf[2*q+0][1] = r[1];
                bf[2*q+1][0] = r[2]; bf[2*q+1][1] = r[3];
            }
            #pragma unroll
            for (int mi = 0; mi < 2; mi++)
                #pragma unroll
                for (int ni = 0; ni < 8; ni++)
                    mma16816(acc[mi][ni], af[mi], bf[ni]);
        }
    }
    __syncthreads();   // all compute done before smem reuse

    // ---- epilogue: partial[n] = sum_d C[n][d]*hs[n][d] ----
    float* sH  = (float*)smem;
    float* red = (float*)(smem + 128*SH_PITCH*4);
    for (int idx = tid; idx < 128*16; idx += 256) {
        int r = idx >> 4, c8 = idx & 15;
        const __half2* hp = (const __half2*)(g_hsh + ((size_t)(n0 + r)*KK + k)*DD + d0 + c8*8);
        float* dst = &sH[r*SH_PITCH + c8*8];
        #pragma unroll
        for (int u = 0; u < 4; u++) {
            float2 f = __half22float2(hp[u]);
            dst[u*2+0] = f.x; dst[u*2+1] = f.y;
        }
    }
    __syncthreads();

    float p[2][2] = {{0.f, 0.f}, {0.f, 0.f}};
    #pragma unroll
    for (int mi = 0; mi < 2; mi++) {
        int r0 = wm + mi*16 + (lane >> 2);
        #pragma unroll
        for (int ni = 0; ni < 8; ni++) {
            int cb = wn + ni*8 + (lane & 3)*2;
            p[mi][0] += acc[mi][ni][0]*sH[r0*SH_PITCH + cb]
                      + acc[mi][ni][1]*sH[r0*SH_PITCH + cb + 1];
            p[mi][1] += acc[mi][ni][2]*sH[(r0+8)*SH_PITCH + cb]
                      + acc[mi][ni][3]*sH[(r0+8)*SH_PITCH + cb + 1];
        }
    }
    #pragma unroll
    for (int mi = 0; mi < 2; mi++)
        #pragma unroll
        for (int h = 0; h < 2; h++) {
            p[mi][h] += __shfl_xor_sync(0xffffffffu, p[mi][h], 1);
            p[mi][h] += __shfl_xor_sync(0xffffffffu, p[mi][h], 2);
        }
    if ((lane & 3) == 0) {
        int nw = wid >> 2;
        int rr = lane >> 2;
        #pragma unroll
        for (int mi = 0; mi < 2; mi++) {
            red[(wm + mi*16 + rr)*2 + nw]     = p[mi][0];
            red[(wm + mi*16 + rr + 8)*2 + nw] = p[mi][1];
        }
    }
    __syncthreads();
    if (tid < 128)
        g_part[((size_t)dt*NP + n0 + tid)*KK + k] = red[tid*2] + red[tid*2+1];
}

// ---------------- K13: finalize ----------------
__global__ void k_final(const float* __restrict__ bilb, float* __restrict__ out)
{
    int idx = blockIdx.x*256 + threadIdx.x;
    if (idx >= NP*KK) return;
    int k = idx % KK;
    float s = bilb[k];
    #pragma unroll
    for (int t = 0; t < 6; t++) s += g_part[t*(NP*KK) + idx];
    out[idx] = s;
}

// ---------------- launch ----------------
extern "C" void kernel_launch(void* const* d_in, const int* in_sizes, int n_in,
                              void* d_out, int out_size)
{
    const float* seq      = (const float*)d_in[0];
    const float* att      = (const float*)d_in[1];
    const float* mask     = (const float*)d_in[2];
    const int*   mpos     = (const int*)  d_in[3];
    const int*   pairs    = (const int*)  d_in[4];
    const float* Wattn    = (const float*)d_in[5];
    const float* battn    = (const float*)d_in[6];
    const float* attn_net = (const float*)d_in[7];
    const float* Wlin     = (const float*)d_in[8];
    const float* blin     = (const float*)d_in[9];
    const float* Wseg     = (const float*)d_in[10];
    const float* bseg     = (const float*)d_in[11];
    const float* Whead    = (const float*)d_in[12];
    const float* bhead    = (const float*)d_in[13];
    const float* Wtail    = (const float*)d_in[14];
    const float* btail    = (const float*)d_in[15];
    const float* bil      = (const float*)d_in[16];
    const float* bilb     = (const float*)d_in[17];
    float* out = (float*)d_out;

    float *emb, *t1, *htss, *Th, *Tt, *Rh, *Rt;
    cudaGetSymbolAddress((void**)&emb,  g_emb);
    cudaGetSymbolAddress((void**)&t1,   g_t1);
    cudaGetSymbolAddress((void**)&htss, g_htss);
    cudaGetSymbolAddress((void**)&Th,   g_Th);
    cudaGetSymbolAddress((void**)&Tt,   g_Tt);
    cudaGetSymbolAddress((void**)&Rh,   g_Rh);
    cudaGetSymbolAddress((void**)&Rt,   g_Rt);

    cudaFuncSetAttribute(k_bilinear_mma, cudaFuncAttributeMaxDynamicSharedMemorySize, SMEM_DYN);
    cudaFuncSetAttribute(sgemm_dual128, cudaFuncAttributeMaxDynamicSharedMemorySize, DUAL_SMEM);

    // 1. fused prep: gather | antn transpose | S3
    k_prep<<<GATHER_BLKS + ANTR_BLKS + S3_BLKS, 256>>>(seq, att, mask, mpos, attn_net, Wlin);
    // 2. t1 = tanh(emb @ Wattn + battn)
    sgemm_ca<<<dim3(RR/64, (BBS*NE*NM)/64), 256>>>(emb, DD, Wattn, RR, battn, t1, RR, DD, 1);
    // 3. fused scores + softmax
    k_scsm<<<BBS*NE, 128>>>(mask);
    // 4/5. T_h / T_t merged (64x128 tiles)
    sgemm_dual128<<<dim3(2*(DD/128), (BBS*NE*NM)/64), 256, DUAL_SMEM>>>(
        emb, DD, Whead, Wtail, DD, nullptr, nullptr, Th, Tt, DD, DD);
    // 6/7. ht -> x  (idle blocks convert bilinear weights to fp16)
    k_htx<<<dim3(NE*NE, BBS), 256>>>(blin, bil);
    // 8. conv + relu at pairs
    k_htss<<<NP, 256>>>(pairs, Wseg, bseg);
    // 9. Rh / Rt merged
    sgemm_dual128<<<dim3(2*(DD/128), NP/64), 256, DUAL_SMEM>>>(
        htss, FF, Whead + DD*DD, Wtail + DD*DD, DD, bhead, btail, Rh, Rt, DD, FF);
    // 10. hs,ts fp16
    k_hsts<<<NP, 256>>>(pairs);
    // 11. HMMA bilinear: grid (24 tiles, 97 k), fp16 single pass, 3-stage pipe
    k_bilinear_mma<<<dim3(24, 97), 256, SMEM_DYN>>>();
    // 12. finalize
    k_final<<<(NP*KK + 255)/256, 256>>>(bilb, out);
}

// round 10
// speedup vs baseline: 1.1013x; 1.1013x over previous
#include <cuda_runtime.h>
#include <cuda_fp16.h>
#include <math.h>
#include <stdint.h>

#define NE 42
#define NM 8
#define LL 1024
#define DD 768
#define HH 12
#define KK 97
#define FF 256
#define RR 256
#define BBS 4
#define NP 512   /* bs * P */

// ---------------- scratch (device globals; no allocs) ----------------
__device__ float g_emb [BBS*NE*NM*DD];
__device__ float g_as  [BBS*NE*LL*HH];     // TRANSPOSED: [be][l][h]
__device__ float g_t1  [BBS*NE*NM*RR];
__device__ float g_anT [RR*128];
__device__ float g_w   [BBS*NE*KK*NM];
__device__ float g_Th  [BBS*NE*NM*DD];
__device__ float g_Tt  [BBS*NE*NM*DD];
__device__ float g_S3  [BBS*LL*3];
__device__ float g_x   [BBS*NE*NE*3];
__device__ float g_htss[NP*FF];
__device__ float g_Rh  [NP*DD];
__device__ float g_Rt  [NP*DD];
__device__ __align__(16) __half g_hsh [NP*KK*DD];
__device__ __align__(16) __half g_tshi[NP*KK*DD];
__device__ __align__(16) __half g_Bhi [KK*DD*DD];
__device__ float g_part[6*NP*KK];

__device__ __forceinline__ float ftanh(float x)
{
    float e = __expf(2.0f * x);
    return 1.0f - 2.0f / (e + 1.0f);
}

__device__ __forceinline__ void cp16(uint32_t dst, const void* src)
{
    asm volatile("cp.async.cg.shared.global [%0], [%1], 16;" :: "r"(dst), "l"(src));
}

// ---------------- K1: fused prep: gather emb+as (transposed) | antr | S3 ----------------
#define GATHER_BLKS (BBS*NE)
#define ANTR_BLKS   128
#define S3_BLKS     ((BBS*LL)/2)

__global__ __launch_bounds__(256) void k_prep(const float* __restrict__ seq,
                                              const float* __restrict__ att,
                                              const float* __restrict__ mask,
                                              const int* __restrict__ mpos,
                                              const float* __restrict__ attn_net,
                                              const float* __restrict__ Wlin)
{
    int bid = blockIdx.x;
    int tid = threadIdx.x;
    if (bid < GATHER_BLKS) {
        int be = bid;
        int b  = be / NE;
        __shared__ int   spos[NM];
        __shared__ float smk [NM];
        __shared__ float sinv;
        if (tid < NM) {
            int p = mpos[be*NM + tid] + 1;
            p = max(0, min(p, LL-1));
            spos[tid] = p;
            smk[tid]  = mask[be*NM + tid];
        }
        __syncthreads();
        if (tid == 0) {
            float c = 0.f;
            #pragma unroll
            for (int m = 0; m < NM; m++) c += smk[m];
            sinv = 1.0f / fmaxf(c, 1.0f);
        }
        __syncthreads();
        for (int idx = tid; idx < NM*DD; idx += 256) {
            int m = idx / DD, d = idx - m*DD;
            g_emb[be*NM*DD + idx] = seq[(b*LL + spos[m])*DD + d] * smk[m];
        }
        for (int idx = tid; idx < HH*LL; idx += 256) {
            int h = idx / LL, l = idx - h*LL;
            float acc = 0.f;
            #pragma unroll
            for (int m = 0; m < NM; m++)
                acc += att[((b*HH + h)*LL + spos[m])*LL + l] * smk[m];
            g_as[((size_t)be*LL + l)*HH + h] = acc * sinv;
        }
    } else if (bid < GATHER_BLKS + ANTR_BLKS) {
        int idx = (bid - GATHER_BLKS)*256 + tid;
        int j = idx >> 7, k = idx & 127;
        g_anT[idx] = (k < KK) ? attn_net[k*RR + j] : 0.f;
    } else {
        int rp = bid - GATHER_BLKS - ANTR_BLKS;
        int half = tid >> 7;
        int t2 = tid & 127;
        int row = rp*2 + half;
        const float* s = seq + (size_t)row*DD;
        float a0 = 0.f, a1 = 0.f, a2 = 0.f;
        for (int j = t2; j < DD; j += 128) {
            float v = s[j];
            a0 += v*Wlin[j*3+0]; a1 += v*Wlin[j*3+1]; a2 += v*Wlin[j*3+2];
        }
        __shared__ float red[2][3][128];
        red[half][0][t2] = a0; red[half][1][t2] = a1; red[half][2][t2] = a2;
        __syncthreads();
        for (int s2 = 64; s2 > 0; s2 >>= 1) {
            if (t2 < s2) {
                red[half][0][t2] += red[half][0][t2+s2];
                red[half][1][t2] += red[half][1][t2+s2];
                red[half][2][t2] += red[half][2][t2+s2];
            }
            __syncthreads();
        }
        if (t2 < 3) g_S3[row*3 + t2] = red[half][t2][0];
    }
}

// ---------------- cp.async double-buffered SGEMM (64x64x32) — for t1 ----------------
__global__ __launch_bounds__(256) void sgemm_ca(const float* __restrict__ A, int lda,
                                                const float* __restrict__ B, int ldb,
                                                const float* __restrict__ bias,
                                                float* __restrict__ C, int ldc,
                                                int Kd, int act)
{
    __shared__ float As[2][64][32];
    __shared__ float Bs[2][32][68];
    int m0 = blockIdx.y * 64, n0 = blockIdx.x * 64;
    int tid = threadIdx.x;
    int ty = tid >> 4, tx = tid & 15;
    uint32_t sA = (uint32_t)__cvta_generic_to_shared(&As[0][0][0]);
    uint32_t sB = (uint32_t)__cvta_generic_to_shared(&Bs[0][0][0]);
    float acc[4][4];
    #pragma unroll
    for (int i = 0; i < 4; i++)
        #pragma unroll
        for (int j = 0; j < 4; j++) acc[i][j] = 0.f;

    int nstage = Kd >> 5;
    auto fill = [&](int s, int k0) {
        #pragma unroll
        for (int j = 0; j < 2; j++) {
            int c = tid + j*256;
            int r = c >> 3, q = c & 7;
            cp16(sA + (uint32_t)(s*64*32 + r*32 + q*4)*4,
                 A + (size_t)(m0 + r)*lda + k0 + q*4);
            int rb = c >> 4, qb = c & 15;
            cp16(sB + (uint32_t)(s*32*68 + rb*68 + qb*4)*4,
                 B + (size_t)(k0 + rb)*ldb + n0 + qb*4);
        }
        asm volatile("cp.async.commit_group;");
    };

    fill(0, 0);
    for (int s = 0; s < nstage; s++) {
        if (s + 1 < nstage) {
            fill((s + 1) & 1, (s + 1) << 5);
            asm volatile("cp.async.wait_group 1;");
        } else {
            asm volatile("cp.async.wait_group 0;");
        }
        __syncthreads();
        int bs = s & 1;
        #pragma unroll
        for (int kk = 0; kk < 32; kk++) {
            float a[4], bv[4];
            #pragma unroll
            for (int i = 0; i < 4; i++) a[i]  = As[bs][ty*4 + i][kk];
            #pragma unroll
            for (int j = 0; j < 4; j++) bv[j] = Bs[bs][kk][tx*4 + j];
            #pragma unroll
            for (int i = 0; i < 4; i++)
                #pragma unroll
                for (int j = 0; j < 4; j++) acc[i][j] += a[i]*bv[j];
        }
        __syncthreads();
    }
    #pragma unroll
    for (int i = 0; i < 4; i++) {
        int row = m0 + ty*4 + i;
        #pragma unroll
        for (int j = 0; j < 4; j++) {
            int col = n0 + tx*4 + j;
            float v = acc[i][j];
            if (bias) v += bias[col];
            if (act)  v = ftanh(v);
            C[(size_t)row*ldc + col] = v;
        }
    }
}

// ---------------- dual SGEMM 64x64, transposed A smem, vectorized LDS.128 ----------------
#define DT_PAD 68
__global__ __launch_bounds__(256) void sgemm_dualT(const float* __restrict__ A, int lda,
                                                   const float* __restrict__ B0,
                                                   const float* __restrict__ B1, int ldb,
                                                   const float* __restrict__ bias0,
                                                   const float* __restrict__ bias1,
                                                   float* __restrict__ C0,
                                                   float* __restrict__ C1, int ldc,
                                                   int Kd)
{
    __shared__ float At[2][32][DT_PAD];    // [kk][row] transposed
    __shared__ float Bs[2][32][DT_PAD];    // [kk][col]
    int hx = gridDim.x >> 1;
    int half = blockIdx.x >= hx;
    const float* B    = half ? B1    : B0;
    const float* bias = half ? bias1 : bias0;
    float*       C    = half ? C1    : C0;
    int n0 = (blockIdx.x - half*hx) * 64;
    int m0 = blockIdx.y * 64;
    int tid = threadIdx.x;
    int ty = tid >> 4, tx = tid & 15;
    uint32_t sB = (uint32_t)__cvta_generic_to_shared(&Bs[0][0][0]);

    float acc[4][4];
    #pragma unroll
    for (int i = 0; i < 4; i++)
        #pragma unroll
        for (int j = 0; j < 4; j++) acc[i][j] = 0.f;

    int nstage = Kd >> 5;
    const int ar = tid >> 3;            // A row this thread loads (0..31 / +32)
    const int aq = tid & 7;             // 16B chunk within row
    float4 areg[2];

    auto ldgA = [&](int k0) {
        areg[0] = *(const float4*)(A + (size_t)(m0 + ar)*lda + k0 + aq*4);
        areg[1] = *(const float4*)(A + (size_t)(m0 + ar + 32)*lda + k0 + aq*4);
    };
    auto stsA = [&](int s) {
        #pragma unroll
        for (int j = 0; j < 2; j++) {
            int r = ar + j*32;
            At[s][aq*4+0][r] = areg[j].x;
            At[s][aq*4+1][r] = areg[j].y;
            At[s][aq*4+2][r] = areg[j].z;
            At[s][aq*4+3][r] = areg[j].w;
        }
    };
    auto cpB = [&](int s, int k0) {
        #pragma unroll
        for (int j = 0; j < 2; j++) {
            int c = tid + j*256;
            int rb = c >> 4, qb = c & 15;
            cp16(sB + (uint32_t)(s*32*DT_PAD + rb*DT_PAD + qb*4)*4,
                 B + (size_t)(k0 + rb)*ldb + n0 + qb*4);
        }
        asm volatile("cp.async.commit_group;");
    };

    // prologue
    cpB(0, 0);
    ldgA(0);
    stsA(0);
    asm volatile("cp.async.wait_group 0;");
    __syncthreads();

    for (int s = 0; s < nstage; s++) {
        int bs = s & 1;
        if (s + 1 < nstage) {
            cpB(bs ^ 1, (s + 1) << 5);
            ldgA((s + 1) << 5);
        }
        #pragma unroll
        for (int kk = 0; kk < 32; kk++) {
            float4 a4 = *(const float4*)&At[bs][kk][ty*4];
            float4 b4 = *(const float4*)&Bs[bs][kk][tx*4];
            acc[0][0] += a4.x*b4.x; acc[0][1] += a4.x*b4.y; acc[0][2] += a4.x*b4.z; acc[0][3] += a4.x*b4.w;
            acc[1][0] += a4.y*b4.x; acc[1][1] += a4.y*b4.y; acc[1][2] += a4.y*b4.z; acc[1][3] += a4.y*b4.w;
            acc[2][0] += a4.z*b4.x; acc[2][1] += a4.z*b4.y; acc[2][2] += a4.z*b4.z; acc[2][3] += a4.z*b4.w;
            acc[3][0] += a4.w*b4.x; acc[3][1] += a4.w*b4.y; acc[3][2] += a4.w*b4.z; acc[3][3] += a4.w*b4.w;
        }
        __syncthreads();                 // all reads of buffer bs done
        if (s + 1 < nstage) {
            stsA(bs ^ 1);
            asm volatile("cp.async.wait_group 0;");
        }
        __syncthreads();                 // buffer bs^1 (A sts + B cp.async) visible
    }
    #pragma unroll
    for (int i = 0; i < 4; i++) {
        int row = m0 + ty*4 + i;
        #pragma unroll
        for (int j = 0; j < 4; j++) {
            int col = n0 + tx*4 + j;
            float v = acc[i][j];
            if (bias) v += bias[col];
            C[(size_t)row*ldc + col] = v;
        }
    }
}

// ---------------- fused scores + softmax over mentions ----------------
__global__ __launch_bounds__(128) void k_scsm(const float* __restrict__ mask)
{
    int be = blockIdx.x;
    int tid = threadIdx.x;
    __shared__ float st[NM*RR];
    for (int i = tid; i < NM*RR/4; i += 128)
        *(float4*)&st[i*4] = *(const float4*)&g_t1[(size_t)be*NM*RR + i*4];
    __syncthreads();
    if (tid >= KK) return;
    float sc[NM];
    #pragma unroll
    for (int m = 0; m < NM; m++)
        sc[m] = (1.0f - mask[be*NM + m]) * (-1e6f);
    for (int j = 0; j < RR; j++) {
        float a = g_anT[j*128 + tid];
        #pragma unroll
        for (int m = 0; m < NM; m++) sc[m] += st[m*RR + j] * a;
    }
    float mx = sc[0];
    #pragma unroll
    for (int m = 1; m < NM; m++) mx = fmaxf(mx, sc[m]);
    float ssum = 0.f;
    #pragma unroll
    for (int m = 0; m < NM; m++) { sc[m] = expf(sc[m] - mx); ssum += sc[m]; }
    float inv = 1.0f / ssum;
    #pragma unroll
    for (int m = 0; m < NM; m++) g_w[(be*KK + tid)*NM + m] = sc[m]*inv;
}

// ---------------- K7: ht + norm + x; idle blocks convert B->fp16 ----------------
#define BCONV_BLOCKS (861*BBS)
#define BCONV_N4     ((size_t)KK*DD*DD/4)
#define BCONV_CHUNK  ((BCONV_N4 + BCONV_BLOCKS - 1)/BCONV_BLOCKS)

__global__ __launch_bounds__(256) void k_htx(const float* __restrict__ blin,
                                             const float* __restrict__ bil)
{
    int b = blockIdx.y;
    int i = blockIdx.x / NE, j = blockIdx.x % NE;
    int tid = threadIdx.x;
    if (j < i) {
        size_t q = (size_t)b*861 + (size_t)i*(i-1)/2 + j;
        size_t beg = q*BCONV_CHUNK;
        size_t end = beg + BCONV_CHUNK;
        if (end > BCONV_N4) end = BCONV_N4;
        __half2* ph = (__half2*)g_Bhi;
        for (size_t i4 = beg + tid; i4 < end; i4 += 256) {
            float4 v = ((const float4*)bil)[i4];
            ph[i4*2+0] = __floats2half2_rn(v.x, v.y);
            ph[i4*2+1] = __floats2half2_rn(v.z, v.w);
        }
        return;
    }
    const float* ai = g_as + ((size_t)(b*NE + i))*LL*HH;
    const float* aj = g_as + ((size_t)(b*NE + j))*LL*HH;
    const float* s3 = g_S3 + b*LL*3;
    float sum = 0.f, x0 = 0.f, x1 = 0.f, x2 = 0.f;
    for (int l = tid; l < LL; l += 256) {
        float4 u0 = *(const float4*)&ai[l*HH + 0];
        float4 u1 = *(const float4*)&ai[l*HH + 4];
        float4 u2 = *(const float4*)&ai[l*HH + 8];
        float4 v0 = *(const float4*)&aj[l*HH + 0];
        float4 v1 = *(const float4*)&aj[l*HH + 4];
        float4 v2 = *(const float4*)&aj[l*HH + 8];
        float acc = u0.x*v0.x + u0.y*v0.y + u0.z*v0.z + u0.w*v0.w
                  + u1.x*v1.x + u1.y*v1.y + u1.z*v1.z + u1.w*v1.w
                  + u2.x*v2.x + u2.y*v2.y + u2.z*v2.z + u2.w*v2.w;
        acc *= (1.0f / HH);
        sum += acc;
        x0 += acc * s3[l*3+0];
        x1 += acc * s3[l*3+1];
        x2 += acc * s3[l*3+2];
    }
    __shared__ float red[4][256];
    red[0][tid] = sum; red[1][tid] = x0; red[2][tid] = x1; red[3][tid] = x2;
    __syncthreads();
    for (int s2 = 128; s2 > 0; s2 >>= 1) {
        if (tid < s2) {
            red[0][tid] += red[0][tid+s2];
            red[1][tid] += red[1][tid+s2];
            red[2][tid] += red[2][tid+s2];
            red[3][tid] += red[3][tid+s2];
        }
        __syncthreads();
    }
    if (tid == 0) {
        float inv = 1.0f / (red[0][0] + 1e-5f);
        float v0 = red[1][0]*inv + blin[0];
        float v1 = red[2][0]*inv + blin[1];
        float v2 = red[3][0]*inv + blin[2];
        float* xo = g_x + ((b*NE + i)*NE + j)*3;
        xo[0] = v0; xo[1] = v1; xo[2] = v2;
        float* xm = g_x + ((b*NE + j)*NE + i)*3;
        xm[0] = v0; xm[1] = v1; xm[2] = v2;
    }
}

// ---------------- K8: 3x3 conv + relu at pair positions ----------------
__global__ void k_htss(const int* __restrict__ pairs, const float* __restrict__ Wseg,
                       const float* __restrict__ bseg)
{
    int n = blockIdx.x;
    int b = n >> 7;
    int tid = threadIdx.x;
    __shared__ int shi, sti;
    __shared__ float sx[27];
    if (tid == 0) { shi = pairs[n*2]; sti = pairs[n*2+1]; }
    __syncthreads();
    if (tid < 27) {
        int dy = tid / 9, dx = (tid / 3) % 3, c = tid % 3;
        int ii = shi + dy - 1, jj = sti + dx - 1;
        sx[tid] = (ii >= 0 && ii < NE && jj >= 0 && jj < NE)
                  ? g_x[((b*NE + ii)*NE + jj)*3 + c] : 0.f;
    }
    __syncthreads();
    float acc = bseg[tid];
    #pragma unroll
    for (int t = 0; t < 27; t++) acc += sx[t] * Wseg[t*FF + tid];
    g_htss[n*FF + tid] = fmaxf(acc, 0.f);
}

// ---------------- K10: hs,ts -> fp16 ----------------
__global__ __launch_bounds__(256) void k_hsts(const int* __restrict__ pairs)
{
    int n = blockIdx.x;
    int b = n >> 7;
    int tid = threadIdx.x;
    __shared__ float sT[2*NM*DD];
    int hi = pairs[n*2], ti = pairs[n*2+1];
    const float* Th = g_Th + (b*NE + hi)*NM*DD;
    const float* Tt = g_Tt + (b*NE + ti)*NM*DD;
    for (int idx = tid; idx < NM*DD; idx += 256) {
        sT[idx]         = Th[idx];
        sT[NM*DD + idx] = Tt[idx];
    }
    float rh[3], rt[3];
    #pragma unroll
    for (int i2 = 0; i2 < 3; i2++) {
        rh[i2] = g_Rh[n*DD + tid + i2*256];
        rt[i2] = g_Rt[n*DD + tid + i2*256];
    }
    __syncthreads();
    const float* wh = g_w + (b*NE + hi)*KK*NM;
    const float* wt = g_w + (b*NE + ti)*KK*NM;
    for (int k = 0; k < KK; k++) {
        float whr[NM], wtr[NM];
        #pragma unroll
        for (int m = 0; m < NM; m++) {
            whr[m] = __ldg(&wh[k*NM + m]);
            wtr[m] = __ldg(&wt[k*NM + m]);
        }
        #pragma unroll
        for (int i2 = 0; i2 < 3; i2++) {
            int d = tid + i2*256;
            float ah = rh[i2], at2 = rt[i2];
            #pragma unroll
            for (int m = 0; m < NM; m++) {
                ah  += whr[m] * sT[m*DD + d];
                at2 += wtr[m] * sT[NM*DD + m*DD + d];
            }
            size_t o = (size_t)(n*KK + k)*DD + d;
            g_hsh[o]  = __float2half_rn(ftanh(ah));
            g_tshi[o] = __float2half_rn(ftanh(at2));
        }
    }
}

// ================= HMMA (mma.sync fp16) bilinear core, single pass =================
#define SW128(o) ((o) ^ (((o) >> 3) & 0x70))
#define TILE_BYTES 16384
#define SH_PITCH 132
#define SMEM_DYN (128*SH_PITCH*4 + 128*2*4 + 1024)

__device__ __forceinline__ void ldm4(uint32_t* r, uint32_t addr)
{
    asm volatile("ldmatrix.sync.aligned.m8n8.x4.shared.b16 {%0,%1,%2,%3}, [%4];"
                 : "=r"(r[0]), "=r"(r[1]), "=r"(r[2]), "=r"(r[3]) : "r"(addr));
}
__device__ __forceinline__ void mma16816(float* c, const uint32_t* a, const uint32_t* b)
{
    asm volatile("mma.sync.aligned.m16n8k16.row.col.f32.f16.f16.f32 "
                 "{%0,%1,%2,%3}, {%4,%5,%6,%7}, {%8,%9}, {%0,%1,%2,%3};"
                 : "+f"(c[0]), "+f"(c[1]), "+f"(c[2]), "+f"(c[3])
                 : "r"(a[0]), "r"(a[1]), "r"(a[2]), "r"(a[3]), "r"(b[0]), "r"(b[1]));
}

__global__ __launch_bounds__(256) void k_bilinear_mma()
{
    extern __shared__ char dsm[];
    char* smem = (char*)((((uintptr_t)dsm) + 1023) & ~(uintptr_t)1023);
    uint32_t sbase = (uint32_t)__cvta_generic_to_shared(smem);

    const int k  = blockIdx.y;
    const int nt = blockIdx.x & 3;
    const int dt = blockIdx.x >> 2;
    const int n0 = nt * 128, d0 = dt * 128;
    const int tid = threadIdx.x;
    const int lane = tid & 31, wid = tid >> 5;
    const int wm = (wid & 3) * 32;
    const int wn = (wid >> 2) * 64;

    const __half* Abase = g_tshi + ((size_t)n0 * KK + k) * DD;
    const __half* Bbase = g_Bhi + ((size_t)k * DD + d0) * DD;

    float acc[2][8][4];
    #pragma unroll
    for (int mi = 0; mi < 2; mi++)
        #pragma unroll
        for (int ni = 0; ni < 8; ni++)
            #pragma unroll
            for (int j = 0; j < 4; j++) acc[mi][ni][j] = 0.f;

    auto fill = [&](int it, int buf) {
        int k0 = it * 64;
        uint32_t abase = sbase + buf*2*TILE_BYTES;
        uint32_t bbase = abase + TILE_BYTES;
        #pragma unroll
        for (int j = 0; j < 8; j++) {
            int c = tid + j*256;
            if (c < 1024) {
                int r = c >> 3, q = c & 7;
                cp16(abase + SW128(r*128 + q*16), Abase + (size_t)r*(KK*DD) + k0 + q*8);
            } else {
                int c2 = c - 1024;
                int r = c2 >> 3, q = c2 & 7;
                cp16(bbase + SW128(r*128 + q*16), Bbase + (size_t)r*DD + k0 + q*8);
            }
        }
    };

    fill(0, 0);
    asm volatile("cp.async.commit_group;");

    for (int i = 0; i < 12; i++) {
        if (i + 1 < 12) {
            fill(i + 1, (i + 1) & 1);
            asm volatile("cp.async.commit_group;");
            asm volatile("cp.async.wait_group 1;");
        } else {
            asm volatile("cp.async.wait_group 0;");
        }
        __syncthreads();

        uint32_t abase = sbase + (i & 1)*2*TILE_BYTES;
        uint32_t bbase = abase + TILE_BYTES;
        #pragma unroll
        for (int ks = 0; ks < 4; ks++) {
            uint32_t af[2][4];
            #pragma unroll
            for (int mi = 0; mi < 2; mi++) {
                int row = wm + mi*16 + ((lane >> 3) & 1)*8 + (lane & 7);
                int cb  = ks*32 + (lane >> 4)*16;
                ldm4(af[mi], abase + SW128(row*128 + cb));
            }
            uint32_t bf[8][2];
            #pragma unroll
            for (int q = 0; q < 4; q++) {
                uint32_t r[4];
                int nrow = wn + (2*q + (lane >> 4))*8 + (lane & 7);
                int cb   = ks*32 + ((lane >> 3) & 1)*16;
                ldm4(r, bbase + SW128(nrow*128 + cb));
                bf[2*q+0][0] = r[0]; bf[2*q+0][1] = r[1];
                bf[2*q+1][0] = r[2]; bf[2*q+1][1] = r[3];
            }
            #pragma unroll
            for (int mi = 0; mi < 2; mi++)
                #pragma unroll
                for (int ni = 0; ni < 8; ni++)
                    mma16816(acc[mi][ni], af[mi], bf[ni]);
        }
        __syncthreads();
    }

    // ---- epilogue: partial[n] = sum_d C[n][d]*hs[n][d] ----
    float* sH  = (float*)smem;
    float* red = (float*)(smem + 128*SH_PITCH*4);
    for (int idx = tid; idx < 128*16; idx += 256) {
        int r = idx >> 4, c8 = idx & 15;
        const __half2* hp = (const __half2*)(g_hsh + ((size_t)(n0 + r)*KK + k)*DD + d0 + c8*8);
        float* dst = &sH[r*SH_PITCH + c8*8];
        #pragma unroll
        for (int u = 0; u < 4; u++) {
            float2 f = __half22float2(hp[u]);
            dst[u*2+0] = f.x; dst[u*2+1] = f.y;
        }
    }
    __syncthreads();

    float p[2][2] = {{0.f, 0.f}, {0.f, 0.f}};
    #pragma unroll
    for (int mi = 0; mi < 2; mi++) {
        int r0 = wm + mi*16 + (lane >> 2);
        #pragma unroll
        for (int ni = 0; ni < 8; ni++) {
            int cb = wn + ni*8 + (lane & 3)*2;
            p[mi][0] += acc[mi][ni][0]*sH[r0*SH_PITCH + cb]
                      + acc[mi][ni][1]*sH[r0*SH_PITCH + cb + 1];
            p[mi][1] += acc[mi][ni][2]*sH[(r0+8)*SH_PITCH + cb]
                      + acc[mi][ni][3]*sH[(r0+8)*SH_PITCH + cb + 1];
        }
    }
    #pragma unroll
    for (int mi = 0; mi < 2; mi++)
        #pragma unroll
        for (int h = 0; h < 2; h++) {
            p[mi][h] += __shfl_xor_sync(0xffffffffu, p[mi][h], 1);
            p[mi][h] += __shfl_xor_sync(0xffffffffu, p[mi][h], 2);
        }
    if ((lane & 3) == 0) {
        int nw = wid >> 2;
        int rr = lane >> 2;
        #pragma unroll
        for (int mi = 0; mi < 2; mi++) {
            red[(wm + mi*16 + rr)*2 + nw]     = p[mi][0];
            red[(wm + mi*16 + rr + 8)*2 + nw] = p[mi][1];
        }
    }
    __syncthreads();
    if (tid < 128)
        g_part[((size_t)dt*NP + n0 + tid)*KK + k] = red[tid*2] + red[tid*2+1];
}

// ---------------- K13: finalize ----------------
__global__ void k_final(const float* __restrict__ bilb, float* __restrict__ out)
{
    int idx = blockIdx.x*256 + threadIdx.x;
    if (idx >= NP*KK) return;
    int k = idx % KK;
    float s = bilb[k];
    #pragma unroll
    for (int t = 0; t < 6; t++) s += g_part[t*(NP*KK) + idx];
    out[idx] = s;
}

// ---------------- launch ----------------
extern "C" void kernel_launch(void* const* d_in, const int* in_sizes, int n_in,
                              void* d_out, int out_size)
{
    const float* seq      = (const float*)d_in[0];
    const float* att      = (const float*)d_in[1];
    const float* mask     = (const float*)d_in[2];
    const int*   mpos     = (const int*)  d_in[3];
    const int*   pairs    = (const int*)  d_in[4];
    const float* Wattn    = (const float*)d_in[5];
    const float* battn    = (const float*)d_in[6];
    const float* attn_net = (const float*)d_in[7];
    const float* Wlin     = (const float*)d_in[8];
    const float* blin     = (const float*)d_in[9];
    const float* Wseg     = (const float*)d_in[10];
    const float* bseg     = (const float*)d_in[11];
    const float* Whead    = (const float*)d_in[12];
    const float* bhead    = (const float*)d_in[13];
    const float* Wtail    = (const float*)d_in[14];
    const float* btail    = (const float*)d_in[15];
    const float* bil      = (const float*)d_in[16];
    const float* bilb     = (const float*)d_in[17];
    float* out = (float*)d_out;

    float *emb, *t1, *htss, *Th, *Tt, *Rh, *Rt;
    cudaGetSymbolAddress((void**)&emb,  g_emb);
    cudaGetSymbolAddress((void**)&t1,   g_t1);
    cudaGetSymbolAddress((void**)&htss, g_htss);
    cudaGetSymbolAddress((void**)&Th,   g_Th);
    cudaGetSymbolAddress((void**)&Tt,   g_Tt);
    cudaGetSymbolAddress((void**)&Rh,   g_Rh);
    cudaGetSymbolAddress((void**)&Rt,   g_Rt);

    cudaFuncSetAttribute(k_bilinear_mma, cudaFuncAttributeMaxDynamicSharedMemorySize, SMEM_DYN);

    // 1. fused prep: gather | antn transpose | S3
    k_prep<<<GATHER_BLKS + ANTR_BLKS + S3_BLKS, 256>>>(seq, att, mask, mpos, attn_net, Wlin);
    // 2. t1 = tanh(emb @ Wattn + battn)
    sgemm_ca<<<dim3(RR/64, (BBS*NE*NM)/64), 256>>>(emb, DD, Wattn, RR, battn, t1, RR, DD, 1);
    // 3. fused scores + softmax
    k_scsm<<<BBS*NE, 128>>>(mask);
    // 4/5. T_h / T_t merged (transposed-A vectorized dual GEMM)
    sgemm_dualT<<<dim3(2*(DD/64), (BBS*NE*NM)/64), 256>>>(emb, DD, Whead, Wtail, DD,
                                                          nullptr, nullptr, Th, Tt, DD, DD);
    // 6/7. ht -> x  (idle blocks convert bilinear weights to fp16)
    k_htx<<<dim3(NE*NE, BBS), 256>>>(blin, bil);
    // 8. conv + relu at pairs
    k_htss<<<NP, 256>>>(pairs, Wseg, bseg);
    // 9. Rh / Rt merged
    sgemm_dualT<<<dim3(2*(DD/64), NP/64), 256>>>(htss, FF, Whead + DD*DD, Wtail + DD*DD, DD,
                                                 bhead, btail, Rh, Rt, DD, FF);
    // 10. hs,ts fp16
    k_hsts<<<NP, 256>>>(pairs);
    // 11. HMMA bilinear: grid (24 tiles, 97 k), fp16 single pass
    k_bilinear_mma<<<dim3(24, 97), 256, SMEM_DYN>>>();
    // 12. finalize
    k_final<<<(NP*KK + 255)/256, 256>>>(bilb, out);
}

// round 11
// speedup vs baseline: 1.1815x; 1.0728x over previous
#include <cuda_runtime.h>
#include <cuda_fp16.h>
#include <math.h>
#include <stdint.h>

#define NE 42
#define NM 8
#define LL 1024
#define DD 768
#define HH 12
#define KK 97
#define FF 256
#define RR 256
#define BBS 4
#define NP 512   /* bs * P */

// ---------------- scratch (device globals; no allocs) ----------------
__device__ float g_emb [BBS*NE*NM*DD];
__device__ float g_as  [BBS*NE*LL*HH];     // TRANSPOSED: [be][l][h]
__device__ float g_t1  [BBS*NE*NM*RR];
__device__ float g_anT [RR*128];
__device__ float g_w   [BBS*NE*KK*NM];
__device__ float g_Th  [BBS*NE*NM*DD];
__device__ float g_Tt  [BBS*NE*NM*DD];
__device__ float g_S3  [BBS*LL*3];
__device__ float g_x   [BBS*NE*NE*3];
__device__ float g_htss[NP*FF];
__device__ float g_Rh  [NP*DD];
__device__ float g_Rt  [NP*DD];
__device__ __align__(16) __half g_hsh [NP*KK*DD];
__device__ __align__(16) __half g_tshi[NP*KK*DD];
__device__ __align__(16) __half g_Bhi [KK*DD*DD];
__device__ float g_part[6*NP*KK];

__device__ __forceinline__ float fasttanh(float x)
{
    float y;
    asm("tanh.approx.f32 %0, %1;" : "=f"(y) : "f"(x));
    return y;
}

__device__ __forceinline__ void cp16(uint32_t dst, const void* src)
{
    asm volatile("cp.async.cg.shared.global [%0], [%1], 16;" :: "r"(dst), "l"(src));
}

// ---------------- K1: fused prep: gather emb+as (transposed) | antr | S3 ----------------
#define GATHER_BLKS (BBS*NE)
#define ANTR_BLKS   128
#define S3_BLKS     ((BBS*LL)/2)

__global__ __launch_bounds__(256) void k_prep(const float* __restrict__ seq,
                                              const float* __restrict__ att,
                                              const float* __restrict__ mask,
                                              const int* __restrict__ mpos,
                                              const float* __restrict__ attn_net,
                                              const float* __restrict__ Wlin)
{
    int bid = blockIdx.x;
    int tid = threadIdx.x;
    if (bid < GATHER_BLKS) {
        int be = bid;
        int b  = be / NE;
        __shared__ int   spos[NM];
        __shared__ float smk [NM];
        __shared__ float sinv;
        if (tid < NM) {
            int p = mpos[be*NM + tid] + 1;
            p = max(0, min(p, LL-1));
            spos[tid] = p;
            smk[tid]  = mask[be*NM + tid];
        }
        __syncthreads();
        if (tid == 0) {
            float c = 0.f;
            #pragma unroll
            for (int m = 0; m < NM; m++) c += smk[m];
            sinv = 1.0f / fmaxf(c, 1.0f);
        }
        __syncthreads();
        for (int idx = tid; idx < NM*DD; idx += 256) {
            int m = idx / DD, d = idx - m*DD;
            g_emb[be*NM*DD + idx] = seq[(b*LL + spos[m])*DD + d] * smk[m];
        }
        for (int idx = tid; idx < HH*LL; idx += 256) {
            int h = idx / LL, l = idx - h*LL;
            float acc = 0.f;
            #pragma unroll
            for (int m = 0; m < NM; m++)
                acc += att[((b*HH + h)*LL + spos[m])*LL + l] * smk[m];
            g_as[((size_t)be*LL + l)*HH + h] = acc * sinv;
        }
    } else if (bid < GATHER_BLKS + ANTR_BLKS) {
        int idx = (bid - GATHER_BLKS)*256 + tid;
        int j = idx >> 7, k = idx & 127;
        g_anT[idx] = (k < KK) ? attn_net[k*RR + j] : 0.f;
    } else {
        int rp = bid - GATHER_BLKS - ANTR_BLKS;
        int half = tid >> 7;
        int t2 = tid & 127;
        int row = rp*2 + half;
        const float* s = seq + (size_t)row*DD;
        float a0 = 0.f, a1 = 0.f, a2 = 0.f;
        for (int j = t2; j < DD; j += 128) {
            float v = s[j];
            a0 += v*Wlin[j*3+0]; a1 += v*Wlin[j*3+1]; a2 += v*Wlin[j*3+2];
        }
        __shared__ float red[2][3][128];
        red[half][0][t2] = a0; red[half][1][t2] = a1; red[half][2][t2] = a2;
        __syncthreads();
        for (int s2 = 64; s2 > 0; s2 >>= 1) {
            if (t2 < s2) {
                red[half][0][t2] += red[half][0][t2+s2];
                red[half][1][t2] += red[half][1][t2+s2];
                red[half][2][t2] += red[half][2][t2+s2];
            }
            __syncthreads();
        }
        if (t2 < 3) g_S3[row*3 + t2] = red[half][t2][0];
    }
}

// ---------------- cp.async double-buffered SGEMM (64x64x32) — for t1 ----------------
__global__ __launch_bounds__(256) void sgemm_ca(const float* __restrict__ A, int lda,
                                                const float* __restrict__ B, int ldb,
                                                const float* __restrict__ bias,
                                                float* __restrict__ C, int ldc,
                                                int Kd, int act)
{
    __shared__ float As[2][64][32];
    __shared__ float Bs[2][32][68];
    int m0 = blockIdx.y * 64, n0 = blockIdx.x * 64;
    int tid = threadIdx.x;
    int ty = tid >> 4, tx = tid & 15;
    uint32_t sA = (uint32_t)__cvta_generic_to_shared(&As[0][0][0]);
    uint32_t sB = (uint32_t)__cvta_generic_to_shared(&Bs[0][0][0]);
    float acc[4][4];
    #pragma unroll
    for (int i = 0; i < 4; i++)
        #pragma unroll
        for (int j = 0; j < 4; j++) acc[i][j] = 0.f;

    int nstage = Kd >> 5;
    auto fill = [&](int s, int k0) {
        #pragma unroll
        for (int j = 0; j < 2; j++) {
            int c = tid + j*256;
            int r = c >> 3, q = c & 7;
            cp16(sA + (uint32_t)(s*64*32 + r*32 + q*4)*4,
                 A + (size_t)(m0 + r)*lda + k0 + q*4);
            int rb = c >> 4, qb = c & 15;
            cp16(sB + (uint32_t)(s*32*68 + rb*68 + qb*4)*4,
                 B + (size_t)(k0 + rb)*ldb + n0 + qb*4);
        }
        asm volatile("cp.async.commit_group;");
    };

    fill(0, 0);
    for (int s = 0; s < nstage; s++) {
        if (s + 1 < nstage) {
            fill((s + 1) & 1, (s + 1) << 5);
            asm volatile("cp.async.wait_group 1;");
        } else {
            asm volatile("cp.async.wait_group 0;");
        }
        __syncthreads();
        int bs = s & 1;
        #pragma unroll
        for (int kk = 0; kk < 32; kk++) {
            float a[4], bv[4];
            #pragma unroll
            for (int i = 0; i < 4; i++) a[i]  = As[bs][ty*4 + i][kk];
            #pragma unroll
            for (int j = 0; j < 4; j++) bv[j] = Bs[bs][kk][tx*4 + j];
            #pragma unroll
            for (int i = 0; i < 4; i++)
                #pragma unroll
                for (int j = 0; j < 4; j++) acc[i][j] += a[i]*bv[j];
        }
        __syncthreads();
    }
    #pragma unroll
    for (int i = 0; i < 4; i++) {
        int row = m0 + ty*4 + i;
        #pragma unroll
        for (int j = 0; j < 4; j++) {
            int col = n0 + tx*4 + j;
            float v = acc[i][j];
            if (bias) v += bias[col];
            if (act)  v = fasttanh(v);
            C[(size_t)row*ldc + col] = v;
        }
    }
}

// ---------------- dual-output cp.async SGEMM (R8 known-good) ----------------
__global__ __launch_bounds__(256) void sgemm_ca_dual(const float* __restrict__ A, int lda,
                                                     const float* __restrict__ B0,
                                                     const float* __restrict__ B1, int ldb,
                                                     const float* __restrict__ bias0,
                                                     const float* __restrict__ bias1,
                                                     float* __restrict__ C0,
                                                     float* __restrict__ C1, int ldc,
                                                     int Kd)
{
    __shared__ float As[2][64][32];
    __shared__ float Bs[2][32][68];
    int hx = gridDim.x >> 1;
    int half = blockIdx.x >= hx;
    const float* B    = half ? B1    : B0;
    const float* bias = half ? bias1 : bias0;
    float*       C    = half ? C1    : C0;
    int n0 = (blockIdx.x - half*hx) * 64;
    int m0 = blockIdx.y * 64;
    int tid = threadIdx.x;
    int ty = tid >> 4, tx = tid & 15;
    uint32_t sA = (uint32_t)__cvta_generic_to_shared(&As[0][0][0]);
    uint32_t sB = (uint32_t)__cvta_generic_to_shared(&Bs[0][0][0]);
    float acc[4][4];
    #pragma unroll
    for (int i = 0; i < 4; i++)
        #pragma unroll
        for (int j = 0; j < 4; j++) acc[i][j] = 0.f;

    int nstage = Kd >> 5;
    auto fill = [&](int s, int k0) {
        #pragma unroll
        for (int j = 0; j < 2; j++) {
            int c = tid + j*256;
            int r = c >> 3, q = c & 7;
            cp16(sA + (uint32_t)(s*64*32 + r*32 + q*4)*4,
                 A + (size_t)(m0 + r)*lda + k0 + q*4);
            int rb = c >> 4, qb = c & 15;
            cp16(sB + (uint32_t)(s*32*68 + rb*68 + qb*4)*4,
                 B + (size_t)(k0 + rb)*ldb + n0 + qb*4);
        }
        asm volatile("cp.async.commit_group;");
    };

    fill(0, 0);
    for (int s = 0; s < nstage; s++) {
        if (s + 1 < nstage) {
            fill((s + 1) & 1, (s + 1) << 5);
            asm volatile("cp.async.wait_group 1;");
        } else {
            asm volatile("cp.async.wait_group 0;");
        }
        __syncthreads();
        int bs = s & 1;
        #pragma unroll
        for (int kk = 0; kk < 32; kk++) {
            float a[4], bv[4];
            #pragma unroll
            for (int i = 0; i < 4; i++) a[i]  = As[bs][ty*4 + i][kk];
            #pragma unroll
            for (int j = 0; j < 4; j++) bv[j] = Bs[bs][kk][tx*4 + j];
            #pragma unroll
            for (int i = 0; i < 4; i++)
                #pragma unroll
                for (int j = 0; j < 4; j++) acc[i][j] += a[i]*bv[j];
        }
        __syncthreads();
    }
    #pragma unroll
    for (int i = 0; i < 4; i++) {
        int row = m0 + ty*4 + i;
        #pragma unroll
        for (int j = 0; j < 4; j++) {
            int col = n0 + tx*4 + j;
            float v = acc[i][j];
            if (bias) v += bias[col];
            C[(size_t)row*ldc + col] = v;
        }
    }
}

// ---------------- fused scores + softmax over mentions ----------------
__global__ __launch_bounds__(128) void k_scsm(const float* __restrict__ mask)
{
    int be = blockIdx.x;
    int tid = threadIdx.x;
    __shared__ float st[NM*RR];
    for (int i = tid; i < NM*RR/4; i += 128)
        *(float4*)&st[i*4] = *(const float4*)&g_t1[(size_t)be*NM*RR + i*4];
    __syncthreads();
    if (tid >= KK) return;
    float sc[NM];
    #pragma unroll
    for (int m = 0; m < NM; m++)
        sc[m] = (1.0f - mask[be*NM + m]) * (-1e6f);
    for (int j = 0; j < RR; j++) {
        float a = g_anT[j*128 + tid];
        #pragma unroll
        for (int m = 0; m < NM; m++) sc[m] += st[m*RR + j] * a;
    }
    float mx = sc[0];
    #pragma unroll
    for (int m = 1; m < NM; m++) mx = fmaxf(mx, sc[m]);
    float ssum = 0.f;
    #pragma unroll
    for (int m = 0; m < NM; m++) { sc[m] = expf(sc[m] - mx); ssum += sc[m]; }
    float inv = 1.0f / ssum;
    #pragma unroll
    for (int m = 0; m < NM; m++) g_w[(be*KK + tid)*NM + m] = sc[m]*inv;
}

// ---------------- K7: ht + norm + x; idle blocks convert B->fp16 ----------------
#define BCONV_BLOCKS (861*BBS)
#define BCONV_N4     ((size_t)KK*DD*DD/4)
#define BCONV_CHUNK  ((BCONV_N4 + BCONV_BLOCKS - 1)/BCONV_BLOCKS)

__global__ __launch_bounds__(256) void k_htx(const float* __restrict__ blin,
                                             const float* __restrict__ bil)
{
    int b = blockIdx.y;
    int i = blockIdx.x / NE, j = blockIdx.x % NE;
    int tid = threadIdx.x;
    if (j < i) {
        size_t q = (size_t)b*861 + (size_t)i*(i-1)/2 + j;
        size_t beg = q*BCONV_CHUNK;
        size_t end = beg + BCONV_CHUNK;
        if (end > BCONV_N4) end = BCONV_N4;
        __half2* ph = (__half2*)g_Bhi;
        for (size_t i4 = beg + tid; i4 < end; i4 += 256) {
            float4 v = ((const float4*)bil)[i4];
            ph[i4*2+0] = __floats2half2_rn(v.x, v.y);
            ph[i4*2+1] = __floats2half2_rn(v.z, v.w);
        }
        return;
    }
    const float* ai = g_as + ((size_t)(b*NE + i))*LL*HH;
    const float* aj = g_as + ((size_t)(b*NE + j))*LL*HH;
    const float* s3 = g_S3 + b*LL*3;
    float sum = 0.f, x0 = 0.f, x1 = 0.f, x2 = 0.f;
    for (int l = tid; l < LL; l += 256) {
        float4 u0 = *(const float4*)&ai[l*HH + 0];
        float4 u1 = *(const float4*)&ai[l*HH + 4];
        float4 u2 = *(const float4*)&ai[l*HH + 8];
        float4 v0 = *(const float4*)&aj[l*HH + 0];
        float4 v1 = *(const float4*)&aj[l*HH + 4];
        float4 v2 = *(const float4*)&aj[l*HH + 8];
        float acc = u0.x*v0.x + u0.y*v0.y + u0.z*v0.z + u0.w*v0.w
                  + u1.x*v1.x + u1.y*v1.y + u1.z*v1.z + u1.w*v1.w
                  + u2.x*v2.x + u2.y*v2.y + u2.z*v2.z + u2.w*v2.w;
        acc *= (1.0f / HH);
        sum += acc;
        x0 += acc * s3[l*3+0];
        x1 += acc * s3[l*3+1];
        x2 += acc * s3[l*3+2];
    }
    __shared__ float red[4][256];
    red[0][tid] = sum; red[1][tid] = x0; red[2][tid] = x1; red[3][tid] = x2;
    __syncthreads();
    for (int s2 = 128; s2 > 0; s2 >>= 1) {
        if (tid < s2) {
            red[0][tid] += red[0][tid+s2];
            red[1][tid] += red[1][tid+s2];
            red[2][tid] += red[2][tid+s2];
            red[3][tid] += red[3][tid+s2];
        }
        __syncthreads();
    }
    if (tid == 0) {
        float inv = 1.0f / (red[0][0] + 1e-5f);
        float v0 = red[1][0]*inv + blin[0];
        float v1 = red[2][0]*inv + blin[1];
        float v2 = red[3][0]*inv + blin[2];
        float* xo = g_x + ((b*NE + i)*NE + j)*3;
        xo[0] = v0; xo[1] = v1; xo[2] = v2;
        float* xm = g_x + ((b*NE + j)*NE + i)*3;
        xm[0] = v0; xm[1] = v1; xm[2] = v2;
    }
}

// ---------------- K8: 3x3 conv + relu at pair positions ----------------
__global__ void k_htss(const int* __restrict__ pairs, const float* __restrict__ Wseg,
                       const float* __restrict__ bseg)
{
    int n = blockIdx.x;
    int b = n >> 7;
    int tid = threadIdx.x;
    __shared__ int shi, sti;
    __shared__ float sx[27];
    if (tid == 0) { shi = pairs[n*2]; sti = pairs[n*2+1]; }
    __syncthreads();
    if (tid < 27) {
        int dy = tid / 9, dx = (tid / 3) % 3, c = tid % 3;
        int ii = shi + dy - 1, jj = sti + dx - 1;
        sx[tid] = (ii >= 0 && ii < NE && jj >= 0 && jj < NE)
                  ? g_x[((b*NE + ii)*NE + jj)*3 + c] : 0.f;
    }
    __syncthreads();
    float acc = bseg[tid];
    #pragma unroll
    for (int t = 0; t < 27; t++) acc += sx[t] * Wseg[t*FF + tid];
    g_htss[n*FF + tid] = fmaxf(acc, 0.f);
}

// ---------------- K10: hs,ts -> fp16 (vector w loads + tanh.approx) ----------------
__global__ __launch_bounds__(256) void k_hsts(const int* __restrict__ pairs)
{
    int n = blockIdx.x;
    int b = n >> 7;
    int tid = threadIdx.x;
    __shared__ float sT[2*NM*DD];
    int hi = pairs[n*2], ti = pairs[n*2+1];
    const float* Th = g_Th + (b*NE + hi)*NM*DD;
    const float* Tt = g_Tt + (b*NE + ti)*NM*DD;
    for (int idx = tid; idx < NM*DD; idx += 256) {
        sT[idx]         = Th[idx];
        sT[NM*DD + idx] = Tt[idx];
    }
    float rh[3], rt[3];
    #pragma unroll
    for (int i2 = 0; i2 < 3; i2++) {
        rh[i2] = g_Rh[n*DD + tid + i2*256];
        rt[i2] = g_Rt[n*DD + tid + i2*256];
    }
    __syncthreads();
    const float4* wh4 = (const float4*)(g_w + (size_t)(b*NE + hi)*KK*NM);
    const float4* wt4 = (const float4*)(g_w + (size_t)(b*NE + ti)*KK*NM);
    for (int k = 0; k < KK; k++) {
        float4 wh0 = __ldg(&wh4[k*2]),   wh1 = __ldg(&wh4[k*2+1]);
        float4 wt0 = __ldg(&wt4[k*2]),   wt1 = __ldg(&wt4[k*2+1]);
        float whr[NM] = {wh0.x, wh0.y, wh0.z, wh0.w, wh1.x, wh1.y, wh1.z, wh1.w};
        float wtr[NM] = {wt0.x, wt0.y, wt0.z, wt0.w, wt1.x, wt1.y, wt1.z, wt1.w};
        #pragma unroll
        for (int i2 = 0; i2 < 3; i2++) {
            int d = tid + i2*256;
            float ah = rh[i2], at2 = rt[i2];
            #pragma unroll
            for (int m = 0; m < NM; m++) {
                ah  += whr[m] * sT[m*DD + d];
                at2 += wtr[m] * sT[NM*DD + m*DD + d];
            }
            size_t o = (size_t)(n*KK + k)*DD + d;
            g_hsh[o]  = __float2half_rn(fasttanh(ah));
            g_tshi[o] = __float2half_rn(fasttanh(at2));
        }
    }
}

// ================= HMMA (mma.sync fp16) bilinear core, single pass =================
#define SW128(o) ((o) ^ (((o) >> 3) & 0x70))
#define TILE_BYTES 16384
#define SH_PITCH 132
#define SMEM_DYN (128*SH_PITCH*4 + 128*2*4 + 1024)

__device__ __forceinline__ void ldm4(uint32_t* r, uint32_t addr)
{
    asm volatile("ldmatrix.sync.aligned.m8n8.x4.shared.b16 {%0,%1,%2,%3}, [%4];"
                 : "=r"(r[0]), "=r"(r[1]), "=r"(r[2]), "=r"(r[3]) : "r"(addr));
}
__device__ __forceinline__ void mma16816(float* c, const uint32_t* a, const uint32_t* b)
{
    asm volatile("mma.sync.aligned.m16n8k16.row.col.f32.f16.f16.f32 "
                 "{%0,%1,%2,%3}, {%4,%5,%6,%7}, {%8,%9}, {%0,%1,%2,%3};"
                 : "+f"(c[0]), "+f"(c[1]), "+f"(c[2]), "+f"(c[3])
                 : "r"(a[0]), "r"(a[1]), "r"(a[2]), "r"(a[3]), "r"(b[0]), "r"(b[1]));
}

__global__ __launch_bounds__(256) void k_bilinear_mma()
{
    extern __shared__ char dsm[];
    char* smem = (char*)((((uintptr_t)dsm) + 1023) & ~(uintptr_t)1023);
    uint32_t sbase = (uint32_t)__cvta_generic_to_shared(smem);

    const int k  = blockIdx.y;
    const int nt = blockIdx.x & 3;
    const int dt = blockIdx.x >> 2;
    const int n0 = nt * 128, d0 = dt * 128;
    const int tid = threadIdx.x;
    const int lane = tid & 31, wid = tid >> 5;
    const int wm = (wid & 3) * 32;
    const int wn = (wid >> 2) * 64;

    const __half* Abase = g_tshi + ((size_t)n0 * KK + k) * DD;
    const __half* Bbase = g_Bhi + ((size_t)k * DD + d0) * DD;

    float acc[2][8][4];
    #pragma unroll
    for (int mi = 0; mi < 2; mi++)
        #pragma unroll
        for (int ni = 0; ni < 8; ni++)
            #pragma unroll
            for (int j = 0; j < 4; j++) acc[mi][ni][j] = 0.f;

    auto fill = [&](int it, int buf) {
        int k0 = it * 64;
        uint32_t abase = sbase + buf*2*TILE_BYTES;
        uint32_t bbase = abase + TILE_BYTES;
        #pragma unroll
        for (int j = 0; j < 8; j++) {
            int c = tid + j*256;
            if (c < 1024) {
                int r = c >> 3, q = c & 7;
                cp16(abase + SW128(r*128 + q*16), Abase + (size_t)r*(KK*DD) + k0 + q*8);
            } else {
                int c2 = c - 1024;
                int r = c2 >> 3, q = c2 & 7;
                cp16(bbase + SW128(r*128 + q*16), Bbase + (size_t)r*DD + k0 + q*8);
            }
        }
    };

    fill(0, 0);
    asm volatile("cp.async.commit_group;");

    for (int i = 0; i < 12; i++) {
        if (i + 1 < 12) {
            fill(i + 1, (i + 1) & 1);
            asm volatile("cp.async.commit_group;");
            asm volatile("cp.async.wait_group 1;");
        } else {
            asm volatile("cp.async.wait_group 0;");
        }
        __syncthreads();

        uint32_t abase = sbase + (i & 1)*2*TILE_BYTES;
        uint32_t bbase = abase + TILE_BYTES;
        #pragma unroll
        for (int ks = 0; ks < 4; ks++) {
            uint32_t af[2][4];
            #pragma unroll
            for (int mi = 0; mi < 2; mi++) {
                int row = wm + mi*16 + ((lane >> 3) & 1)*8 + (lane & 7);
                int cb  = ks*32 + (lane >> 4)*16;
                ldm4(af[mi], abase + SW128(row*128 + cb));
            }
            uint32_t bf[8][2];
            #pragma unroll
            for (int q = 0; q < 4; q++) {
                uint32_t r[4];
                int nrow = wn + (2*q + (lane >> 4))*8 + (lane & 7);
                int cb   = ks*32 + ((lane >> 3) & 1)*16;
                ldm4(r, bbase + SW128(nrow*128 + cb));
                bf[2*q+0][0] = r[0]; bf[2*q+0][1] = r[1];
                bf[2*q+1][0] = r[2]; bf[2*q+1][1] = r[3];
            }
            #pragma unroll
            for (int mi = 0; mi < 2; mi++)
                #pragma unroll
                for (int ni = 0; ni < 8; ni++)
                    mma16816(acc[mi][ni], af[mi], bf[ni]);
        }
        __syncthreads();
    }

    // ---- epilogue: partial[n] = sum_d C[n][d]*hs[n][d] ----
    float* sH  = (float*)smem;
    float* red = (float*)(smem + 128*SH_PITCH*4);
    for (int idx = tid; idx < 128*16; idx += 256) {
        int r = idx >> 4, c8 = idx & 15;
        const __half2* hp = (const __half2*)(g_hsh + ((size_t)(n0 + r)*KK + k)*DD + d0 + c8*8);
        float* dst = &sH[r*SH_PITCH + c8*8];
        #pragma unroll
        for (int u = 0; u < 4; u++) {
            float2 f = __half22float2(hp[u]);
            dst[u*2+0] = f.x; dst[u*2+1] = f.y;
        }
    }
    __syncthreads();

    float p[2][2] = {{0.f, 0.f}, {0.f, 0.f}};
    #pragma unroll
    for (int mi = 0; mi < 2; mi++) {
        int r0 = wm + mi*16 + (lane >> 2);
        #pragma unroll
        for (int ni = 0; ni < 8; ni++) {
            int cb = wn + ni*8 + (lane & 3)*2;
            p[mi][0] += acc[mi][ni][0]*sH[r0*SH_PITCH + cb]
                      + acc[mi][ni][1]*sH[r0*SH_PITCH + cb + 1];
            p[mi][1] += acc[mi][ni][2]*sH[(r0+8)*SH_PITCH + cb]
                      + acc[mi][ni][3]*sH[(r0+8)*SH_PITCH + cb + 1];
        }
    }
    #pragma unroll
    for (int mi = 0; mi < 2; mi++)
        #pragma unroll
        for (int h = 0; h < 2; h++) {
            p[mi][h] += __shfl_xor_sync(0xffffffffu, p[mi][h], 1);
            p[mi][h] += __shfl_xor_sync(0xffffffffu, p[mi][h], 2);
        }
    if ((lane & 3) == 0) {
        int nw = wid >> 2;
        int rr = lane >> 2;
        #pragma unroll
        for (int mi = 0; mi < 2; mi++) {
            red[(wm + mi*16 + rr)*2 + nw]     = p[mi][0];
            red[(wm + mi*16 + rr + 8)*2 + nw] = p[mi][1];
        }
    }
    __syncthreads();
    if (tid < 128)
        g_part[((size_t)dt*NP + n0 + tid)*KK + k] = red[tid*2] + red[tid*2+1];
}

// ---------------- K13: finalize ----------------
__global__ void k_final(const float* __restrict__ bilb, float* __restrict__ out)
{
    int idx = blockIdx.x*256 + threadIdx.x;
    if (idx >= NP*KK) return;
    int k = idx % KK;
    float s = bilb[k];
    #pragma unroll
    for (int t = 0; t < 6; t++) s += g_part[t*(NP*KK) + idx];
    out[idx] = s;
}

// ---------------- launch ----------------
extern "C" void kernel_launch(void* const* d_in, const int* in_sizes, int n_in,
                              void* d_out, int out_size)
{
    const float* seq      = (const float*)d_in[0];
    const float* att      = (const float*)d_in[1];
    const float* mask     = (const float*)d_in[2];
    const int*   mpos     = (const int*)  d_in[3];
    const int*   pairs    = (const int*)  d_in[4];
    const float* Wattn    = (const float*)d_in[5];
    const float* battn    = (const float*)d_in[6];
    const float* attn_net = (const float*)d_in[7];
    const float* Wlin     = (const float*)d_in[8];
    const float* blin     = (const float*)d_in[9];
    const float* Wseg     = (const float*)d_in[10];
    const float* bseg     = (const float*)d_in[11];
    const float* Whead    = (const float*)d_in[12];
    const float* bhead    = (const float*)d_in[13];
    const float* Wtail    = (const float*)d_in[14];
    const float* btail    = (const float*)d_in[15];
    const float* bil      = (const float*)d_in[16];
    const float* bilb     = (const float*)d_in[17];
    float* out = (float*)d_out;

    float *emb, *t1, *htss, *Th, *Tt, *Rh, *Rt;
    cudaGetSymbolAddress((void**)&emb,  g_emb);
    cudaGetSymbolAddress((void**)&t1,   g_t1);
    cudaGetSymbolAddress((void**)&htss, g_htss);
    cudaGetSymbolAddress((void**)&Th,   g_Th);
    cudaGetSymbolAddress((void**)&Tt,   g_Tt);
    cudaGetSymbolAddress((void**)&Rh,   g_Rh);
    cudaGetSymbolAddress((void**)&Rt,   g_Rt);

    cudaFuncSetAttribute(k_bilinear_mma, cudaFuncAttributeMaxDynamicSharedMemorySize, SMEM_DYN);

    // 1. fused prep: gather | antn transpose | S3
    k_prep<<<GATHER_BLKS + ANTR_BLKS + S3_BLKS, 256>>>(seq, att, mask, mpos, attn_net, Wlin);
    // 2. t1 = tanh(emb @ Wattn + battn)
    sgemm_ca<<<dim3(RR/64, (BBS*NE*NM)/64), 256>>>(emb, DD, Wattn, RR, battn, t1, RR, DD, 1);
    // 3. fused scores + softmax
    k_scsm<<<BBS*NE, 128>>>(mask);
    // 4/5. T_h / T_t merged
    sgemm_ca_dual<<<dim3(2*(DD/64), (BBS*NE*NM)/64), 256>>>(emb, DD, Whead, Wtail, DD,
                                                            nullptr, nullptr, Th, Tt, DD, DD);
    // 6/7. ht -> x  (idle blocks convert bilinear weights to fp16)
    k_htx<<<dim3(NE*NE, BBS), 256>>>(blin, bil);
    // 8. conv + relu at pairs
    k_htss<<<NP, 256>>>(pairs, Wseg, bseg);
    // 9. Rh / Rt merged
    sgemm_ca_dual<<<dim3(2*(DD/64), NP/64), 256>>>(htss, FF, Whead + DD*DD, Wtail + DD*DD, DD,
                                                   bhead, btail, Rh, Rt, DD, FF);
    // 10. hs,ts fp16
    k_hsts<<<NP, 256>>>(pairs);
    // 11. HMMA bilinear: grid (24 tiles, 97 k), fp16 single pass
    k_bilinear_mma<<<dim3(24, 97), 256, SMEM_DYN>>>();
    // 12. finalize
    k_final<<<(NP*KK + 255)/256, 256>>>(bilb, out);
}

// round 12
// speedup vs baseline: 1.3014x; 1.1015x over previous
#include <cuda_runtime.h>
#include <cuda_fp16.h>
#include <math.h>
#include <stdint.h>

#define NE 42
#define NM 8
#define LL 1024
#define DD 768
#define HH 12
#define KK 97
#define FF 256
#define RR 256
#define BBS 4
#define NP 512   /* bs * P */

// ---------------- scratch (device globals; no allocs) ----------------
__device__ float g_emb [BBS*NE*NM*DD];
__device__ float g_as  [BBS*NE*LL*HH];     // TRANSPOSED: [be][l][h]
__device__ float g_t1  [BBS*NE*NM*RR];
__device__ float g_anT [RR*128];
__device__ float g_w   [BBS*NE*KK*NM];
__device__ float g_Th  [BBS*NE*NM*DD];
__device__ float g_Tt  [BBS*NE*NM*DD];
__device__ float g_S3  [BBS*LL*3];
__device__ float g_x   [BBS*NE*NE*3];
__device__ float g_htss[NP*FF];
__device__ float g_Rh  [NP*DD];
__device__ float g_Rt  [NP*DD];
__device__ __align__(16) __half g_hsh [NP*KK*DD];
__device__ __align__(16) __half g_tshi[NP*KK*DD];
__device__ __align__(16) __half g_Bhi [KK*DD*DD];
__device__ float g_part[6*NP*KK];

__device__ __forceinline__ float fasttanh(float x)
{
    float y;
    asm("tanh.approx.f32 %0, %1;" : "=f"(y) : "f"(x));
    return y;
}

__device__ __forceinline__ void cp16(uint32_t dst, const void* src)
{
    asm volatile("cp.async.cg.shared.global [%0], [%1], 16;" :: "r"(dst), "l"(src));
}

// ---------------- K1: fused prep: emb gather | as gather (parallel) | antr | S3 ----------------
#define EMB_BLKS  (BBS*NE)            /* 168 */
#define AS_BLKS   (BBS*NE*HH)         /* 2016: one per (be,h) */
#define ANTR_BLKS 128
#define S3_BLKS   ((BBS*LL)/2)        /* 2048 */

__global__ __launch_bounds__(256) void k_prep(const float* __restrict__ seq,
                                              const float* __restrict__ att,
                                              const float* __restrict__ mask,
                                              const int* __restrict__ mpos,
                                              const float* __restrict__ attn_net,
                                              const float* __restrict__ Wlin)
{
    int bid = blockIdx.x;
    int tid = threadIdx.x;
    if (bid < EMB_BLKS) {
        // ---- mention embedding gather ----
        int be = bid;
        int b  = be / NE;
        __shared__ int   spos[NM];
        __shared__ float smk [NM];
        if (tid < NM) {
            int p = mpos[be*NM + tid] + 1;
            p = max(0, min(p, LL-1));
            spos[tid] = p;
            smk[tid]  = mask[be*NM + tid];
        }
        __syncthreads();
        for (int idx = tid; idx < NM*DD; idx += 256) {
            int m = idx / DD, d = idx - m*DD;
            g_emb[be*NM*DD + idx] = seq[(b*LL + spos[m])*DD + d] * smk[m];
        }
    } else if (bid < EMB_BLKS + AS_BLKS) {
        // ---- entity_as gather: one block per (be, h) ----
        int q = bid - EMB_BLKS;
        int be = q / HH, h = q % HH;
        int b  = be / NE;
        __shared__ int   spos[NM];
        __shared__ float smk [NM];
        __shared__ float sinv;
        if (tid < NM) {
            int p = mpos[be*NM + tid] + 1;
            p = max(0, min(p, LL-1));
            spos[tid] = p;
            smk[tid]  = mask[be*NM + tid];
        }
        __syncthreads();
        if (tid == 0) {
            float c = 0.f;
            #pragma unroll
            for (int m = 0; m < NM; m++) c += smk[m];
            sinv = 1.0f / fmaxf(c, 1.0f);
        }
        __syncthreads();
        for (int l = tid; l < LL; l += 256) {
            float acc = 0.f;
            #pragma unroll
            for (int m = 0; m < NM; m++)
                acc += att[((b*HH + h)*LL + spos[m])*LL + l] * smk[m];
            g_as[((size_t)be*LL + l)*HH + h] = acc * sinv;
        }
    } else if (bid < EMB_BLKS + AS_BLKS + ANTR_BLKS) {
        int idx = (bid - EMB_BLKS - AS_BLKS)*256 + tid;
        int j = idx >> 7, k = idx & 127;
        g_anT[idx] = (k < KK) ? attn_net[k*RR + j] : 0.f;
    } else {
        int rp = bid - EMB_BLKS - AS_BLKS - ANTR_BLKS;
        int half = tid >> 7;
        int t2 = tid & 127;
        int row = rp*2 + half;
        const float* s = seq + (size_t)row*DD;
        float a0 = 0.f, a1 = 0.f, a2 = 0.f;
        for (int j = t2; j < DD; j += 128) {
            float v = s[j];
            a0 += v*Wlin[j*3+0]; a1 += v*Wlin[j*3+1]; a2 += v*Wlin[j*3+2];
        }
        __shared__ float red[2][3][128];
        red[half][0][t2] = a0; red[half][1][t2] = a1; red[half][2][t2] = a2;
        __syncthreads();
        for (int s2 = 64; s2 > 0; s2 >>= 1) {
            if (t2 < s2) {
                red[half][0][t2] += red[half][0][t2+s2];
                red[half][1][t2] += red[half][1][t2+s2];
                red[half][2][t2] += red[half][2][t2+s2];
            }
            __syncthreads();
        }
        if (t2 < 3) g_S3[row*3 + t2] = red[half][t2][0];
    }
}

// ---------------- cp.async double-buffered SGEMM (64x64x32), kk-by-4 float4 ----------------
__global__ __launch_bounds__(256) void sgemm_ca(const float* __restrict__ A, int lda,
                                                const float* __restrict__ B, int ldb,
                                                const float* __restrict__ bias,
                                                float* __restrict__ C, int ldc,
                                                int Kd, int act)
{
    __shared__ float As[2][64][32];
    __shared__ float Bs[2][32][68];
    int m0 = blockIdx.y * 64, n0 = blockIdx.x * 64;
    int tid = threadIdx.x;
    int ty = tid >> 4, tx = tid & 15;
    uint32_t sA = (uint32_t)__cvta_generic_to_shared(&As[0][0][0]);
    uint32_t sB = (uint32_t)__cvta_generic_to_shared(&Bs[0][0][0]);
    float acc[4][4];
    #pragma unroll
    for (int i = 0; i < 4; i++)
        #pragma unroll
        for (int j = 0; j < 4; j++) acc[i][j] = 0.f;

    int nstage = Kd >> 5;
    auto fill = [&](int s, int k0) {
        #pragma unroll
        for (int j = 0; j < 2; j++) {
            int c = tid + j*256;
            int r = c >> 3, q = c & 7;
            cp16(sA + (uint32_t)(s*64*32 + r*32 + q*4)*4,
                 A + (size_t)(m0 + r)*lda + k0 + q*4);
            int rb = c >> 4, qb = c & 15;
            cp16(sB + (uint32_t)(s*32*68 + rb*68 + qb*4)*4,
                 B + (size_t)(k0 + rb)*ldb + n0 + qb*4);
        }
        asm volatile("cp.async.commit_group;");
    };

    fill(0, 0);
    for (int s = 0; s < nstage; s++) {
        if (s + 1 < nstage) {
            fill((s + 1) & 1, (s + 1) << 5);
            asm volatile("cp.async.wait_group 1;");
        } else {
            asm volatile("cp.async.wait_group 0;");
        }
        __syncthreads();
        int bs = s & 1;
        #pragma unroll
        for (int k4 = 0; k4 < 8; k4++) {
            float4 a4[4];
            #pragma unroll
            for (int i = 0; i < 4; i++)
                a4[i] = *(const float4*)&As[bs][ty*4 + i][k4*4];
            #pragma unroll
            for (int kk = 0; kk < 4; kk++) {
                float4 b4 = *(const float4*)&Bs[bs][k4*4 + kk][tx*4];
                float a0 = (&a4[0].x)[kk], a1 = (&a4[1].x)[kk],
                      a2 = (&a4[2].x)[kk], a3 = (&a4[3].x)[kk];
                acc[0][0] += a0*b4.x; acc[0][1] += a0*b4.y; acc[0][2] += a0*b4.z; acc[0][3] += a0*b4.w;
                acc[1][0] += a1*b4.x; acc[1][1] += a1*b4.y; acc[1][2] += a1*b4.z; acc[1][3] += a1*b4.w;
                acc[2][0] += a2*b4.x; acc[2][1] += a2*b4.y; acc[2][2] += a2*b4.z; acc[2][3] += a2*b4.w;
                acc[3][0] += a3*b4.x; acc[3][1] += a3*b4.y; acc[3][2] += a3*b4.z; acc[3][3] += a3*b4.w;
            }
        }
        __syncthreads();
    }
    #pragma unroll
    for (int i = 0; i < 4; i++) {
        int row = m0 + ty*4 + i;
        #pragma unroll
        for (int j = 0; j < 4; j++) {
            int col = n0 + tx*4 + j;
            float v = acc[i][j];
            if (bias) v += bias[col];
            if (act)  v = fasttanh(v);
            C[(size_t)row*ldc + col] = v;
        }
    }
}

// ---------------- dual-output cp.async SGEMM, kk-by-4 float4 ----------------
__global__ __launch_bounds__(256) void sgemm_ca_dual(const float* __restrict__ A, int lda,
                                                     const float* __restrict__ B0,
                                                     const float* __restrict__ B1, int ldb,
                                                     const float* __restrict__ bias0,
                                                     const float* __restrict__ bias1,
                                                     float* __restrict__ C0,
                                                     float* __restrict__ C1, int ldc,
                                                     int Kd)
{
    __shared__ float As[2][64][32];
    __shared__ float Bs[2][32][68];
    int hx = gridDim.x >> 1;
    int half = blockIdx.x >= hx;
    const float* B    = half ? B1    : B0;
    const float* bias = half ? bias1 : bias0;
    float*       C    = half ? C1    : C0;
    int n0 = (blockIdx.x - half*hx) * 64;
    int m0 = blockIdx.y * 64;
    int tid = threadIdx.x;
    int ty = tid >> 4, tx = tid & 15;
    uint32_t sA = (uint32_t)__cvta_generic_to_shared(&As[0][0][0]);
    uint32_t sB = (uint32_t)__cvta_generic_to_shared(&Bs[0][0][0]);
    float acc[4][4];
    #pragma unroll
    for (int i = 0; i < 4; i++)
        #pragma unroll
        for (int j = 0; j < 4; j++) acc[i][j] = 0.f;

    int nstage = Kd >> 5;
    auto fill = [&](int s, int k0) {
        #pragma unroll
        for (int j = 0; j < 2; j++) {
            int c = tid + j*256;
            int r = c >> 3, q = c & 7;
            cp16(sA + (uint32_t)(s*64*32 + r*32 + q*4)*4,
                 A + (size_t)(m0 + r)*lda + k0 + q*4);
            int rb = c >> 4, qb = c & 15;
            cp16(sB + (uint32_t)(s*32*68 + rb*68 + qb*4)*4,
                 B + (size_t)(k0 + rb)*ldb + n0 + qb*4);
        }
        asm volatile("cp.async.commit_group;");
    };

    fill(0, 0);
    for (int s = 0; s < nstage; s++) {
        if (s + 1 < nstage) {
            fill((s + 1) & 1, (s + 1) << 5);
            asm volatile("cp.async.wait_group 1;");
        } else {
            asm volatile("cp.async.wait_group 0;");
        }
        __syncthreads();
        int bs = s & 1;
        #pragma unroll
        for (int k4 = 0; k4 < 8; k4++) {
            float4 a4[4];
            #pragma unroll
            for (int i = 0; i < 4; i++)
                a4[i] = *(const float4*)&As[bs][ty*4 + i][k4*4];
            #pragma unroll
            for (int kk = 0; kk < 4; kk++) {
                float4 b4 = *(const float4*)&Bs[bs][k4*4 + kk][tx*4];
                float a0 = (&a4[0].x)[kk], a1 = (&a4[1].x)[kk],
                      a2 = (&a4[2].x)[kk], a3 = (&a4[3].x)[kk];
                acc[0][0] += a0*b4.x; acc[0][1] += a0*b4.y; acc[0][2] += a0*b4.z; acc[0][3] += a0*b4.w;
                acc[1][0] += a1*b4.x; acc[1][1] += a1*b4.y; acc[1][2] += a1*b4.z; acc[1][3] += a1*b4.w;
                acc[2][0] += a2*b4.x; acc[2][1] += a2*b4.y; acc[2][2] += a2*b4.z; acc[2][3] += a2*b4.w;
                acc[3][0] += a3*b4.x; acc[3][1] += a3*b4.y; acc[3][2] += a3*b4.z; acc[3][3] += a3*b4.w;
            }
        }
        __syncthreads();
    }
    #pragma unroll
    for (int i = 0; i < 4; i++) {
        int row = m0 + ty*4 + i;
        #pragma unroll
        for (int j = 0; j < 4; j++) {
            int col = n0 + tx*4 + j;
            float v = acc[i][j];
            if (bias) v += bias[col];
            C[(size_t)row*ldc + col] = v;
        }
    }
}

// ---------------- fused scores + softmax over mentions ----------------
__global__ __launch_bounds__(128) void k_scsm(const float* __restrict__ mask)
{
    int be = blockIdx.x;
    int tid = threadIdx.x;
    __shared__ float st[NM*RR];
    for (int i = tid; i < NM*RR/4; i += 128)
        *(float4*)&st[i*4] = *(const float4*)&g_t1[(size_t)be*NM*RR + i*4];
    __syncthreads();
    if (tid >= KK) return;
    float sc[NM];
    #pragma unroll
    for (int m = 0; m < NM; m++)
        sc[m] = (1.0f - mask[be*NM + m]) * (-1e6f);
    for (int j = 0; j < RR; j++) {
        float a = g_anT[j*128 + tid];
        #pragma unroll
        for (int m = 0; m < NM; m++) sc[m] += st[m*RR + j] * a;
    }
    float mx = sc[0];
    #pragma unroll
    for (int m = 1; m < NM; m++) mx = fmaxf(mx, sc[m]);
    float ssum = 0.f;
    #pragma unroll
    for (int m = 0; m < NM; m++) { sc[m] = expf(sc[m] - mx); ssum += sc[m]; }
    float inv = 1.0f / ssum;
    #pragma unroll
    for (int m = 0; m < NM; m++) g_w[(be*KK + tid)*NM + m] = sc[m]*inv;
}

// ---------------- K7: ht + norm + x; idle blocks convert B->fp16 ----------------
#define BCONV_BLOCKS (861*BBS)
#define BCONV_N4     ((size_t)KK*DD*DD/4)
#define BCONV_CHUNK  ((BCONV_N4 + BCONV_BLOCKS - 1)/BCONV_BLOCKS)

__global__ __launch_bounds__(256) void k_htx(const float* __restrict__ blin,
                                             const float* __restrict__ bil)
{
    int b = blockIdx.y;
    int i = blockIdx.x / NE, j = blockIdx.x % NE;
    int tid = threadIdx.x;
    if (j < i) {
        size_t q = (size_t)b*861 + (size_t)i*(i-1)/2 + j;
        size_t beg = q*BCONV_CHUNK;
        size_t end = beg + BCONV_CHUNK;
        if (end > BCONV_N4) end = BCONV_N4;
        __half2* ph = (__half2*)g_Bhi;
        for (size_t i4 = beg + tid; i4 < end; i4 += 256) {
            float4 v = ((const float4*)bil)[i4];
            ph[i4*2+0] = __floats2half2_rn(v.x, v.y);
            ph[i4*2+1] = __floats2half2_rn(v.z, v.w);
        }
        return;
    }
    const float* ai = g_as + ((size_t)(b*NE + i))*LL*HH;
    const float* aj = g_as + ((size_t)(b*NE + j))*LL*HH;
    const float* s3 = g_S3 + b*LL*3;
    float sum = 0.f, x0 = 0.f, x1 = 0.f, x2 = 0.f;
    for (int l = tid; l < LL; l += 256) {
        float4 u0 = *(const float4*)&ai[l*HH + 0];
        float4 u1 = *(const float4*)&ai[l*HH + 4];
        float4 u2 = *(const float4*)&ai[l*HH + 8];
        float4 v0 = *(const float4*)&aj[l*HH + 0];
        float4 v1 = *(const float4*)&aj[l*HH + 4];
        float4 v2 = *(const float4*)&aj[l*HH + 8];
        float acc = u0.x*v0.x + u0.y*v0.y + u0.z*v0.z + u0.w*v0.w
                  + u1.x*v1.x + u1.y*v1.y + u1.z*v1.z + u1.w*v1.w
                  + u2.x*v2.x + u2.y*v2.y + u2.z*v2.z + u2.w*v2.w;
        acc *= (1.0f / HH);
        sum += acc;
        x0 += acc * s3[l*3+0];
        x1 += acc * s3[l*3+1];
        x2 += acc * s3[l*3+2];
    }
    __shared__ float red[4][256];
    red[0][tid] = sum; red[1][tid] = x0; red[2][tid] = x1; red[3][tid] = x2;
    __syncthreads();
    for (int s2 = 128; s2 > 0; s2 >>= 1) {
        if (tid < s2) {
            red[0][tid] += red[0][tid+s2];
            red[1][tid] += red[1][tid+s2];
            red[2][tid] += red[2][tid+s2];
            red[3][tid] += red[3][tid+s2];
        }
        __syncthreads();
    }
    if (tid == 0) {
        float inv = 1.0f / (red[0][0] + 1e-5f);
        float v0 = red[1][0]*inv + blin[0];
        float v1 = red[2][0]*inv + blin[1];
        float v2 = red[3][0]*inv + blin[2];
        float* xo = g_x + ((b*NE + i)*NE + j)*3;
        xo[0] = v0; xo[1] = v1; xo[2] = v2;
        float* xm = g_x + ((b*NE + j)*NE + i)*3;
        xm[0] = v0; xm[1] = v1; xm[2] = v2;
    }
}

// ---------------- K8: 3x3 conv + relu at pair positions ----------------
__global__ void k_htss(const int* __restrict__ pairs, const float* __restrict__ Wseg,
                       const float* __restrict__ bseg)
{
    int n = blockIdx.x;
    int b = n >> 7;
    int tid = threadIdx.x;
    __shared__ int shi, sti;
    __shared__ float sx[27];
    if (tid == 0) { shi = pairs[n*2]; sti = pairs[n*2+1]; }
    __syncthreads();
    if (tid < 27) {
        int dy = tid / 9, dx = (tid / 3) % 3, c = tid % 3;
        int ii = shi + dy - 1, jj = sti + dx - 1;
        sx[tid] = (ii >= 0 && ii < NE && jj >= 0 && jj < NE)
                  ? g_x[((b*NE + ii)*NE + jj)*3 + c] : 0.f;
    }
    __syncthreads();
    float acc = bseg[tid];
    #pragma unroll
    for (int t = 0; t < 27; t++) acc += sx[t] * Wseg[t*FF + tid];
    g_htss[n*FF + tid] = fmaxf(acc, 0.f);
}

// ---------------- K10: hs,ts -> fp16 (vector w loads + tanh.approx) ----------------
__global__ __launch_bounds__(256) void k_hsts(const int* __restrict__ pairs)
{
    int n = blockIdx.x;
    int b = n >> 7;
    int tid = threadIdx.x;
    __shared__ float sT[2*NM*DD];
    int hi = pairs[n*2], ti = pairs[n*2+1];
    const float* Th = g_Th + (b*NE + hi)*NM*DD;
    const float* Tt = g_Tt + (b*NE + ti)*NM*DD;
    for (int idx = tid; idx < NM*DD; idx += 256) {
        sT[idx]         = Th[idx];
        sT[NM*DD + idx] = Tt[idx];
    }
    float rh[3], rt[3];
    #pragma unroll
    for (int i2 = 0; i2 < 3; i2++) {
        rh[i2] = g_Rh[n*DD + tid + i2*256];
        rt[i2] = g_Rt[n*DD + tid + i2*256];
    }
    __syncthreads();
    const float4* wh4 = (const float4*)(g_w + (size_t)(b*NE + hi)*KK*NM);
    const float4* wt4 = (const float4*)(g_w + (size_t)(b*NE + ti)*KK*NM);
    for (int k = 0; k < KK; k++) {
        float4 wh0 = __ldg(&wh4[k*2]),   wh1 = __ldg(&wh4[k*2+1]);
        float4 wt0 = __ldg(&wt4[k*2]),   wt1 = __ldg(&wt4[k*2+1]);
        float whr[NM] = {wh0.x, wh0.y, wh0.z, wh0.w, wh1.x, wh1.y, wh1.z, wh1.w};
        float wtr[NM] = {wt0.x, wt0.y, wt0.z, wt0.w, wt1.x, wt1.y, wt1.z, wt1.w};
        #pragma unroll
        for (int i2 = 0; i2 < 3; i2++) {
            int d = tid + i2*256;
            float ah = rh[i2], at2 = rt[i2];
            #pragma unroll
            for (int m = 0; m < NM; m++) {
                ah  += whr[m] * sT[m*DD + d];
                at2 += wtr[m] * sT[NM*DD + m*DD + d];
            }
            size_t o = (size_t)(n*KK + k)*DD + d;
            g_hsh[o]  = __float2half_rn(fasttanh(ah));
            g_tshi[o] = __float2half_rn(fasttanh(at2));
        }
    }
}

// ================= HMMA (mma.sync fp16) bilinear core, single pass =================
#define SW128(o) ((o) ^ (((o) >> 3) & 0x70))
#define TILE_BYTES 16384
#define SH_PITCH 132
#define SMEM_DYN (128*SH_PITCH*4 + 128*2*4 + 1024)

__device__ __forceinline__ void ldm4(uint32_t* r, uint32_t addr)
{
    asm volatile("ldmatrix.sync.aligned.m8n8.x4.shared.b16 {%0,%1,%2,%3}, [%4];"
                 : "=r"(r[0]), "=r"(r[1]), "=r"(r[2]), "=r"(r[3]) : "r"(addr));
}
__device__ __forceinline__ void mma16816(float* c, const uint32_t* a, const uint32_t* b)
{
    asm volatile("mma.sync.aligned.m16n8k16.row.col.f32.f16.f16.f32 "
                 "{%0,%1,%2,%3}, {%4,%5,%6,%7}, {%8,%9}, {%0,%1,%2,%3};"
                 : "+f"(c[0]), "+f"(c[1]), "+f"(c[2]), "+f"(c[3])
                 : "r"(a[0]), "r"(a[1]), "r"(a[2]), "r"(a[3]), "r"(b[0]), "r"(b[1]));
}

__global__ __launch_bounds__(256) void k_bilinear_mma()
{
    extern __shared__ char dsm[];
    char* smem = (char*)((((uintptr_t)dsm) + 1023) & ~(uintptr_t)1023);
    uint32_t sbase = (uint32_t)__cvta_generic_to_shared(smem);

    const int k  = blockIdx.y;
    const int nt = blockIdx.x & 3;
    const int dt = blockIdx.x >> 2;
    const int n0 = nt * 128, d0 = dt * 128;
    const int tid = threadIdx.x;
    const int lane = tid & 31, wid = tid >> 5;
    const int wm = (wid & 3) * 32;
    const int wn = (wid >> 2) * 64;

    const __half* Abase = g_tshi + ((size_t)n0 * KK + k) * DD;
    const __half* Bbase = g_Bhi + ((size_t)k * DD + d0) * DD;

    float acc[2][8][4];
    #pragma unroll
    for (int mi = 0; mi < 2; mi++)
        #pragma unroll
        for (int ni = 0; ni < 8; ni++)
            #pragma unroll
            for (int j = 0; j < 4; j++) acc[mi][ni][j] = 0.f;

    auto fill = [&](int it, int buf) {
        int k0 = it * 64;
        uint32_t abase = sbase + buf*2*TILE_BYTES;
        uint32_t bbase = abase + TILE_BYTES;
        #pragma unroll
        for (int j = 0; j < 8; j++) {
            int c = tid + j*256;
            if (c < 1024) {
                int r = c >> 3, q = c & 7;
                cp16(abase + SW128(r*128 + q*16), Abase + (size_t)r*(KK*DD) + k0 + q*8);
            } else {
                int c2 = c - 1024;
                int r = c2 >> 3, q = c2 & 7;
                cp16(bbase + SW128(r*128 + q*16), Bbase + (size_t)r*DD + k0 + q*8);
            }
        }
    };

    fill(0, 0);
    asm volatile("cp.async.commit_group;");

    for (int i = 0; i < 12; i++) {
        if (i + 1 < 12) {
            fill(i + 1, (i + 1) & 1);
            asm volatile("cp.async.commit_group;");
            asm volatile("cp.async.wait_group 1;");
        } else {
            asm volatile("cp.async.wait_group 0;");
        }
        __syncthreads();

        uint32_t abase = sbase + (i & 1)*2*TILE_BYTES;
        uint32_t bbase = abase + TILE_BYTES;
        #pragma unroll
        for (int ks = 0; ks < 4; ks++) {
            uint32_t af[2][4];
            #pragma unroll
            for (int mi = 0; mi < 2; mi++) {
                int row = wm + mi*16 + ((lane >> 3) & 1)*8 + (lane & 7);
                int cb  = ks*32 + (lane >> 4)*16;
                ldm4(af[mi], abase + SW128(row*128 + cb));
            }
            uint32_t bf[8][2];
            #pragma unroll
            for (int q = 0; q < 4; q++) {
                uint32_t r[4];
                int nrow = wn + (2*q + (lane >> 4))*8 + (lane & 7);
                int cb   = ks*32 + ((lane >> 3) & 1)*16;
                ldm4(r, bbase + SW128(nrow*128 + cb));
                bf[2*q+0][0] = r[0]; bf[2*q+0][1] = r[1];
                bf[2*q+1][0] = r[2]; bf[2*q+1][1] = r[3];
            }
            #pragma unroll
            for (int mi = 0; mi < 2; mi++)
                #pragma unroll
                for (int ni = 0; ni < 8; ni++)
                    mma16816(acc[mi][ni], af[mi], bf[ni]);
        }
        __syncthreads();
    }

    // ---- epilogue: partial[n] = sum_d C[n][d]*hs[n][d] ----
    float* sH  = (float*)smem;
    float* red = (float*)(smem + 128*SH_PITCH*4);
    for (int idx = tid; idx < 128*16; idx += 256) {
        int r = idx >> 4, c8 = idx & 15;
        const __half2* hp = (const __half2*)(g_hsh + ((size_t)(n0 + r)*KK + k)*DD + d0 + c8*8);
        float* dst = &sH[r*SH_PITCH + c8*8];
        #pragma unroll
        for (int u = 0; u < 4; u++) {
            float2 f = __half22float2(hp[u]);
            dst[u*2+0] = f.x; dst[u*2+1] = f.y;
        }
    }
    __syncthreads();

    float p[2][2] = {{0.f, 0.f}, {0.f, 0.f}};
    #pragma unroll
    for (int mi = 0; mi < 2; mi++) {
        int r0 = wm + mi*16 + (lane >> 2);
        #pragma unroll
        for (int ni = 0; ni < 8; ni++) {
            int cb = wn + ni*8 + (lane & 3)*2;
            p[mi][0] += acc[mi][ni][0]*sH[r0*SH_PITCH + cb]
                      + acc[mi][ni][1]*sH[r0*SH_PITCH + cb + 1];
            p[mi][1] += acc[mi][ni][2]*sH[(r0+8)*SH_PITCH + cb]
                      + acc[mi][ni][3]*sH[(r0+8)*SH_PITCH + cb + 1];
        }
    }
    #pragma unroll
    for (int mi = 0; mi < 2; mi++)
        #pragma unroll
        for (int h = 0; h < 2; h++) {
            p[mi][h] += __shfl_xor_sync(0xffffffffu, p[mi][h], 1);
            p[mi][h] += __shfl_xor_sync(0xffffffffu, p[mi][h], 2);
        }
    if ((lane & 3) == 0) {
        int nw = wid >> 2;
        int rr = lane >> 2;
        #pragma unroll
        for (int mi = 0; mi < 2; mi++) {
            red[(wm + mi*16 + rr)*2 + nw]     = p[mi][0];
            red[(wm + mi*16 + rr + 8)*2 + nw] = p[mi][1];
        }
    }
    __syncthreads();
    if (tid < 128)
        g_part[((size_t)dt*NP + n0 + tid)*KK + k] = red[tid*2] + red[tid*2+1];
}

// ---------------- K13: finalize ----------------
__global__ void k_final(const float* __restrict__ bilb, float* __restrict__ out)
{
    int idx = blockIdx.x*256 + threadIdx.x;
    if (idx >= NP*KK) return;
    int k = idx % KK;
    float s = bilb[k];
    #pragma unroll
    for (int t = 0; t < 6; t++) s += g_part[t*(NP*KK) + idx];
    out[idx] = s;
}

// ---------------- launch ----------------
extern "C" void kernel_launch(void* const* d_in, const int* in_sizes, int n_in,
                              void* d_out, int out_size)
{
    const float* seq      = (const float*)d_in[0];
    const float* att      = (const float*)d_in[1];
    const float* mask     = (const float*)d_in[2];
    const int*   mpos     = (const int*)  d_in[3];
    const int*   pairs    = (const int*)  d_in[4];
    const float* Wattn    = (const float*)d_in[5];
    const float* battn    = (const float*)d_in[6];
    const float* attn_net = (const float*)d_in[7];
    const float* Wlin     = (const float*)d_in[8];
    const float* blin     = (const float*)d_in[9];
    const float* Wseg     = (const float*)d_in[10];
    const float* bseg     = (const float*)d_in[11];
    const float* Whead    = (const float*)d_in[12];
    const float* bhead    = (const float*)d_in[13];
    const float* Wtail    = (const float*)d_in[14];
    const float* btail    = (const float*)d_in[15];
    const float* bil      = (const float*)d_in[16];
    const float* bilb     = (const float*)d_in[17];
    float* out = (float*)d_out;

    float *emb, *t1, *htss, *Th, *Tt, *Rh, *Rt;
    cudaGetSymbolAddress((void**)&emb,  g_emb);
    cudaGetSymbolAddress((void**)&t1,   g_t1);
    cudaGetSymbolAddress((void**)&htss, g_htss);
    cudaGetSymbolAddress((void**)&Th,   g_Th);
    cudaGetSymbolAddress((void**)&Tt,   g_Tt);
    cudaGetSymbolAddress((void**)&Rh,   g_Rh);
    cudaGetSymbolAddress((void**)&Rt,   g_Rt);

    cudaFuncSetAttribute(k_bilinear_mma, cudaFuncAttributeMaxDynamicSharedMemorySize, SMEM_DYN);

    // 1. fused prep: emb gather | as gather (one blk per be,h) | antn transpose | S3
    k_prep<<<EMB_BLKS + AS_BLKS + ANTR_BLKS + S3_BLKS, 256>>>(seq, att, mask, mpos, attn_net, Wlin);
    // 2. t1 = tanh(emb @ Wattn + battn)
    sgemm_ca<<<dim3(RR/64, (BBS*NE*NM)/64), 256>>>(emb, DD, Wattn, RR, battn, t1, RR, DD, 1);
    // 3. fused scores + softmax
    k_scsm<<<BBS*NE, 128>>>(mask);
    // 4/5. T_h / T_t merged
    sgemm_ca_dual<<<dim3(2*(DD/64), (BBS*NE*NM)/64), 256>>>(emb, DD, Whead, Wtail, DD,
                                                            nullptr, nullptr, Th, Tt, DD, DD);
    // 6/7. ht -> x  (idle blocks convert bilinear weights to fp16)
    k_htx<<<dim3(NE*NE, BBS), 256>>>(blin, bil);
    // 8. conv + relu at pairs
    k_htss<<<NP, 256>>>(pairs, Wseg, bseg);
    // 9. Rh / Rt merged
    sgemm_ca_dual<<<dim3(2*(DD/64), NP/64), 256>>>(htss, FF, Whead + DD*DD, Wtail + DD*DD, DD,
                                                   bhead, btail, Rh, Rt, DD, FF);
    // 10. hs,ts fp16
    k_hsts<<<NP, 256>>>(pairs);
    // 11. HMMA bilinear: grid (24 tiles, 97 k), fp16 single pass
    k_bilinear_mma<<<dim3(24, 97), 256, SMEM_DYN>>>();
    // 12. finalize
    k_final<<<(NP*KK + 255)/256, 256>>>(bilb, out);
}

// round 13
// speedup vs baseline: 1.5115x; 1.1615x over previous
#include <cuda_runtime.h>
#include <cuda_fp16.h>
#include <math.h>
#include <stdint.h>

#define NE 42
#define NM 8
#define LL 1024
#define DD 768
#define HH 12
#define KK 97
#define FF 256
#define RR 256
#define BBS 4
#define NP 512   /* bs * P */
#define MEMB (BBS*NE*NM)     /* 1344 */
#define MEMBP 1408           /* padded to 128 multiple */

// ---------------- scratch (device globals; no allocs) ----------------
__device__ float g_emb [BBS*NE*NM*DD];
__device__ float g_as  [BBS*NE*LL*HH];     // TRANSPOSED: [be][l][h]
__device__ float g_t1  [BBS*NE*NM*RR];
__device__ float g_anT [RR*128];
__device__ float g_w   [BBS*NE*KK*NM];
__device__ float g_Th  [BBS*NE*NM*DD];
__device__ float g_Tt  [BBS*NE*NM*DD];
__device__ float g_S3  [BBS*LL*3];
__device__ float g_x   [BBS*NE*NE*3];
__device__ float g_Rh  [NP*DD];
__device__ float g_Rt  [NP*DD];
__device__ __align__(16) __half g_embh [MEMBP*DD];   // fp16 emb, zero-padded rows
__device__ __align__(16) __half g_htssh[NP*FF];      // fp16 conv output
__device__ __align__(16) __half g_Whh[DD*DD];        // Whead top, transposed [out][in]
__device__ __align__(16) __half g_Wth[DD*DD];        // Wtail top, transposed
__device__ __align__(16) __half g_Whb[DD*FF];        // Whead bottom, transposed [out][in]
__device__ __align__(16) __half g_Wtb[DD*FF];        // Wtail bottom, transposed
__device__ __align__(16) __half g_hsh [NP*KK*DD];
__device__ __align__(16) __half g_tshi[NP*KK*DD];
__device__ __align__(16) __half g_Bhi [KK*DD*DD];
__device__ float g_part[6*NP*KK];

__device__ __forceinline__ float fasttanh(float x)
{
    float y;
    asm("tanh.approx.f32 %0, %1;" : "=f"(y) : "f"(x));
    return y;
}

__device__ __forceinline__ void cp16(uint32_t dst, const void* src)
{
    asm volatile("cp.async.cg.shared.global [%0], [%1], 16;" :: "r"(dst), "l"(src));
}

// ---------------- K0: weight fp16 transpose/convert ----------------
#define WTOP (DD*DD)        /* 589824 */
#define WBOT (DD*FF)        /* 196608 */
#define WC_TOTAL (2*WTOP + 2*WBOT)

__global__ void k_wconv(const float* __restrict__ Whead, const float* __restrict__ Wtail)
{
    int idx = blockIdx.x*256 + threadIdx.x;
    if (idx < WTOP) {
        int n = idx / DD, k = idx % DD;
        g_Whh[idx] = __float2half_rn(Whead[(size_t)k*DD + n]);
    } else if (idx < 2*WTOP) {
        int q = idx - WTOP;
        int n = q / DD, k = q % DD;
        g_Wth[q] = __float2half_rn(Wtail[(size_t)k*DD + n]);
    } else if (idx < 2*WTOP + WBOT) {
        int q = idx - 2*WTOP;
        int n = q / FF, k = q % FF;
        g_Whb[q] = __float2half_rn(Whead[(size_t)(DD + k)*DD + n]);
    } else if (idx < WC_TOTAL) {
        int q = idx - 2*WTOP - WBOT;
        int n = q / FF, k = q % FF;
        g_Wtb[q] = __float2half_rn(Wtail[(size_t)(DD + k)*DD + n]);
    }
}

// ---------------- K1: fused prep: emb gather | as gather | antr | S3 | emb pad ----------------
#define EMB_BLKS  (BBS*NE)            /* 168 */
#define AS_BLKS   (BBS*NE*HH)         /* 2016 */
#define ANTR_BLKS 128
#define S3_BLKS   ((BBS*LL)/2)        /* 2048 */
#define PAD_BLKS  1

__global__ __launch_bounds__(256) void k_prep(const float* __restrict__ seq,
                                              const float* __restrict__ att,
                                              const float* __restrict__ mask,
                                              const int* __restrict__ mpos,
                                              const float* __restrict__ attn_net,
                                              const float* __restrict__ Wlin)
{
    int bid = blockIdx.x;
    int tid = threadIdx.x;
    if (bid < EMB_BLKS) {
        int be = bid;
        int b  = be / NE;
        __shared__ int   spos[NM];
        __shared__ float smk [NM];
        if (tid < NM) {
            int p = mpos[be*NM + tid] + 1;
            p = max(0, min(p, LL-1));
            spos[tid] = p;
            smk[tid]  = mask[be*NM + tid];
        }
        __syncthreads();
        for (int idx = tid; idx < NM*DD; idx += 256) {
            int m = idx / DD, d = idx - m*DD;
            float v = seq[(b*LL + spos[m])*DD + d] * smk[m];
            g_emb [be*NM*DD + idx] = v;
            g_embh[(size_t)be*NM*DD + idx] = __float2half_rn(v);
        }
    } else if (bid < EMB_BLKS + AS_BLKS) {
        int q = bid - EMB_BLKS;
        int be = q / HH, h = q % HH;
        int b  = be / NE;
        __shared__ int   spos[NM];
        __shared__ float smk [NM];
        __shared__ float sinv;
        if (tid < NM) {
            int p = mpos[be*NM + tid] + 1;
            p = max(0, min(p, LL-1));
            spos[tid] = p;
            smk[tid]  = mask[be*NM + tid];
        }
        __syncthreads();
        if (tid == 0) {
            float c = 0.f;
            #pragma unroll
            for (int m = 0; m < NM; m++) c += smk[m];
            sinv = 1.0f / fmaxf(c, 1.0f);
        }
        __syncthreads();
        for (int l = tid; l < LL; l += 256) {
            float acc = 0.f;
            #pragma unroll
            for (int m = 0; m < NM; m++)
                acc += att[((b*HH + h)*LL + spos[m])*LL + l] * smk[m];
            g_as[((size_t)be*LL + l)*HH + h] = acc * sinv;
        }
    } else if (bid < EMB_BLKS + AS_BLKS + ANTR_BLKS) {
        int idx = (bid - EMB_BLKS - AS_BLKS)*256 + tid;
        int j = idx >> 7, k = idx & 127;
        g_anT[idx] = (k < KK) ? attn_net[k*RR + j] : 0.f;
    } else if (bid < EMB_BLKS + AS_BLKS + ANTR_BLKS + S3_BLKS) {
        int rp = bid - EMB_BLKS - AS_BLKS - ANTR_BLKS;
        int half = tid >> 7;
        int t2 = tid & 127;
        int row = rp*2 + half;
        const float* s = seq + (size_t)row*DD;
        float a0 = 0.f, a1 = 0.f, a2 = 0.f;
        for (int j = t2; j < DD; j += 128) {
            float v = s[j];
            a0 += v*Wlin[j*3+0]; a1 += v*Wlin[j*3+1]; a2 += v*Wlin[j*3+2];
        }
        __shared__ float red[2][3][128];
        red[half][0][t2] = a0; red[half][1][t2] = a1; red[half][2][t2] = a2;
        __syncthreads();
        for (int s2 = 64; s2 > 0; s2 >>= 1) {
            if (t2 < s2) {
                red[half][0][t2] += red[half][0][t2+s2];
                red[half][1][t2] += red[half][1][t2+s2];
                red[half][2][t2] += red[half][2][t2+s2];
            }
            __syncthreads();
        }
        if (t2 < 3) g_S3[row*3 + t2] = red[half][t2][0];
    } else {
        // zero-pad g_embh rows MEMB..MEMBP
        __half z = __float2half_rn(0.f);
        for (int idx = tid; idx < (MEMBP - MEMB)*DD; idx += 256)
            g_embh[(size_t)MEMB*DD + idx] = z;
    }
}

// ---------------- cp.async double-buffered SGEMM (64x64x32), kk-by-4 float4 — t1 only ----------------
__global__ __launch_bounds__(256) void sgemm_ca(const float* __restrict__ A, int lda,
                                                const float* __restrict__ B, int ldb,
                                                const float* __restrict__ bias,
                                                float* __restrict__ C, int ldc,
                                                int Kd, int act)
{
    __shared__ float As[2][64][32];
    __shared__ float Bs[2][32][68];
    int m0 = blockIdx.y * 64, n0 = blockIdx.x * 64;
    int tid = threadIdx.x;
    int ty = tid >> 4, tx = tid & 15;
    uint32_t sA = (uint32_t)__cvta_generic_to_shared(&As[0][0][0]);
    uint32_t sB = (uint32_t)__cvta_generic_to_shared(&Bs[0][0][0]);
    float acc[4][4];
    #pragma unroll
    for (int i = 0; i < 4; i++)
        #pragma unroll
        for (int j = 0; j < 4; j++) acc[i][j] = 0.f;

    int nstage = Kd >> 5;
    auto fill = [&](int s, int k0) {
        #pragma unroll
        for (int j = 0; j < 2; j++) {
            int c = tid + j*256;
            int r = c >> 3, q = c & 7;
            cp16(sA + (uint32_t)(s*64*32 + r*32 + q*4)*4,
                 A + (size_t)(m0 + r)*lda + k0 + q*4);
            int rb = c >> 4, qb = c & 15;
            cp16(sB + (uint32_t)(s*32*68 + rb*68 + qb*4)*4,
                 B + (size_t)(k0 + rb)*ldb + n0 + qb*4);
        }
        asm volatile("cp.async.commit_group;");
    };

    fill(0, 0);
    for (int s = 0; s < nstage; s++) {
        if (s + 1 < nstage) {
            fill((s + 1) & 1, (s + 1) << 5);
            asm volatile("cp.async.wait_group 1;");
        } else {
            asm volatile("cp.async.wait_group 0;");
        }
        __syncthreads();
        int bs = s & 1;
        #pragma unroll
        for (int k4 = 0; k4 < 8; k4++) {
            float4 a4[4];
            #pragma unroll
            for (int i = 0; i < 4; i++)
                a4[i] = *(const float4*)&As[bs][ty*4 + i][k4*4];
            #pragma unroll
            for (int kk = 0; kk < 4; kk++) {
                float4 b4 = *(const float4*)&Bs[bs][k4*4 + kk][tx*4];
                float a0 = (&a4[0].x)[kk], a1 = (&a4[1].x)[kk],
                      a2 = (&a4[2].x)[kk], a3 = (&a4[3].x)[kk];
                acc[0][0] += a0*b4.x; acc[0][1] += a0*b4.y; acc[0][2] += a0*b4.z; acc[0][3] += a0*b4.w;
                acc[1][0] += a1*b4.x; acc[1][1] += a1*b4.y; acc[1][2] += a1*b4.z; acc[1][3] += a1*b4.w;
                acc[2][0] += a2*b4.x; acc[2][1] += a2*b4.y; acc[2][2] += a2*b4.z; acc[2][3] += a2*b4.w;
                acc[3][0] += a3*b4.x; acc[3][1] += a3*b4.y; acc[3][2] += a3*b4.z; acc[3][3] += a3*b4.w;
            }
        }
        __syncthreads();
    }
    #pragma unroll
    for (int i = 0; i < 4; i++) {
        int row = m0 + ty*4 + i;
        #pragma unroll
        for (int j = 0; j < 4; j++) {
            int col = n0 + tx*4 + j;
            float v = acc[i][j];
            if (bias) v += bias[col];
            if (act)  v = fasttanh(v);
            C[(size_t)row*ldc + col] = v;
        }
    }
}

// ---------------- fused scores + softmax over mentions ----------------
__global__ __launch_bounds__(128) void k_scsm(const float* __restrict__ mask)
{
    int be = blockIdx.x;
    int tid = threadIdx.x;
    __shared__ float st[NM*RR];
    for (int i = tid; i < NM*RR/4; i += 128)
        *(float4*)&st[i*4] = *(const float4*)&g_t1[(size_t)be*NM*RR + i*4];
    __syncthreads();
    if (tid >= KK) return;
    float sc[NM];
    #pragma unroll
    for (int m = 0; m < NM; m++)
        sc[m] = (1.0f - mask[be*NM + m]) * (-1e6f);
    for (int j = 0; j < RR; j++) {
        float a = g_anT[j*128 + tid];
        #pragma unroll
        for (int m = 0; m < NM; m++) sc[m] += st[m*RR + j] * a;
    }
    float mx = sc[0];
    #pragma unroll
    for (int m = 1; m < NM; m++) mx = fmaxf(mx, sc[m]);
    float ssum = 0.f;
    #pragma unroll
    for (int m = 0; m < NM; m++) { sc[m] = expf(sc[m] - mx); ssum += sc[m]; }
    float inv = 1.0f / ssum;
    #pragma unroll
    for (int m = 0; m < NM; m++) g_w[(be*KK + tid)*NM + m] = sc[m]*inv;
}

// ================= shared HMMA helpers =================
#define SW128(o) ((o) ^ (((o) >> 3) & 0x70))
#define TILE_BYTES 16384

__device__ __forceinline__ void ldm4(uint32_t* r, uint32_t addr)
{
    asm volatile("ldmatrix.sync.aligned.m8n8.x4.shared.b16 {%0,%1,%2,%3}, [%4];"
                 : "=r"(r[0]), "=r"(r[1]), "=r"(r[2]), "=r"(r[3]) : "r"(addr));
}
__device__ __forceinline__ void mma16816(float* c, const uint32_t* a, const uint32_t* b)
{
    asm volatile("mma.sync.aligned.m16n8k16.row.col.f32.f16.f16.f32 "
                 "{%0,%1,%2,%3}, {%4,%5,%6,%7}, {%8,%9}, {%0,%1,%2,%3};"
                 : "+f"(c[0]), "+f"(c[1]), "+f"(c[2]), "+f"(c[3])
                 : "r"(a[0]), "r"(a[1]), "r"(a[2]), "r"(a[3]), "r"(b[0]), "r"(b[1]));
}

// ---------------- generic NT fp16 HMMA GEMM, fp32 out, dual pair via z ----------------
#define HG_SMEM (2*2*TILE_BYTES + 1024)
__global__ __launch_bounds__(256) void k_hgemm(const __half* __restrict__ A, int lda,
                                               const __half* __restrict__ B0T,
                                               const __half* __restrict__ B1T, int ldb,
                                               const float* __restrict__ bias0,
                                               const float* __restrict__ bias1,
                                               float* __restrict__ C0,
                                               float* __restrict__ C1,
                                               int M, int ldc, int Kd)
{
    extern __shared__ char dsm[];
    char* smem = (char*)((((uintptr_t)dsm) + 1023) & ~(uintptr_t)1023);
    uint32_t sbase = (uint32_t)__cvta_generic_to_shared(smem);

    const __half* Bt  = blockIdx.z ? B1T : B0T;
    const float* bias = blockIdx.z ? bias1 : bias0;
    float* C          = blockIdx.z ? C1 : C0;
    const int n0 = blockIdx.x * 128;
    const int m0 = blockIdx.y * 128;
    const int tid = threadIdx.x;
    const int lane = tid & 31, wid = tid >> 5;
    const int wm = (wid & 3) * 32;      // m offset within tile
    const int wn = (wid >> 2) * 64;     // n offset within tile

    const __half* Abase = A + (size_t)m0*lda;
    const __half* Bbase = Bt + (size_t)n0*ldb;

    float acc[2][8][4];
    #pragma unroll
    for (int mi = 0; mi < 2; mi++)
        #pragma unroll
        for (int ni = 0; ni < 8; ni++)
            #pragma unroll
            for (int j = 0; j < 4; j++) acc[mi][ni][j] = 0.f;

    auto fill = [&](int it, int buf) {
        int k0 = it * 64;
        uint32_t abase = sbase + buf*2*TILE_BYTES;
        uint32_t bbase = abase + TILE_BYTES;
        #pragma unroll
        for (int j = 0; j < 8; j++) {
            int c = tid + j*256;
            if (c < 1024) {
                int r = c >> 3, q = c & 7;
                cp16(abase + SW128(r*128 + q*16), Abase + (size_t)r*lda + k0 + q*8);
            } else {
                int c2 = c - 1024;
                int r = c2 >> 3, q = c2 & 7;
                cp16(bbase + SW128(r*128 + q*16), Bbase + (size_t)r*ldb + k0 + q*8);
            }
        }
    };

    int nstage = Kd >> 6;
    fill(0, 0);
    asm volatile("cp.async.commit_group;");

    for (int i = 0; i < nstage; i++) {
        if (i + 1 < nstage) {
            fill(i + 1, (i + 1) & 1);
            asm volatile("cp.async.commit_group;");
            asm volatile("cp.async.wait_group 1;");
        } else {
            asm volatile("cp.async.wait_group 0;");
        }
        __syncthreads();

        uint32_t abase = sbase + (i & 1)*2*TILE_BYTES;
        uint32_t bbase = abase + TILE_BYTES;
        #pragma unroll
        for (int ks = 0; ks < 4; ks++) {
            uint32_t af[2][4];
            #pragma unroll
            for (int mi = 0; mi < 2; mi++) {
                int row = wm + mi*16 + ((lane >> 3) & 1)*8 + (lane & 7);
                int cb  = ks*32 + (lane >> 4)*16;
                ldm4(af[mi], abase + SW128(row*128 + cb));
            }
            uint32_t bf[8][2];
            #pragma unroll
            for (int q = 0; q < 4; q++) {
                uint32_t r[4];
                int nrow = wn + (2*q + (lane >> 4))*8 + (lane & 7);
                int cb   = ks*32 + ((lane >> 3) & 1)*16;
                ldm4(r, bbase + SW128(nrow*128 + cb));
                bf[2*q+0][0] = r[0]; bf[2*q+0][1] = r[1];
                bf[2*q+1][0] = r[2]; bf[2*q+1][1] = r[3];
            }
            #pragma unroll
            for (int mi = 0; mi < 2; mi++)
                #pragma unroll
                for (int ni = 0; ni < 8; ni++)
                    mma16816(acc[mi][ni], af[mi], bf[ni]);
        }
        __syncthreads();
    }

    // epilogue: write fp32 C with optional bias; guard rows < M
    #pragma unroll
    for (int mi = 0; mi < 2; mi++) {
        int r0 = m0 + wm + mi*16 + (lane >> 2);
        #pragma unroll
        for (int ni = 0; ni < 8; ni++) {
            int cb = n0 + wn + ni*8 + (lane & 3)*2;
            float b0 = bias ? bias[cb] : 0.f;
            float b1 = bias ? bias[cb+1] : 0.f;
            if (r0 < M) {
                float2 v = make_float2(acc[mi][ni][0] + b0, acc[mi][ni][1] + b1);
                *(float2*)&C[(size_t)r0*ldc + cb] = v;
            }
            if (r0 + 8 < M) {
                float2 v = make_float2(acc[mi][ni][2] + b0, acc[mi][ni][3] + b1);
                *(float2*)&C[(size_t)(r0+8)*ldc + cb] = v;
            }
        }
    }
}

// ---------------- K7: ht + norm + x; idle blocks convert B->fp16 ----------------
#define BCONV_BLOCKS (861*BBS)
#define BCONV_N4     ((size_t)KK*DD*DD/4)
#define BCONV_CHUNK  ((BCONV_N4 + BCONV_BLOCKS - 1)/BCONV_BLOCKS)

__global__ __launch_bounds__(256) void k_htx(const float* __restrict__ blin,
                                             const float* __restrict__ bil)
{
    int b = blockIdx.y;
    int i = blockIdx.x / NE, j = blockIdx.x % NE;
    int tid = threadIdx.x;
    if (j < i) {
        size_t q = (size_t)b*861 + (size_t)i*(i-1)/2 + j;
        size_t beg = q*BCONV_CHUNK;
        size_t end = beg + BCONV_CHUNK;
        if (end > BCONV_N4) end = BCONV_N4;
        __half2* ph = (__half2*)g_Bhi;
        for (size_t i4 = beg + tid; i4 < end; i4 += 256) {
            float4 v = ((const float4*)bil)[i4];
            ph[i4*2+0] = __floats2half2_rn(v.x, v.y);
            ph[i4*2+1] = __floats2half2_rn(v.z, v.w);
        }
        return;
    }
    const float* ai = g_as + ((size_t)(b*NE + i))*LL*HH;
    const float* aj = g_as + ((size_t)(b*NE + j))*LL*HH;
    const float* s3 = g_S3 + b*LL*3;
    float sum = 0.f, x0 = 0.f, x1 = 0.f, x2 = 0.f;
    for (int l = tid; l < LL; l += 256) {
        float4 u0 = *(const float4*)&ai[l*HH + 0];
        float4 u1 = *(const float4*)&ai[l*HH + 4];
        float4 u2 = *(const float4*)&ai[l*HH + 8];
        float4 v0 = *(const float4*)&aj[l*HH + 0];
        float4 v1 = *(const float4*)&aj[l*HH + 4];
        float4 v2 = *(const float4*)&aj[l*HH + 8];
        float acc = u0.x*v0.x + u0.y*v0.y + u0.z*v0.z + u0.w*v0.w
                  + u1.x*v1.x + u1.y*v1.y + u1.z*v1.z + u1.w*v1.w
                  + u2.x*v2.x + u2.y*v2.y + u2.z*v2.z + u2.w*v2.w;
        acc *= (1.0f / HH);
        sum += acc;
        x0 += acc * s3[l*3+0];
        x1 += acc * s3[l*3+1];
        x2 += acc * s3[l*3+2];
    }
    __shared__ float red[4][256];
    red[0][tid] = sum; red[1][tid] = x0; red[2][tid] = x1; red[3][tid] = x2;
    __syncthreads();
    for (int s2 = 128; s2 > 0; s2 >>= 1) {
        if (tid < s2) {
            red[0][tid] += red[0][tid+s2];
            red[1][tid] += red[1][tid+s2];
            red[2][tid] += red[2][tid+s2];
            red[3][tid] += red[3][tid+s2];
        }
        __syncthreads();
    }
    if (tid == 0) {
        float inv = 1.0f / (red[0][0] + 1e-5f);
        float v0 = red[1][0]*inv + blin[0];
        float v1 = red[2][0]*inv + blin[1];
        float v2 = red[3][0]*inv + blin[2];
        float* xo = g_x + ((b*NE + i)*NE + j)*3;
        xo[0] = v0; xo[1] = v1; xo[2] = v2;
        float* xm = g_x + ((b*NE + j)*NE + i)*3;
        xm[0] = v0; xm[1] = v1; xm[2] = v2;
    }
}

// ---------------- K8: 3x3 conv + relu at pair positions (fp16 out) ----------------
__global__ void k_htss(const int* __restrict__ pairs, const float* __restrict__ Wseg,
                       const float* __restrict__ bseg)
{
    int n = blockIdx.x;
    int b = n >> 7;
    int tid = threadIdx.x;
    __shared__ int shi, sti;
    __shared__ float sx[27];
    if (tid == 0) { shi = pairs[n*2]; sti = pairs[n*2+1]; }
    __syncthreads();
    if (tid < 27) {
        int dy = tid / 9, dx = (tid / 3) % 3, c = tid % 3;
        int ii = shi + dy - 1, jj = sti + dx - 1;
        sx[tid] = (ii >= 0 && ii < NE && jj >= 0 && jj < NE)
                  ? g_x[((b*NE + ii)*NE + jj)*3 + c] : 0.f;
    }
    __syncthreads();
    float acc = bseg[tid];
    #pragma unroll
    for (int t = 0; t < 27; t++) acc += sx[t] * Wseg[t*FF + tid];
    g_htssh[n*FF + tid] = __float2half_rn(fmaxf(acc, 0.f));
}

// ---------------- K10: hs,ts -> fp16 ----------------
__global__ __launch_bounds__(256) void k_hsts(const int* __restrict__ pairs)
{
    int n = blockIdx.x;
    int b = n >> 7;
    int tid = threadIdx.x;
    __shared__ float sT[2*NM*DD];
    int hi = pairs[n*2], ti = pairs[n*2+1];
    const float* Th = g_Th + (b*NE + hi)*NM*DD;
    const float* Tt = g_Tt + (b*NE + ti)*NM*DD;
    for (int idx = tid; idx < NM*DD; idx += 256) {
        sT[idx]         = Th[idx];
        sT[NM*DD + idx] = Tt[idx];
    }
    float rh[3], rt[3];
    #pragma unroll
    for (int i2 = 0; i2 < 3; i2++) {
        rh[i2] = g_Rh[n*DD + tid + i2*256];
        rt[i2] = g_Rt[n*DD + tid + i2*256];
    }
    __syncthreads();
    const float4* wh4 = (const float4*)(g_w + (size_t)(b*NE + hi)*KK*NM);
    const float4* wt4 = (const float4*)(g_w + (size_t)(b*NE + ti)*KK*NM);
    for (int k = 0; k < KK; k++) {
        float4 wh0 = __ldg(&wh4[k*2]),   wh1 = __ldg(&wh4[k*2+1]);
        float4 wt0 = __ldg(&wt4[k*2]),   wt1 = __ldg(&wt4[k*2+1]);
        float whr[NM] = {wh0.x, wh0.y, wh0.z, wh0.w, wh1.x, wh1.y, wh1.z, wh1.w};
        float wtr[NM] = {wt0.x, wt0.y, wt0.z, wt0.w, wt1.x, wt1.y, wt1.z, wt1.w};
        #pragma unroll
        for (int i2 = 0; i2 < 3; i2++) {
            int d = tid + i2*256;
            float ah = rh[i2], at2 = rt[i2];
            #pragma unroll
            for (int m = 0; m < NM; m++) {
                ah  += whr[m] * sT[m*DD + d];
                at2 += wtr[m] * sT[NM*DD + m*DD + d];
            }
            size_t o = (size_t)(n*KK + k)*DD + d;
            g_hsh[o]  = __float2half_rn(fasttanh(ah));
            g_tshi[o] = __float2half_rn(fasttanh(at2));
        }
    }
}

// ================= HMMA bilinear core, single pass =================
#define SH_PITCH 132
#define SMEM_DYN (128*SH_PITCH*4 + 128*2*4 + 1024)

__global__ __launch_bounds__(256) void k_bilinear_mma()
{
    extern __shared__ char dsm[];
    char* smem = (char*)((((uintptr_t)dsm) + 1023) & ~(uintptr_t)1023);
    uint32_t sbase = (uint32_t)__cvta_generic_to_shared(smem);

    const int k  = blockIdx.y;
    const int nt = blockIdx.x & 3;
    const int dt = blockIdx.x >> 2;
    const int n0 = nt * 128, d0 = dt * 128;
    const int tid = threadIdx.x;
    const int lane = tid & 31, wid = tid >> 5;
    const int wm = (wid & 3) * 32;
    const int wn = (wid >> 2) * 64;

    const __half* Abase = g_tshi + ((size_t)n0 * KK + k) * DD;
    const __half* Bbase = g_Bhi + ((size_t)k * DD + d0) * DD;

    float acc[2][8][4];
    #pragma unroll
    for (int mi = 0; mi < 2; mi++)
        #pragma unroll
        for (int ni = 0; ni < 8; ni++)
            #pragma unroll
            for (int j = 0; j < 4; j++) acc[mi][ni][j] = 0.f;

    auto fill = [&](int it, int buf) {
        int k0 = it * 64;
        uint32_t abase = sbase + buf*2*TILE_BYTES;
        uint32_t bbase = abase + TILE_BYTES;
        #pragma unroll
        for (int j = 0; j < 8; j++) {
            int c = tid + j*256;
            if (c < 1024) {
                int r = c >> 3, q = c & 7;
                cp16(abase + SW128(r*128 + q*16), Abase + (size_t)r*(KK*DD) + k0 + q*8);
            } else {
                int c2 = c - 1024;
                int r = c2 >> 3, q = c2 & 7;
                cp16(bbase + SW128(r*128 + q*16), Bbase + (size_t)r*DD + k0 + q*8);
            }
        }
    };

    fill(0, 0);
    asm volatile("cp.async.commit_group;");

    for (int i = 0; i < 12; i++) {
        if (i + 1 < 12) {
            fill(i + 1, (i + 1) & 1);
            asm volatile("cp.async.commit_group;");
            asm volatile("cp.async.wait_group 1;");
        } else {
            asm volatile("cp.async.wait_group 0;");
        }
        __syncthreads();

        uint32_t abase = sbase + (i & 1)*2*TILE_BYTES;
        uint32_t bbase = abase + TILE_BYTES;
        #pragma unroll
        for (int ks = 0; ks < 4; ks++) {
            uint32_t af[2][4];
            #pragma unroll
            for (int mi = 0; mi < 2; mi++) {
                int row = wm + mi*16 + ((lane >> 3) & 1)*8 + (lane & 7);
                int cb  = ks*32 + (lane >> 4)*16;
                ldm4(af[mi], abase + SW128(row*128 + cb));
            }
            uint32_t bf[8][2];
            #pragma unroll
            for (int q = 0; q < 4; q++) {
                uint32_t r[4];
                int nrow = wn + (2*q + (lane >> 4))*8 + (lane & 7);
                int cb   = ks*32 + ((lane >> 3) & 1)*16;
                ldm4(r, bbase + SW128(nrow*128 + cb));
                bf[2*q+0][0] = r[0]; bf[2*q+0][1] = r[1];
                bf[2*q+1][0] = r[2]; bf[2*q+1][1] = r[3];
            }
            #pragma unroll
            for (int mi = 0; mi < 2; mi++)
                #pragma unroll
                for (int ni = 0; ni < 8; ni++)
                    mma16816(acc[mi][ni], af[mi], bf[ni]);
        }
        __syncthreads();
    }

    // ---- epilogue: partial[n] = sum_d C[n][d]*hs[n][d] ----
    float* sH  = (float*)smem;
    float* red = (float*)(smem + 128*SH_PITCH*4);
    for (int idx = tid; idx < 128*16; idx += 256) {
        int r = idx >> 4, c8 = idx & 15;
        const __half2* hp = (const __half2*)(g_hsh + ((size_t)(n0 + r)*KK + k)*DD + d0 + c8*8);
        float* dst = &sH[r*SH_PITCH + c8*8];
        #pragma unroll
        for (int u = 0; u < 4; u++) {
            float2 f = __half22float2(hp[u]);
            dst[u*2+0] = f.x; dst[u*2+1] = f.y;
        }
    }
    __syncthreads();

    float p[2][2] = {{0.f, 0.f}, {0.f, 0.f}};
    #pragma unroll
    for (int mi = 0; mi < 2; mi++) {
        int r0 = wm + mi*16 + (lane >> 2);
        #pragma unroll
        for (int ni = 0; ni < 8; ni++) {
            int cb = wn + ni*8 + (lane & 3)*2;
            p[mi][0] += acc[mi][ni][0]*sH[r0*SH_PITCH + cb]
                      + acc[mi][ni][1]*sH[r0*SH_PITCH + cb + 1];
            p[mi][1] += acc[mi][ni][2]*sH[(r0+8)*SH_PITCH + cb]
                      + acc[mi][ni][3]*sH[(r0+8)*SH_PITCH + cb + 1];
        }
    }
    #pragma unroll
    for (int mi = 0; mi < 2; mi++)
        #pragma unroll
        for (int h = 0; h < 2; h++) {
            p[mi][h] += __shfl_xor_sync(0xffffffffu, p[mi][h], 1);
            p[mi][h] += __shfl_xor_sync(0xffffffffu, p[mi][h], 2);
        }
    if ((lane & 3) == 0) {
        int nw = wid >> 2;
        int rr = lane >> 2;
        #pragma unroll
        for (int mi = 0; mi < 2; mi++) {
            red[(wm + mi*16 + rr)*2 + nw]     = p[mi][0];
            red[(wm + mi*16 + rr + 8)*2 + nw] = p[mi][1];
        }
    }
    __syncthreads();
    if (tid < 128)
        g_part[((size_t)dt*NP + n0 + tid)*KK + k] = red[tid*2] + red[tid*2+1];
}

// ---------------- K13: finalize ----------------
__global__ void k_final(const float* __restrict__ bilb, float* __restrict__ out)
{
    int idx = blockIdx.x*256 + threadIdx.x;
    if (idx >= NP*KK) return;
    int k = idx % KK;
    float s = bilb[k];
    #pragma unroll
    for (int t = 0; t < 6; t++) s += g_part[t*(NP*KK) + idx];
    out[idx] = s;
}

// ---------------- launch ----------------
extern "C" void kernel_launch(void* const* d_in, const int* in_sizes, int n_in,
                              void* d_out, int out_size)
{
    const float* seq      = (const float*)d_in[0];
    const float* att      = (const float*)d_in[1];
    const float* mask     = (const float*)d_in[2];
    const int*   mpos     = (const int*)  d_in[3];
    const int*   pairs    = (const int*)  d_in[4];
    const float* Wattn    = (const float*)d_in[5];
    const float* battn    = (const float*)d_in[6];
    const float* attn_net = (const float*)d_in[7];
    const float* Wlin     = (const float*)d_in[8];
    const float* blin     = (const float*)d_in[9];
    const float* Wseg     = (const float*)d_in[10];
    const float* bseg     = (const float*)d_in[11];
    const float* Whead    = (const float*)d_in[12];
    const float* bhead    = (const float*)d_in[13];
    const float* Wtail    = (const float*)d_in[14];
    const float* btail    = (const float*)d_in[15];
    const float* bil      = (const float*)d_in[16];
    const float* bilb     = (const float*)d_in[17];
    float* out = (float*)d_out;

    float *emb, *t1, *Th, *Tt, *Rh, *Rt;
    __half *embh, *htssh, *Whh, *Wth, *Whb, *Wtb;
    cudaGetSymbolAddress((void**)&emb,   g_emb);
    cudaGetSymbolAddress((void**)&t1,    g_t1);
    cudaGetSymbolAddress((void**)&Th,    g_Th);
    cudaGetSymbolAddress((void**)&Tt,    g_Tt);
    cudaGetSymbolAddress((void**)&Rh,    g_Rh);
    cudaGetSymbolAddress((void**)&Rt,    g_Rt);
    cudaGetSymbolAddress((void**)&embh,  g_embh);
    cudaGetSymbolAddress((void**)&htssh, g_htssh);
    cudaGetSymbolAddress((void**)&Whh,   g_Whh);
    cudaGetSymbolAddress((void**)&Wth,   g_Wth);
    cudaGetSymbolAddress((void**)&Whb,   g_Whb);
    cudaGetSymbolAddress((void**)&Wtb,   g_Wtb);

    cudaFuncSetAttribute(k_bilinear_mma, cudaFuncAttributeMaxDynamicSharedMemorySize, SMEM_DYN);
    cudaFuncSetAttribute(k_hgemm, cudaFuncAttributeMaxDynamicSharedMemorySize, HG_SMEM);

    // 0. weight fp16 transpose/convert (independent)
    k_wconv<<<(WC_TOTAL + 255)/256, 256>>>(Whead, Wtail);
    // 1. fused prep
    k_prep<<<EMB_BLKS + AS_BLKS + ANTR_BLKS + S3_BLKS + PAD_BLKS, 256>>>(
        seq, att, mask, mpos, attn_net, Wlin);
    // 2. t1 = tanh(emb @ Wattn + battn)  (fp32 for softmax accuracy)
    sgemm_ca<<<dim3(RR/64, MEMB/64), 256>>>(emb, DD, Wattn, RR, battn, t1, RR, DD, 1);
    // 3. fused scores + softmax
    k_scsm<<<BBS*NE, 128>>>(mask);
    // 4/5. T_h / T_t via fp16 HMMA (M=1344 padded to 1408)
    k_hgemm<<<dim3(DD/128, MEMBP/128, 2), 256, HG_SMEM>>>(
        embh, DD, Whh, Wth, DD, nullptr, nullptr, Th, Tt, MEMB, DD, DD);
    // 6/7. ht -> x  (idle blocks convert bilinear weights to fp16)
    k_htx<<<dim3(NE*NE, BBS), 256>>>(blin, bil);
    // 8. conv + relu at pairs (fp16 out)
    k_htss<<<NP, 256>>>(pairs, Wseg, bseg);
    // 9. Rh / Rt via fp16 HMMA (M=512, K=256)
    k_hgemm<<<dim3(DD/128, NP/128, 2), 256, HG_SMEM>>>(
        htssh, FF, Whb, Wtb, FF, bhead, btail, Rh, Rt, NP, DD, FF);
    // 10. hs,ts fp16
    k_hsts<<<NP, 256>>>(pairs);
    // 11. HMMA bilinear
    k_bilinear_mma<<<dim3(24, 97), 256, SMEM_DYN>>>();
    // 12. finalize
    k_final<<<(NP*KK + 255)/256, 256>>>(bilb, out);
}

// round 14
// speedup vs baseline: 1.5874x; 1.0502x over previous
#include <cuda_runtime.h>
#include <cuda_fp16.h>
#include <math.h>
#include <stdint.h>

#define NE 42
#define NM 8
#define LL 1024
#define DD 768
#define HH 12
#define KK 97
#define FF 256
#define RR 256
#define BBS 4
#define NP 512   /* bs * P */
#define MEMB (BBS*NE*NM)     /* 1344 */
#define MEMBP 1408           /* padded to 128 multiple */

// ---------------- scratch (device globals; no allocs) ----------------
__device__ float g_emb [BBS*NE*NM*DD];
__device__ float g_as  [BBS*NE*LL*HH];     // TRANSPOSED: [be][l][h]
__device__ float g_t1  [BBS*NE*NM*RR];
__device__ float g_anT [RR*128];
__device__ float g_w   [BBS*NE*KK*NM];
__device__ float g_Th  [BBS*NE*NM*DD];
__device__ float g_Tt  [BBS*NE*NM*DD];
__device__ float g_S3  [BBS*LL*3];
__device__ float g_x   [BBS*NE*NE*3];
__device__ float g_Rh  [NP*DD];
__device__ float g_Rt  [NP*DD];
__device__ __align__(16) __half g_embh [MEMBP*DD];
__device__ __align__(16) __half g_htssh[NP*FF];
__device__ __align__(16) __half g_Whh[DD*DD];
__device__ __align__(16) __half g_Wth[DD*DD];
__device__ __align__(16) __half g_Whb[DD*FF];
__device__ __align__(16) __half g_Wtb[DD*FF];
__device__ __align__(16) __half g_hsh [NP*KK*DD];
__device__ __align__(16) __half g_tshi[NP*KK*DD];
__device__ __align__(16) __half g_Bhi [KK*DD*DD];
__device__ float g_part[6*NP*KK];

__device__ __forceinline__ float fasttanh(float x)
{
    float y;
    asm("tanh.approx.f32 %0, %1;" : "=f"(y) : "f"(x));
    return y;
}

__device__ __forceinline__ void cp16(uint32_t dst, const void* src)
{
    asm volatile("cp.async.cg.shared.global [%0], [%1], 16;" :: "r"(dst), "l"(src));
}

// ---------------- K0: weight fp16 transpose/convert ----------------
#define WTOP (DD*DD)
#define WBOT (DD*FF)
#define WC_TOTAL (2*WTOP + 2*WBOT)

__global__ void k_wconv(const float* __restrict__ Whead, const float* __restrict__ Wtail)
{
    int idx = blockIdx.x*256 + threadIdx.x;
    if (idx < WTOP) {
        int n = idx / DD, k = idx % DD;
        g_Whh[idx] = __float2half_rn(Whead[(size_t)k*DD + n]);
    } else if (idx < 2*WTOP) {
        int q = idx - WTOP;
        int n = q / DD, k = q % DD;
        g_Wth[q] = __float2half_rn(Wtail[(size_t)k*DD + n]);
    } else if (idx < 2*WTOP + WBOT) {
        int q = idx - 2*WTOP;
        int n = q / FF, k = q % FF;
        g_Whb[q] = __float2half_rn(Whead[(size_t)(DD + k)*DD + n]);
    } else if (idx < WC_TOTAL) {
        int q = idx - 2*WTOP - WBOT;
        int n = q / FF, k = q % FF;
        g_Wtb[q] = __float2half_rn(Wtail[(size_t)(DD + k)*DD + n]);
    }
}

// ---------------- K1: fused prep ----------------
#define EMB_BLKS  (BBS*NE)
#define AS_BLKS   (BBS*NE*HH)
#define ANTR_BLKS 128
#define S3_BLKS   ((BBS*LL)/2)
#define PAD_BLKS  1

__global__ __launch_bounds__(256) void k_prep(const float* __restrict__ seq,
                                              const float* __restrict__ att,
                                              const float* __restrict__ mask,
                                              const int* __restrict__ mpos,
                                              const float* __restrict__ attn_net,
                                              const float* __restrict__ Wlin)
{
    int bid = blockIdx.x;
    int tid = threadIdx.x;
    if (bid < EMB_BLKS) {
        int be = bid;
        int b  = be / NE;
        __shared__ int   spos[NM];
        __shared__ float smk [NM];
        if (tid < NM) {
            int p = mpos[be*NM + tid] + 1;
            p = max(0, min(p, LL-1));
            spos[tid] = p;
            smk[tid]  = mask[be*NM + tid];
        }
        __syncthreads();
        for (int idx = tid; idx < NM*DD; idx += 256) {
            int m = idx / DD, d = idx - m*DD;
            float v = seq[(b*LL + spos[m])*DD + d] * smk[m];
            g_emb [be*NM*DD + idx] = v;
            g_embh[(size_t)be*NM*DD + idx] = __float2half_rn(v);
        }
    } else if (bid < EMB_BLKS + AS_BLKS) {
        int q = bid - EMB_BLKS;
        int be = q / HH, h = q % HH;
        int b  = be / NE;
        __shared__ int   spos[NM];
        __shared__ float smk [NM];
        __shared__ float sinv;
        if (tid < NM) {
            int p = mpos[be*NM + tid] + 1;
            p = max(0, min(p, LL-1));
            spos[tid] = p;
            smk[tid]  = mask[be*NM + tid];
        }
        __syncthreads();
        if (tid == 0) {
            float c = 0.f;
            #pragma unroll
            for (int m = 0; m < NM; m++) c += smk[m];
            sinv = 1.0f / fmaxf(c, 1.0f);
        }
        __syncthreads();
        for (int l = tid; l < LL; l += 256) {
            float acc = 0.f;
            #pragma unroll
            for (int m = 0; m < NM; m++)
                acc += att[((b*HH + h)*LL + spos[m])*LL + l] * smk[m];
            g_as[((size_t)be*LL + l)*HH + h] = acc * sinv;
        }
    } else if (bid < EMB_BLKS + AS_BLKS + ANTR_BLKS) {
        int idx = (bid - EMB_BLKS - AS_BLKS)*256 + tid;
        int j = idx >> 7, k = idx & 127;
        g_anT[idx] = (k < KK) ? attn_net[k*RR + j] : 0.f;
    } else if (bid < EMB_BLKS + AS_BLKS + ANTR_BLKS + S3_BLKS) {
        int rp = bid - EMB_BLKS - AS_BLKS - ANTR_BLKS;
        int half = tid >> 7;
        int t2 = tid & 127;
        int row = rp*2 + half;
        const float* s = seq + (size_t)row*DD;
        float a0 = 0.f, a1 = 0.f, a2 = 0.f;
        for (int j = t2; j < DD; j += 128) {
            float v = s[j];
            a0 += v*Wlin[j*3+0]; a1 += v*Wlin[j*3+1]; a2 += v*Wlin[j*3+2];
        }
        __shared__ float red[2][3][128];
        red[half][0][t2] = a0; red[half][1][t2] = a1; red[half][2][t2] = a2;
        __syncthreads();
        for (int s2 = 64; s2 > 0; s2 >>= 1) {
            if (t2 < s2) {
                red[half][0][t2] += red[half][0][t2+s2];
                red[half][1][t2] += red[half][1][t2+s2];
                red[half][2][t2] += red[half][2][t2+s2];
            }
            __syncthreads();
        }
        if (t2 < 3) g_S3[row*3 + t2] = red[half][t2][0];
    } else {
        __half z = __float2half_rn(0.f);
        for (int idx = tid; idx < (MEMBP - MEMB)*DD; idx += 256)
            g_embh[(size_t)MEMB*DD + idx] = z;
    }
}

// ---------------- cp.async double-buffered SGEMM (64x64x32) — t1 only ----------------
__global__ __launch_bounds__(256) void sgemm_ca(const float* __restrict__ A, int lda,
                                                const float* __restrict__ B, int ldb,
                                                const float* __restrict__ bias,
                                                float* __restrict__ C, int ldc,
                                                int Kd, int act)
{
    __shared__ float As[2][64][32];
    __shared__ float Bs[2][32][68];
    int m0 = blockIdx.y * 64, n0 = blockIdx.x * 64;
    int tid = threadIdx.x;
    int ty = tid >> 4, tx = tid & 15;
    uint32_t sA = (uint32_t)__cvta_generic_to_shared(&As[0][0][0]);
    uint32_t sB = (uint32_t)__cvta_generic_to_shared(&Bs[0][0][0]);
    float acc[4][4];
    #pragma unroll
    for (int i = 0; i < 4; i++)
        #pragma unroll
        for (int j = 0; j < 4; j++) acc[i][j] = 0.f;

    int nstage = Kd >> 5;
    auto fill = [&](int s, int k0) {
        #pragma unroll
        for (int j = 0; j < 2; j++) {
            int c = tid + j*256;
            int r = c >> 3, q = c & 7;
            cp16(sA + (uint32_t)(s*64*32 + r*32 + q*4)*4,
                 A + (size_t)(m0 + r)*lda + k0 + q*4);
            int rb = c >> 4, qb = c & 15;
            cp16(sB + (uint32_t)(s*32*68 + rb*68 + qb*4)*4,
                 B + (size_t)(k0 + rb)*ldb + n0 + qb*4);
        }
        asm volatile("cp.async.commit_group;");
    };

    fill(0, 0);
    for (int s = 0; s < nstage; s++) {
        if (s + 1 < nstage) {
            fill((s + 1) & 1, (s + 1) << 5);
            asm volatile("cp.async.wait_group 1;");
        } else {
            asm volatile("cp.async.wait_group 0;");
        }
        __syncthreads();
        int bs = s & 1;
        #pragma unroll
        for (int k4 = 0; k4 < 8; k4++) {
            float4 a4[4];
            #pragma unroll
            for (int i = 0; i < 4; i++)
                a4[i] = *(const float4*)&As[bs][ty*4 + i][k4*4];
            #pragma unroll
            for (int kk = 0; kk < 4; kk++) {
                float4 b4 = *(const float4*)&Bs[bs][k4*4 + kk][tx*4];
                float a0 = (&a4[0].x)[kk], a1 = (&a4[1].x)[kk],
                      a2 = (&a4[2].x)[kk], a3 = (&a4[3].x)[kk];
                acc[0][0] += a0*b4.x; acc[0][1] += a0*b4.y; acc[0][2] += a0*b4.z; acc[0][3] += a0*b4.w;
                acc[1][0] += a1*b4.x; acc[1][1] += a1*b4.y; acc[1][2] += a1*b4.z; acc[1][3] += a1*b4.w;
                acc[2][0] += a2*b4.x; acc[2][1] += a2*b4.y; acc[2][2] += a2*b4.z; acc[2][3] += a2*b4.w;
                acc[3][0] += a3*b4.x; acc[3][1] += a3*b4.y; acc[3][2] += a3*b4.z; acc[3][3] += a3*b4.w;
            }
        }
        __syncthreads();
    }
    #pragma unroll
    for (int i = 0; i < 4; i++) {
        int row = m0 + ty*4 + i;
        #pragma unroll
        for (int j = 0; j < 4; j++) {
            int col = n0 + tx*4 + j;
            float v = acc[i][j];
            if (bias) v += bias[col];
            if (act)  v = fasttanh(v);
            C[(size_t)row*ldc + col] = v;
        }
    }
}

// ---------------- fused scores + softmax, 512 threads, 4-way j-split ----------------
__global__ __launch_bounds__(512) void k_scsm(const float* __restrict__ mask)
{
    int be = blockIdx.x;
    int tid = threadIdx.x;
    int qq = tid >> 7;           // j-quarter 0..3
    int kx = tid & 127;          // label
    __shared__ float st[NM*RR];          // t1 [m][j]
    __shared__ float sp[4][128*NM];      // partials
    for (int i = tid; i < NM*RR/4; i += 512)
        *(float4*)&st[i*4] = *(const float4*)&g_t1[(size_t)be*NM*RR + i*4];
    __syncthreads();

    float sc[NM];
    #pragma unroll
    for (int m = 0; m < NM; m++) sc[m] = 0.f;
    int j0 = qq*64;
    for (int j = j0; j < j0 + 64; j++) {
        float a = g_anT[j*128 + kx];
        #pragma unroll
        for (int m = 0; m < NM; m++) sc[m] += st[m*RR + j] * a;
    }
    #pragma unroll
    for (int m = 0; m < NM; m++) sp[qq][kx*NM + m] = sc[m];
    __syncthreads();

    if (tid < KK) {
        float s2[NM];
        #pragma unroll
        for (int m = 0; m < NM; m++)
            s2[m] = ((sp[0][tid*NM + m] + sp[1][tid*NM + m])
                   + (sp[2][tid*NM + m] + sp[3][tid*NM + m]))
                  + (1.0f - mask[be*NM + m]) * (-1e6f);
        float mx = s2[0];
        #pragma unroll
        for (int m = 1; m < NM; m++) mx = fmaxf(mx, s2[m]);
        float ssum = 0.f;
        #pragma unroll
        for (int m = 0; m < NM; m++) { s2[m] = expf(s2[m] - mx); ssum += s2[m]; }
        float inv = 1.0f / ssum;
        #pragma unroll
        for (int m = 0; m < NM; m++) g_w[(be*KK + tid)*NM + m] = s2[m]*inv;
    }
}

// ================= shared HMMA helpers =================
#define SW128(o) ((o) ^ (((o) >> 3) & 0x70))
#define TILE_BYTES 16384

__device__ __forceinline__ void ldm4(uint32_t* r, uint32_t addr)
{
    asm volatile("ldmatrix.sync.aligned.m8n8.x4.shared.b16 {%0,%1,%2,%3}, [%4];"
                 : "=r"(r[0]), "=r"(r[1]), "=r"(r[2]), "=r"(r[3]) : "r"(addr));
}
__device__ __forceinline__ void mma16816(float* c, const uint32_t* a, const uint32_t* b)
{
    asm volatile("mma.sync.aligned.m16n8k16.row.col.f32.f16.f16.f32 "
                 "{%0,%1,%2,%3}, {%4,%5,%6,%7}, {%8,%9}, {%0,%1,%2,%3};"
                 : "+f"(c[0]), "+f"(c[1]), "+f"(c[2]), "+f"(c[3])
                 : "r"(a[0]), "r"(a[1]), "r"(a[2]), "r"(a[3]), "r"(b[0]), "r"(b[1]));
}

// ---------------- generic NT fp16 HMMA GEMM, fp32 out, dual pair via z ----------------
#define HG_SMEM (2*2*TILE_BYTES + 1024)
__global__ __launch_bounds__(256) void k_hgemm(const __half* __restrict__ A, int lda,
                                               const __half* __restrict__ B0T,
                                               const __half* __restrict__ B1T, int ldb,
                                               const float* __restrict__ bias0,
                                               const float* __restrict__ bias1,
                                               float* __restrict__ C0,
                                               float* __restrict__ C1,
                                               int M, int ldc, int Kd)
{
    extern __shared__ char dsm[];
    char* smem = (char*)((((uintptr_t)dsm) + 1023) & ~(uintptr_t)1023);
    uint32_t sbase = (uint32_t)__cvta_generic_to_shared(smem);

    const __half* Bt  = blockIdx.z ? B1T : B0T;
    const float* bias = blockIdx.z ? bias1 : bias0;
    float* C          = blockIdx.z ? C1 : C0;
    const int n0 = blockIdx.x * 128;
    const int m0 = blockIdx.y * 128;
    const int tid = threadIdx.x;
    const int lane = tid & 31, wid = tid >> 5;
    const int wm = (wid & 3) * 32;
    const int wn = (wid >> 2) * 64;

    const __half* Abase = A + (size_t)m0*lda;
    const __half* Bbase = Bt + (size_t)n0*ldb;

    float acc[2][8][4];
    #pragma unroll
    for (int mi = 0; mi < 2; mi++)
        #pragma unroll
        for (int ni = 0; ni < 8; ni++)
            #pragma unroll
            for (int j = 0; j < 4; j++) acc[mi][ni][j] = 0.f;

    auto fill = [&](int it, int buf) {
        int k0 = it * 64;
        uint32_t abase = sbase + buf*2*TILE_BYTES;
        uint32_t bbase = abase + TILE_BYTES;
        #pragma unroll
        for (int j = 0; j < 8; j++) {
            int c = tid + j*256;
            if (c < 1024) {
                int r = c >> 3, q = c & 7;
                cp16(abase + SW128(r*128 + q*16), Abase + (size_t)r*lda + k0 + q*8);
            } else {
                int c2 = c - 1024;
                int r = c2 >> 3, q = c2 & 7;
                cp16(bbase + SW128(r*128 + q*16), Bbase + (size_t)r*ldb + k0 + q*8);
            }
        }
    };

    int nstage = Kd >> 6;
    fill(0, 0);
    asm volatile("cp.async.commit_group;");

    for (int i = 0; i < nstage; i++) {
        if (i + 1 < nstage) {
            fill(i + 1, (i + 1) & 1);
            asm volatile("cp.async.commit_group;");
            asm volatile("cp.async.wait_group 1;");
        } else {
            asm volatile("cp.async.wait_group 0;");
        }
        __syncthreads();

        uint32_t abase = sbase + (i & 1)*2*TILE_BYTES;
        uint32_t bbase = abase + TILE_BYTES;
        #pragma unroll
        for (int ks = 0; ks < 4; ks++) {
            uint32_t af[2][4];
            #pragma unroll
            for (int mi = 0; mi < 2; mi++) {
                int row = wm + mi*16 + ((lane >> 3) & 1)*8 + (lane & 7);
                int cb  = ks*32 + (lane >> 4)*16;
                ldm4(af[mi], abase + SW128(row*128 + cb));
            }
            uint32_t bf[8][2];
            #pragma unroll
            for (int q = 0; q < 4; q++) {
                uint32_t r[4];
                int nrow = wn + (2*q + (lane >> 4))*8 + (lane & 7);
                int cb   = ks*32 + ((lane >> 3) & 1)*16;
                ldm4(r, bbase + SW128(nrow*128 + cb));
                bf[2*q+0][0] = r[0]; bf[2*q+0][1] = r[1];
                bf[2*q+1][0] = r[2]; bf[2*q+1][1] = r[3];
            }
            #pragma unroll
            for (int mi = 0; mi < 2; mi++)
                #pragma unroll
                for (int ni = 0; ni < 8; ni++)
                    mma16816(acc[mi][ni], af[mi], bf[ni]);
        }
        __syncthreads();
    }

    #pragma unroll
    for (int mi = 0; mi < 2; mi++) {
        int r0 = m0 + wm + mi*16 + (lane >> 2);
        #pragma unroll
        for (int ni = 0; ni < 8; ni++) {
            int cb = n0 + wn + ni*8 + (lane & 3)*2;
            float b0 = bias ? bias[cb] : 0.f;
            float b1 = bias ? bias[cb+1] : 0.f;
            if (r0 < M) {
                float2 v = make_float2(acc[mi][ni][0] + b0, acc[mi][ni][1] + b1);
                *(float2*)&C[(size_t)r0*ldc + cb] = v;
            }
            if (r0 + 8 < M) {
                float2 v = make_float2(acc[mi][ni][2] + b0, acc[mi][ni][3] + b1);
                *(float2*)&C[(size_t)(r0+8)*ldc + cb] = v;
            }
        }
    }
}

// ---------------- K7: ht + norm + x; idle blocks convert B->fp16 ----------------
#define BCONV_BLOCKS (861*BBS)
#define BCONV_N4     ((size_t)KK*DD*DD/4)
#define BCONV_CHUNK  ((BCONV_N4 + BCONV_BLOCKS - 1)/BCONV_BLOCKS)

__global__ __launch_bounds__(256) void k_htx(const float* __restrict__ blin,
                                             const float* __restrict__ bil)
{
    int b = blockIdx.y;
    int i = blockIdx.x / NE, j = blockIdx.x % NE;
    int tid = threadIdx.x;
    if (j < i) {
        size_t q = (size_t)b*861 + (size_t)i*(i-1)/2 + j;
        size_t beg = q*BCONV_CHUNK;
        size_t end = beg + BCONV_CHUNK;
        if (end > BCONV_N4) end = BCONV_N4;
        __half2* ph = (__half2*)g_Bhi;
        for (size_t i4 = beg + tid; i4 < end; i4 += 256) {
            float4 v = ((const float4*)bil)[i4];
            ph[i4*2+0] = __floats2half2_rn(v.x, v.y);
            ph[i4*2+1] = __floats2half2_rn(v.z, v.w);
        }
        return;
    }
    const float* ai = g_as + ((size_t)(b*NE + i))*LL*HH;
    const float* aj = g_as + ((size_t)(b*NE + j))*LL*HH;
    const float* s3 = g_S3 + b*LL*3;
    float sum = 0.f, x0 = 0.f, x1 = 0.f, x2 = 0.f;
    for (int l = tid; l < LL; l += 256) {
        float4 u0 = *(const float4*)&ai[l*HH + 0];
        float4 u1 = *(const float4*)&ai[l*HH + 4];
        float4 u2 = *(const float4*)&ai[l*HH + 8];
        float4 v0 = *(const float4*)&aj[l*HH + 0];
        float4 v1 = *(const float4*)&aj[l*HH + 4];
        float4 v2 = *(const float4*)&aj[l*HH + 8];
        float acc = u0.x*v0.x + u0.y*v0.y + u0.z*v0.z + u0.w*v0.w
                  + u1.x*v1.x + u1.y*v1.y + u1.z*v1.z + u1.w*v1.w
                  + u2.x*v2.x + u2.y*v2.y + u2.z*v2.z + u2.w*v2.w;
        acc *= (1.0f / HH);
        sum += acc;
        x0 += acc * s3[l*3+0];
        x1 += acc * s3[l*3+1];
        x2 += acc * s3[l*3+2];
    }
    __shared__ float red[4][256];
    red[0][tid] = sum; red[1][tid] = x0; red[2][tid] = x1; red[3][tid] = x2;
    __syncthreads();
    for (int s2 = 128; s2 > 0; s2 >>= 1) {
        if (tid < s2) {
            red[0][tid] += red[0][tid+s2];
            red[1][tid] += red[1][tid+s2];
            red[2][tid] += red[2][tid+s2];
            red[3][tid] += red[3][tid+s2];
        }
        __syncthreads();
    }
    if (tid == 0) {
        float inv = 1.0f / (red[0][0] + 1e-5f);
        float v0 = red[1][0]*inv + blin[0];
        float v1 = red[2][0]*inv + blin[1];
        float v2 = red[3][0]*inv + blin[2];
        float* xo = g_x + ((b*NE + i)*NE + j)*3;
        xo[0] = v0; xo[1] = v1; xo[2] = v2;
        float* xm = g_x + ((b*NE + j)*NE + i)*3;
        xm[0] = v0; xm[1] = v1; xm[2] = v2;
    }
}

// ---------------- K8: 3x3 conv + relu at pair positions (fp16 out) ----------------
__global__ void k_htss(const int* __restrict__ pairs, const float* __restrict__ Wseg,
                       const float* __restrict__ bseg)
{
    int n = blockIdx.x;
    int b = n >> 7;
    int tid = threadIdx.x;
    __shared__ int shi, sti;
    __shared__ float sx[27];
    if (tid == 0) { shi = pairs[n*2]; sti = pairs[n*2+1]; }
    __syncthreads();
    if (tid < 27) {
        int dy = tid / 9, dx = (tid / 3) % 3, c = tid % 3;
        int ii = shi + dy - 1, jj = sti + dx - 1;
        sx[tid] = (ii >= 0 && ii < NE && jj >= 0 && jj < NE)
                  ? g_x[((b*NE + ii)*NE + jj)*3 + c] : 0.f;
    }
    __syncthreads();
    float acc = bseg[tid];
    #pragma unroll
    for (int t = 0; t < 27; t++) acc += sx[t] * Wseg[t*FF + tid];
    g_htssh[n*FF + tid] = __float2half_rn(fmaxf(acc, 0.f));
}

// ---------------- K10: hs,ts -> fp16, k-range split over blockIdx.y ----------------
__global__ __launch_bounds__(256) void k_hsts(const int* __restrict__ pairs)
{
    int n = blockIdx.x;
    int b = n >> 7;
    int kh = blockIdx.y;               // 0 or 1
    int kbeg = kh ? 49 : 0;
    int kend = kh ? KK : 49;
    int tid = threadIdx.x;
    __shared__ float sT[2*NM*DD];
    int hi = pairs[n*2], ti = pairs[n*2+1];
    const float* Th = g_Th + (b*NE + hi)*NM*DD;
    const float* Tt = g_Tt + (b*NE + ti)*NM*DD;
    for (int idx = tid; idx < NM*DD; idx += 256) {
        sT[idx]         = Th[idx];
        sT[NM*DD + idx] = Tt[idx];
    }
    float rh[3], rt[3];
    #pragma unroll
    for (int i2 = 0; i2 < 3; i2++) {
        rh[i2] = g_Rh[n*DD + tid + i2*256];
        rt[i2] = g_Rt[n*DD + tid + i2*256];
    }
    __syncthreads();
    const float4* wh4 = (const float4*)(g_w + (size_t)(b*NE + hi)*KK*NM);
    const float4* wt4 = (const float4*)(g_w + (size_t)(b*NE + ti)*KK*NM);
    for (int k = kbeg; k < kend; k++) {
        float4 wh0 = __ldg(&wh4[k*2]),   wh1 = __ldg(&wh4[k*2+1]);
        float4 wt0 = __ldg(&wt4[k*2]),   wt1 = __ldg(&wt4[k*2+1]);
        float whr[NM] = {wh0.x, wh0.y, wh0.z, wh0.w, wh1.x, wh1.y, wh1.z, wh1.w};
        float wtr[NM] = {wt0.x, wt0.y, wt0.z, wt0.w, wt1.x, wt1.y, wt1.z, wt1.w};
        #pragma unroll
        for (int i2 = 0; i2 < 3; i2++) {
            int d = tid + i2*256;
            float ah = rh[i2], at2 = rt[i2];
            #pragma unroll
            for (int m = 0; m < NM; m++) {
                ah  += whr[m] * sT[m*DD + d];
                at2 += wtr[m] * sT[NM*DD + m*DD + d];
            }
            size_t o = (size_t)(n*KK + k)*DD + d;
            g_hsh[o]  = __float2half_rn(fasttanh(ah));
            g_tshi[o] = __float2half_rn(fasttanh(at2));
        }
    }
}

// ================= HMMA bilinear core, single pass =================
#define SH_PITCH 132
#define SMEM_DYN (128*SH_PITCH*4 + 128*2*4 + 1024)

__global__ __launch_bounds__(256) void k_bilinear_mma()
{
    extern __shared__ char dsm[];
    char* smem = (char*)((((uintptr_t)dsm) + 1023) & ~(uintptr_t)1023);
    uint32_t sbase = (uint32_t)__cvta_generic_to_shared(smem);

    const int k  = blockIdx.y;
    const int nt = blockIdx.x & 3;
    const int dt = blockIdx.x >> 2;
    const int n0 = nt * 128, d0 = dt * 128;
    const int tid = threadIdx.x;
    const int lane = tid & 31, wid = tid >> 5;
    const int wm = (wid & 3) * 32;
    const int wn = (wid >> 2) * 64;

    const __half* Abase = g_tshi + ((size_t)n0 * KK + k) * DD;
    const __half* Bbase = g_Bhi + ((size_t)k * DD + d0) * DD;

    float acc[2][8][4];
    #pragma unroll
    for (int mi = 0; mi < 2; mi++)
        #pragma unroll
        for (int ni = 0; ni < 8; ni++)
            #pragma unroll
            for (int j = 0; j < 4; j++) acc[mi][ni][j] = 0.f;

    auto fill = [&](int it, int buf) {
        int k0 = it * 64;
        uint32_t abase = sbase + buf*2*TILE_BYTES;
        uint32_t bbase = abase + TILE_BYTES;
        #pragma unroll
        for (int j = 0; j < 8; j++) {
            int c = tid + j*256;
            if (c < 1024) {
                int r = c >> 3, q = c & 7;
                cp16(abase + SW128(r*128 + q*16), Abase + (size_t)r*(KK*DD) + k0 + q*8);
            } else {
                int c2 = c - 1024;
                int r = c2 >> 3, q = c2 & 7;
                cp16(bbase + SW128(r*128 + q*16), Bbase + (size_t)r*DD + k0 + q*8);
            }
        }
    };

    fill(0, 0);
    asm volatile("cp.async.commit_group;");

    for (int i = 0; i < 12; i++) {
        if (i + 1 < 12) {
            fill(i + 1, (i + 1) & 1);
            asm volatile("cp.async.commit_group;");
            asm volatile("cp.async.wait_group 1;");
        } else {
            asm volatile("cp.async.wait_group 0;");
        }
        __syncthreads();

        uint32_t abase = sbase + (i & 1)*2*TILE_BYTES;
        uint32_t bbase = abase + TILE_BYTES;
        #pragma unroll
        for (int ks = 0; ks < 4; ks++) {
            uint32_t af[2][4];
            #pragma unroll
            for (int mi = 0; mi < 2; mi++) {
                int row = wm + mi*16 + ((lane >> 3) & 1)*8 + (lane & 7);
                int cb  = ks*32 + (lane >> 4)*16;
                ldm4(af[mi], abase + SW128(row*128 + cb));
            }
            uint32_t bf[8][2];
            #pragma unroll
            for (int q = 0; q < 4; q++) {
                uint32_t r[4];
                int nrow = wn + (2*q + (lane >> 4))*8 + (lane & 7);
                int cb   = ks*32 + ((lane >> 3) & 1)*16;
                ldm4(r, bbase + SW128(nrow*128 + cb));
                bf[2*q+0][0] = r[0]; bf[2*q+0][1] = r[1];
                bf[2*q+1][0] = r[2]; bf[2*q+1][1] = r[3];
            }
            #pragma unroll
            for (int mi = 0; mi < 2; mi++)
                #pragma unroll
                for (int ni = 0; ni < 8; ni++)
                    mma16816(acc[mi][ni], af[mi], bf[ni]);
        }
        __syncthreads();
    }

    float* sH  = (float*)smem;
    float* red = (float*)(smem + 128*SH_PITCH*4);
    for (int idx = tid; idx < 128*16; idx += 256) {
        int r = idx >> 4, c8 = idx & 15;
        const __half2* hp = (const __half2*)(g_hsh + ((size_t)(n0 + r)*KK + k)*DD + d0 + c8*8);
        float* dst = &sH[r*SH_PITCH + c8*8];
        #pragma unroll
        for (int u = 0; u < 4; u++) {
            float2 f = __half22float2(hp[u]);
            dst[u*2+0] = f.x; dst[u*2+1] = f.y;
        }
    }
    __syncthreads();

    float p[2][2] = {{0.f, 0.f}, {0.f, 0.f}};
    #pragma unroll
    for (int mi = 0; mi < 2; mi++) {
        int r0 = wm + mi*16 + (lane >> 2);
        #pragma unroll
        for (int ni = 0; ni < 8; ni++) {
            int cb = wn + ni*8 + (lane & 3)*2;
            p[mi][0] += acc[mi][ni][0]*sH[r0*SH_PITCH + cb]
                      + acc[mi][ni][1]*sH[r0*SH_PITCH + cb + 1];
            p[mi][1] += acc[mi][ni][2]*sH[(r0+8)*SH_PITCH + cb]
                      + acc[mi][ni][3]*sH[(r0+8)*SH_PITCH + cb + 1];
        }
    }
    #pragma unroll
    for (int mi = 0; mi < 2; mi++)
        #pragma unroll
        for (int h = 0; h < 2; h++) {
            p[mi][h] += __shfl_xor_sync(0xffffffffu, p[mi][h], 1);
            p[mi][h] += __shfl_xor_sync(0xffffffffu, p[mi][h], 2);
        }
    if ((lane & 3) == 0) {
        int nw = wid >> 2;
        int rr = lane >> 2;
        #pragma unroll
        for (int mi = 0; mi < 2; mi++) {
            red[(wm + mi*16 + rr)*2 + nw]     = p[mi][0];
            red[(wm + mi*16 + rr + 8)*2 + nw] = p[mi][1];
        }
    }
    __syncthreads();
    if (tid < 128)
        g_part[((size_t)dt*NP + n0 + tid)*KK + k] = red[tid*2] + red[tid*2+1];
}

// ---------------- K13: finalize ----------------
__global__ void k_final(const float* __restrict__ bilb, float* __restrict__ out)
{
    int idx = blockIdx.x*256 + threadIdx.x;
    if (idx >= NP*KK) return;
    int k = idx % KK;
    float s = bilb[k];
    #pragma unroll
    for (int t = 0; t < 6; t++) s += g_part[t*(NP*KK) + idx];
    out[idx] = s;
}

// ---------------- launch ----------------
extern "C" void kernel_launch(void* const* d_in, const int* in_sizes, int n_in,
                              void* d_out, int out_size)
{
    const float* seq      = (const float*)d_in[0];
    const float* att      = (const float*)d_in[1];
    const float* mask     = (const float*)d_in[2];
    const int*   mpos     = (const int*)  d_in[3];
    const int*   pairs    = (const int*)  d_in[4];
    const float* Wattn    = (const float*)d_in[5];
    const float* battn    = (const float*)d_in[6];
    const float* attn_net = (const float*)d_in[7];
    const float* Wlin     = (const float*)d_in[8];
    const float* blin     = (const float*)d_in[9];
    const float* Wseg     = (const float*)d_in[10];
    const float* bseg     = (const float*)d_in[11];
    const float* Whead    = (const float*)d_in[12];
    const float* bhead    = (const float*)d_in[13];
    const float* Wtail    = (const float*)d_in[14];
    const float* btail    = (const float*)d_in[15];
    const float* bil      = (const float*)d_in[16];
    const float* bilb     = (const float*)d_in[17];
    float* out = (float*)d_out;

    float *emb, *t1, *Th, *Tt, *Rh, *Rt;
    __half *embh, *htssh, *Whh, *Wth, *Whb, *Wtb;
    cudaGetSymbolAddress((void**)&emb,   g_emb);
    cudaGetSymbolAddress((void**)&t1,    g_t1);
    cudaGetSymbolAddress((void**)&Th,    g_Th);
    cudaGetSymbolAddress((void**)&Tt,    g_Tt);
    cudaGetSymbolAddress((void**)&Rh,    g_Rh);
    cudaGetSymbolAddress((void**)&Rt,    g_Rt);
    cudaGetSymbolAddress((void**)&embh,  g_embh);
    cudaGetSymbolAddress((void**)&htssh, g_htssh);
    cudaGetSymbolAddress((void**)&Whh,   g_Whh);
    cudaGetSymbolAddress((void**)&Wth,   g_Wth);
    cudaGetSymbolAddress((void**)&Whb,   g_Whb);
    cudaGetSymbolAddress((void**)&Wtb,   g_Wtb);

    cudaFuncSetAttribute(k_bilinear_mma, cudaFuncAttributeMaxDynamicSharedMemorySize, SMEM_DYN);
    cudaFuncSetAttribute(k_hgemm, cudaFuncAttributeMaxDynamicSharedMemorySize, HG_SMEM);

    // 0. weight fp16 transpose/convert (independent)
    k_wconv<<<(WC_TOTAL + 255)/256, 256>>>(Whead, Wtail);
    // 1. fused prep
    k_prep<<<EMB_BLKS + AS_BLKS + ANTR_BLKS + S3_BLKS + PAD_BLKS, 256>>>(
        seq, att, mask, mpos, attn_net, Wlin);
    // 2. t1 = tanh(emb @ Wattn + battn)
    sgemm_ca<<<dim3(RR/64, MEMB/64), 256>>>(emb, DD, Wattn, RR, battn, t1, RR, DD, 1);
    // 3. fused scores + softmax (512 thr, 4-way split)
    k_scsm<<<BBS*NE, 512>>>(mask);
    // 4/5. T_h / T_t via fp16 HMMA
    k_hgemm<<<dim3(DD/128, MEMBP/128, 2), 256, HG_SMEM>>>(
        embh, DD, Whh, Wth, DD, nullptr, nullptr, Th, Tt, MEMB, DD, DD);
    // 6/7. ht -> x  (idle blocks convert bilinear weights to fp16)
    k_htx<<<dim3(NE*NE, BBS), 256>>>(blin, bil);
    // 8. conv + relu at pairs (fp16 out)
    k_htss<<<NP, 256>>>(pairs, Wseg, bseg);
    // 9. Rh / Rt via fp16 HMMA
    k_hgemm<<<dim3(DD/128, NP/128, 2), 256, HG_SMEM>>>(
        htssh, FF, Whb, Wtb, FF, bhead, btail, Rh, Rt, NP, DD, FF);
    // 10. hs,ts fp16 (k-range split x2)
    k_hsts<<<dim3(NP, 2), 256>>>(pairs);
    // 11. HMMA bilinear
    k_bilinear_mma<<<dim3(24, 97), 256, SMEM_DYN>>>();
    // 12. finalize
    k_final<<<(NP*KK + 255)/256, 256>>>(bilb, out);
}

// round 17
// speedup vs baseline: 1.6354x; 1.0302x over previous
#include <cuda_runtime.h>
#include <cuda_fp16.h>
#include <math.h>
#include <stdint.h>

#define NE 42
#define NM 8
#define LL 1024
#define DD 768
#define HH 12
#define KK 97
#define FF 256
#define RR 256
#define BBS 4
#define NP 512
#define MEMB (BBS*NE*NM)     /* 1344 */
#define MEMBP 1408

// ---------------- scratch ----------------
__device__ __align__(16) float g_emb [BBS*NE*NM*DD];
__device__ __align__(16) float g_as  [BBS*NE*LL*HH];
__device__ __align__(16) float g_t1  [BBS*NE*NM*RR];
__device__ __align__(16) float g_anT [RR*128];
__device__ __align__(16) float g_w   [BBS*NE*KK*NM];
__device__ __align__(16) float g_Th  [BBS*NE*NM*DD];
__device__ __align__(16) float g_Tt  [BBS*NE*NM*DD];
__device__ __align__(16) float g_S3  [BBS*LL*3];
__device__ __align__(16) float g_x   [BBS*NE*NE*3];
__device__ __align__(16) float g_Rh  [NP*DD];
__device__ __align__(16) float g_Rt  [NP*DD];
__device__ __align__(16) __half g_embh [MEMBP*DD];
__device__ __align__(16) __half g_htssh[NP*FF];
__device__ __align__(16) __half g_Whh[DD*DD];
__device__ __align__(16) __half g_Wth[DD*DD];
__device__ __align__(16) __half g_Whb[DD*FF];
__device__ __align__(16) __half g_Wtb[DD*FF];
__device__ __align__(16) __half g_hsh [NP*KK*DD];
__device__ __align__(16) __half g_tshi[NP*KK*DD];
__device__ __align__(16) __half g_Bhi [KK*DD*DD];
__device__ __align__(16) float g_part[6*NP*KK];

__device__ __forceinline__ float fasttanh(float x)
{
    float y;
    asm("tanh.approx.f32 %0, %1;" : "=f"(y) : "f"(x));
    return y;
}
__device__ __forceinline__ void cp16(uint32_t dst, const void* src)
{
    asm volatile("cp.async.cg.shared.global [%0], [%1], 16;" :: "r"(dst), "l"(src));
}

// ---------------- K1: fused prep (+ weight fp16 convert) ----------------
#define EMB_BLKS  (BBS*NE)
#define AS_BLKS   (BBS*NE*HH)
#define ANTR_BLKS 128
#define S3_BLKS   ((BBS*LL)/2)
#define PAD_BLKS  1
#define WTOP (DD*DD)
#define WBOT (DD*FF)
#define WC_TOTAL (2*WTOP + 2*WBOT)
#define WC_BLKS (WC_TOTAL/256)
#define PREP_BLKS (EMB_BLKS + AS_BLKS + ANTR_BLKS + S3_BLKS + PAD_BLKS + WC_BLKS)

__global__ __launch_bounds__(256) void k_prep(const float* __restrict__ seq,
                                              const float* __restrict__ att,
                                              const float* __restrict__ mask,
                                              const int* __restrict__ mpos,
                                              const float* __restrict__ attn_net,
                                              const float* __restrict__ Wlin,
                                              const float* __restrict__ Whead,
                                              const float* __restrict__ Wtail)
{
    int bid = blockIdx.x;
    int tid = threadIdx.x;
    if (bid < EMB_BLKS) {
        int be = bid;
        int b  = be / NE;
        __shared__ int   spos[NM];
        __shared__ float smk [NM];
        if (tid < NM) {
            int p = mpos[be*NM + tid] + 1;
            p = max(0, min(p, LL-1));
            spos[tid] = p;
            smk[tid]  = mask[be*NM + tid];
        }
        __syncthreads();
        for (int idx = tid; idx < NM*DD; idx += 256) {
            int m = idx / DD, d = idx - m*DD;
            float v = seq[(b*LL + spos[m])*DD + d] * smk[m];
            g_emb [be*NM*DD + idx] = v;
            g_embh[(size_t)be*NM*DD + idx] = __float2half_rn(v);
        }
    } else if (bid < EMB_BLKS + AS_BLKS) {
        int q = bid - EMB_BLKS;
        int be = q / HH, h = q % HH;
        int b  = be / NE;
        __shared__ int   spos[NM];
        __shared__ float smk [NM];
        __shared__ float sinv;
        if (tid < NM) {
            int p = mpos[be*NM + tid] + 1;
            p = max(0, min(p, LL-1));
            spos[tid] = p;
            smk[tid]  = mask[be*NM + tid];
        }
        __syncthreads();
        if (tid == 0) {
            float c = 0.f;
            #pragma unroll
            for (int m = 0; m < NM; m++) c += smk[m];
            sinv = 1.0f / fmaxf(c, 1.0f);
        }
        __syncthreads();
        for (int l = tid; l < LL; l += 256) {
            float acc = 0.f;
            #pragma unroll
            for (int m = 0; m < NM; m++)
                acc += att[((b*HH + h)*LL + spos[m])*LL + l] * smk[m];
            g_as[((size_t)be*LL + l)*HH + h] = acc * sinv;
        }
    } else if (bid < EMB_BLKS + AS_BLKS + ANTR_BLKS) {
        int idx = (bid - EMB_BLKS - AS_BLKS)*256 + tid;
        int j = idx >> 7, k = idx & 127;
        g_anT[idx] = (k < KK) ? attn_net[k*RR + j] : 0.f;
    } else if (bid < EMB_BLKS + AS_BLKS + ANTR_BLKS + S3_BLKS) {
        int rp = bid - EMB_BLKS - AS_BLKS - ANTR_BLKS;
        int half = tid >> 7;
        int t2 = tid & 127;
        int row = rp*2 + half;
        const float* s = seq + (size_t)row*DD;
        float a0 = 0.f, a1 = 0.f, a2 = 0.f;
        for (int j = t2; j < DD; j += 128) {
            float v = s[j];
            a0 += v*Wlin[j*3+0]; a1 += v*Wlin[j*3+1]; a2 += v*Wlin[j*3+2];
        }
        __shared__ __align__(16) float red[2][3][128];
        red[half][0][t2] = a0; red[half][1][t2] = a1; red[half][2][t2] = a2;
        __syncthreads();
        for (int s2 = 64; s2 > 0; s2 >>= 1) {
            if (t2 < s2) {
                red[half][0][t2] += red[half][0][t2+s2];
                red[half][1][t2] += red[half][1][t2+s2];
                red[half][2][t2] += red[half][2][t2+s2];
            }
            __syncthreads();
        }
        if (t2 < 3) g_S3[row*3 + t2] = red[half][t2][0];
    } else if (bid < EMB_BLKS + AS_BLKS + ANTR_BLKS + S3_BLKS + PAD_BLKS) {
        __half z = __float2half_rn(0.f);
        for (int idx = tid; idx < (MEMBP - MEMB)*DD; idx += 256)
            g_embh[(size_t)MEMB*DD + idx] = z;
    } else {
        int idx = (bid - EMB_BLKS - AS_BLKS - ANTR_BLKS - S3_BLKS - PAD_BLKS)*256 + tid;
        if (idx < WTOP) {
            int n = idx / DD, k = idx % DD;
            g_Whh[idx] = __float2half_rn(Whead[(size_t)k*DD + n]);
        } else if (idx < 2*WTOP) {
            int q = idx - WTOP;
            int n = q / DD, k = q % DD;
            g_Wth[q] = __float2half_rn(Wtail[(size_t)k*DD + n]);
        } else if (idx < 2*WTOP + WBOT) {
            int q = idx - 2*WTOP;
            int n = q / FF, k = q % FF;
            g_Whb[q] = __float2half_rn(Whead[(size_t)(DD + k)*DD + n]);
        } else {
            int q = idx - 2*WTOP - WBOT;
            int n = q / FF, k = q % FF;
            g_Wtb[q] = __float2half_rn(Wtail[(size_t)(DD + k)*DD + n]);
        }
    }
}

// ================= shared HMMA helpers =================
#define SW128(o) ((o) ^ (((o) >> 3) & 0x70))
#define TILE_BYTES 16384
#define HG_SMEM (2*2*TILE_BYTES + 1024)

__device__ __forceinline__ char* align1k(char* p)
{
    return (char*)((((uintptr_t)p) + 1023) & ~(uintptr_t)1023);
}

__device__ __forceinline__ void ldm4(uint32_t* r, uint32_t addr)
{
    asm volatile("ldmatrix.sync.aligned.m8n8.x4.shared.b16 {%0,%1,%2,%3}, [%4];"
                 : "=r"(r[0]), "=r"(r[1]), "=r"(r[2]), "=r"(r[3]) : "r"(addr));
}
__device__ __forceinline__ void mma16816(float* c, const uint32_t* a, const uint32_t* b)
{
    asm volatile("mma.sync.aligned.m16n8k16.row.col.f32.f16.f16.f32 "
                 "{%0,%1,%2,%3}, {%4,%5,%6,%7}, {%8,%9}, {%0,%1,%2,%3};"
                 : "+f"(c[0]), "+f"(c[1]), "+f"(c[2]), "+f"(c[3])
                 : "r"(a[0]), "r"(a[1]), "r"(a[2]), "r"(a[3]), "r"(b[0]), "r"(b[1]));
}

// ---------------- NT fp16 HMMA GEMM body (dual pair via z) ----------------
__device__ __noinline__ void hgemm_body(char* dsm_raw, int nx, int my, int z,
                                        const __half* __restrict__ A, int lda,
                                        const __half* __restrict__ B0T,
                                        const __half* __restrict__ B1T, int ldb,
                                        const float* __restrict__ bias0,
                                        const float* __restrict__ bias1,
                                        float* __restrict__ C0,
                                        float* __restrict__ C1,
                                        int M, int ldc, int Kd)
{
    char* smem = align1k(dsm_raw);
    uint32_t sbase = (uint32_t)__cvta_generic_to_shared(smem);
    const __half* Bt  = z ? B1T : B0T;
    const float* bias = z ? bias1 : bias0;
    float* C          = z ? C1 : C0;
    const int n0 = nx * 128;
    const int m0 = my * 128;
    const int tid = threadIdx.x;
    const int lane = tid & 31, wid = tid >> 5;
    const int wm = (wid & 3) * 32;
    const int wn = (wid >> 2) * 64;

    const __half* Abase = A + (size_t)m0*lda;
    const __half* Bbase = Bt + (size_t)n0*ldb;

    float acc[2][8][4];
    #pragma unroll
    for (int mi = 0; mi < 2; mi++)
        #pragma unroll
        for (int ni = 0; ni < 8; ni++)
            #pragma unroll
            for (int j = 0; j < 4; j++) acc[mi][ni][j] = 0.f;

    auto fill = [&](int it, int buf) {
        int k0 = it * 64;
        uint32_t abase = sbase + buf*2*TILE_BYTES;
        uint32_t bbase = abase + TILE_BYTES;
        #pragma unroll
        for (int j = 0; j < 8; j++) {
            int c = tid + j*256;
            if (c < 1024) {
                int r = c >> 3, q = c & 7;
                cp16(abase + SW128(r*128 + q*16), Abase + (size_t)r*lda + k0 + q*8);
            } else {
                int c2 = c - 1024;
                int r = c2 >> 3, q = c2 & 7;
                cp16(bbase + SW128(r*128 + q*16), Bbase + (size_t)r*ldb + k0 + q*8);
            }
        }
    };

    int nstage = Kd >> 6;
    fill(0, 0);
    asm volatile("cp.async.commit_group;");

    for (int i = 0; i < nstage; i++) {
        if (i + 1 < nstage) {
            fill(i + 1, (i + 1) & 1);
            asm volatile("cp.async.commit_group;");
            asm volatile("cp.async.wait_group 1;");
        } else {
            asm volatile("cp.async.wait_group 0;");
        }
        __syncthreads();

        uint32_t abase = sbase + (i & 1)*2*TILE_BYTES;
        uint32_t bbase = abase + TILE_BYTES;
        #pragma unroll
        for (int ks = 0; ks < 4; ks++) {
            uint32_t af[2][4];
            #pragma unroll
            for (int mi = 0; mi < 2; mi++) {
                int row = wm + mi*16 + ((lane >> 3) & 1)*8 + (lane & 7);
                int cb  = ks*32 + (lane >> 4)*16;
                ldm4(af[mi], abase + SW128(row*128 + cb));
            }
            uint32_t bf[8][2];
            #pragma unroll
            for (int q = 0; q < 4; q++) {
                uint32_t r[4];
                int nrow = wn + (2*q + (lane >> 4))*8 + (lane & 7);
                int cb   = ks*32 + ((lane >> 3) & 1)*16;
                ldm4(r, bbase + SW128(nrow*128 + cb));
                bf[2*q+0][0] = r[0]; bf[2*q+0][1] = r[1];
                bf[2*q+1][0] = r[2]; bf[2*q+1][1] = r[3];
            }
            #pragma unroll
            for (int mi = 0; mi < 2; mi++)
                #pragma unroll
                for (int ni = 0; ni < 8; ni++)
                    mma16816(acc[mi][ni], af[mi], bf[ni]);
        }
        __syncthreads();
    }

    #pragma unroll
    for (int mi = 0; mi < 2; mi++) {
        int r0 = m0 + wm + mi*16 + (lane >> 2);
        #pragma unroll
        for (int ni = 0; ni < 8; ni++) {
            int cb = n0 + wn + ni*8 + (lane & 3)*2;
            float b0 = bias ? bias[cb] : 0.f;
            float b1 = bias ? bias[cb+1] : 0.f;
            if (r0 < M) {
                float2 v = make_float2(acc[mi][ni][0] + b0, acc[mi][ni][1] + b1);
                *(float2*)&C[(size_t)r0*ldc + cb] = v;
            }
            if (r0 + 8 < M) {
                float2 v = make_float2(acc[mi][ni][2] + b0, acc[mi][ni][3] + b1);
                *(float2*)&C[(size_t)(r0+8)*ldc + cb] = v;
            }
        }
    }
}

// ---------------- fp32 SGEMM body for t1 ----------------
__device__ __noinline__ void sgemm_body(char* dsm_raw, int bx, int by,
                                        const float* __restrict__ A, int lda,
                                        const float* __restrict__ B, int ldb,
                                        const float* __restrict__ bias,
                                        float* __restrict__ C, int ldc, int Kd)
{
    char* dsm = align1k(dsm_raw);
    float* As = (float*)dsm;          // [2][64][32]
    float* Bs = As + 4096;            // [2][32][68]
    uint32_t sA = (uint32_t)__cvta_generic_to_shared(As);
    uint32_t sB = (uint32_t)__cvta_generic_to_shared(Bs);
    int m0 = by * 64, n0 = bx * 64;
    int tid = threadIdx.x;
    int ty = tid >> 4, tx = tid & 15;
    float acc[4][4];
    #pragma unroll
    for (int i = 0; i < 4; i++)
        #pragma unroll
        for (int j = 0; j < 4; j++) acc[i][j] = 0.f;

    int nstage = Kd >> 5;
    auto fill = [&](int s, int k0) {
        #pragma unroll
        for (int j = 0; j < 2; j++) {
            int c = tid + j*256;
            int r = c >> 3, q = c & 7;
            cp16(sA + (uint32_t)(s*2048 + r*32 + q*4)*4,
                 A + (size_t)(m0 + r)*lda + k0 + q*4);
            int rb = c >> 4, qb = c & 15;
            cp16(sB + (uint32_t)(s*2176 + rb*68 + qb*4)*4,
                 B + (size_t)(k0 + rb)*ldb + n0 + qb*4);
        }
        asm volatile("cp.async.commit_group;");
    };

    fill(0, 0);
    for (int s = 0; s < nstage; s++) {
        if (s + 1 < nstage) {
            fill((s + 1) & 1, (s + 1) << 5);
            asm volatile("cp.async.wait_group 1;");
        } else {
            asm volatile("cp.async.wait_group 0;");
        }
        __syncthreads();
        int bs = s & 1;
        #pragma unroll
        for (int k4 = 0; k4 < 8; k4++) {
            float4 a4[4];
            #pragma unroll
            for (int i = 0; i < 4; i++)
                a4[i] = *(const float4*)&As[bs*2048 + (ty*4 + i)*32 + k4*4];
            #pragma unroll
            for (int kk = 0; kk < 4; kk++) {
                float4 b4 = *(const float4*)&Bs[bs*2176 + (k4*4 + kk)*68 + tx*4];
                float a0 = (&a4[0].x)[kk], a1 = (&a4[1].x)[kk],
                      a2 = (&a4[2].x)[kk], a3 = (&a4[3].x)[kk];
                acc[0][0] += a0*b4.x; acc[0][1] += a0*b4.y; acc[0][2] += a0*b4.z; acc[0][3] += a0*b4.w;
                acc[1][0] += a1*b4.x; acc[1][1] += a1*b4.y; acc[1][2] += a1*b4.z; acc[1][3] += a1*b4.w;
                acc[2][0] += a2*b4.x; acc[2][1] += a2*b4.y; acc[2][2] += a2*b4.z; acc[2][3] += a2*b4.w;
                acc[3][0] += a3*b4.x; acc[3][1] += a3*b4.y; acc[3][2] += a3*b4.z; acc[3][3] += a3*b4.w;
            }
        }
        __syncthreads();
    }
    #pragma unroll
    for (int i = 0; i < 4; i++) {
        int row = m0 + ty*4 + i;
        #pragma unroll
        for (int j = 0; j < 4; j++) {
            int col = n0 + tx*4 + j;
            C[(size_t)row*ldc + col] = fasttanh(acc[i][j] + bias[col]);
        }
    }
}

// ---------------- combo1: hgemm Th/Tt | t1 sgemm | htx + bconv ----------------
#define C1_HG 132
#define C1_T1 84
#define C1_HTX (NE*NE*BBS)
#define C1_BLKS (C1_HG + C1_T1 + C1_HTX)
#define BCONV_BLOCKS (861*BBS)
#define BCONV_N4     ((size_t)KK*DD*DD/4)
#define BCONV_CHUNK  ((BCONV_N4 + BCONV_BLOCKS - 1)/BCONV_BLOCKS)

__global__ __launch_bounds__(256) void k_combo1(const float* __restrict__ Wattn,
                                                const float* __restrict__ battn,
                                                const float* __restrict__ blin,
                                                const float* __restrict__ bil)
{
    extern __shared__ char dsm[];
    int bid = blockIdx.x;
    int tid = threadIdx.x;
    if (bid < C1_HG) {
        int z = bid / 66, r = bid % 66;
        hgemm_body(dsm, r % 6, r / 6, z, g_embh, DD, g_Whh, g_Wth, DD,
                   nullptr, nullptr, g_Th, g_Tt, MEMB, DD, DD);
        return;
    }
    if (bid < C1_HG + C1_T1) {
        int q = bid - C1_HG;
        sgemm_body(dsm, q % 4, q / 4, g_emb, DD, Wattn, RR, battn, g_t1, RR, DD);
        return;
    }
    int q = bid - C1_HG - C1_T1;
    int b = q / (NE*NE);
    int rem = q % (NE*NE);
    int i = rem / NE, j = rem % NE;
    if (j < i) {
        size_t qc = (size_t)b*861 + (size_t)i*(i-1)/2 + j;
        size_t beg = qc*BCONV_CHUNK;
        size_t end = beg + BCONV_CHUNK;
        if (end > BCONV_N4) end = BCONV_N4;
        __half2* ph = (__half2*)g_Bhi;
        for (size_t i4 = beg + tid; i4 < end; i4 += 256) {
            float4 v = ((const float4*)bil)[i4];
            ph[i4*2+0] = __floats2half2_rn(v.x, v.y);
            ph[i4*2+1] = __floats2half2_rn(v.z, v.w);
        }
        return;
    }
    const float* ai = g_as + ((size_t)(b*NE + i))*LL*HH;
    const float* aj = g_as + ((size_t)(b*NE + j))*LL*HH;
    const float* s3 = g_S3 + b*LL*3;
    float sum = 0.f, x0 = 0.f, x1 = 0.f, x2 = 0.f;
    for (int l = tid; l < LL; l += 256) {
        float4 u0 = *(const float4*)&ai[l*HH + 0];
        float4 u1 = *(const float4*)&ai[l*HH + 4];
        float4 u2 = *(const float4*)&ai[l*HH + 8];
        float4 v0 = *(const float4*)&aj[l*HH + 0];
        float4 v1 = *(const float4*)&aj[l*HH + 4];
        float4 v2 = *(const float4*)&aj[l*HH + 8];
        float acc = u0.x*v0.x + u0.y*v0.y + u0.z*v0.z + u0.w*v0.w
                  + u1.x*v1.x + u1.y*v1.y + u1.z*v1.z + u1.w*v1.w
                  + u2.x*v2.x + u2.y*v2.y + u2.z*v2.z + u2.w*v2.w;
        acc *= (1.0f / HH);
        sum += acc;
        x0 += acc * s3[l*3+0];
        x1 += acc * s3[l*3+1];
        x2 += acc * s3[l*3+2];
    }
    __shared__ __align__(16) float red[4][256];
    red[0][tid] = sum; red[1][tid] = x0; red[2][tid] = x1; red[3][tid] = x2;
    __syncthreads();
    for (int s2 = 128; s2 > 0; s2 >>= 1) {
        if (tid < s2) {
            red[0][tid] += red[0][tid+s2];
            red[1][tid] += red[1][tid+s2];
            red[2][tid] += red[2][tid+s2];
            red[3][tid] += red[3][tid+s2];
        }
        __syncthreads();
    }
    if (tid == 0) {
        float inv = 1.0f / (red[0][0] + 1e-5f);
        float v0 = red[1][0]*inv + blin[0];
        float v1 = red[2][0]*inv + blin[1];
        float v2 = red[3][0]*inv + blin[2];
        float* xo = g_x + ((b*NE + i)*NE + j)*3;
        xo[0] = v0; xo[1] = v1; xo[2] = v2;
        float* xm = g_x + ((b*NE + j)*NE + i)*3;
        xm[0] = v0; xm[1] = v1; xm[2] = v2;
    }
}

// ---------------- combo2: scsm (512 thr) | htss ----------------
__global__ __launch_bounds__(512) void k_combo2(const float* __restrict__ mask,
                                                const int* __restrict__ pairs,
                                                const float* __restrict__ Wseg,
                                                const float* __restrict__ bseg)
{
    int tid = threadIdx.x;
    if (blockIdx.x < BBS*NE) {
        int be = blockIdx.x;
        int qq = tid >> 7;
        int kx = tid & 127;
        __shared__ __align__(16) float st[NM*RR];
        __shared__ __align__(16) float sp[4][128*NM];
        for (int i = tid; i < NM*RR/4; i += 512)
            *(float4*)&st[i*4] = *(const float4*)&g_t1[(size_t)be*NM*RR + i*4];
        __syncthreads();
        float sc[NM];
        #pragma unroll
        for (int m = 0; m < NM; m++) sc[m] = 0.f;
        int j0 = qq*64;
        for (int j = j0; j < j0 + 64; j++) {
            float a = g_anT[j*128 + kx];
            #pragma unroll
            for (int m = 0; m < NM; m++) sc[m] += st[m*RR + j] * a;
        }
        #pragma unroll
        for (int m = 0; m < NM; m++) sp[qq][kx*NM + m] = sc[m];
        __syncthreads();
        if (tid < KK) {
            float s2[NM];
            #pragma unroll
            for (int m = 0; m < NM; m++)
                s2[m] = ((sp[0][tid*NM + m] + sp[1][tid*NM + m])
                       + (sp[2][tid*NM + m] + sp[3][tid*NM + m]))
                      + (1.0f - mask[be*NM + m]) * (-1e6f);
            float mx = s2[0];
            #pragma unroll
            for (int m = 1; m < NM; m++) mx = fmaxf(mx, s2[m]);
            float ssum = 0.f;
            #pragma unroll
            for (int m = 0; m < NM; m++) { s2[m] = expf(s2[m] - mx); ssum += s2[m]; }
            float inv = 1.0f / ssum;
            #pragma unroll
            for (int m = 0; m < NM; m++) g_w[(be*KK + tid)*NM + m] = s2[m]*inv;
        }
        return;
    }
    int n = blockIdx.x - BBS*NE;
    int b = n >> 7;
    __shared__ int shi, sti;
    __shared__ __align__(16) float sx[27];
    if (tid == 0) { shi = pairs[n*2]; sti = pairs[n*2+1]; }
    __syncthreads();
    if (tid < 27) {
        int dy = tid / 9, dx = (tid / 3) % 3, c = tid % 3;
        int ii = shi + dy - 1, jj = sti + dx - 1;
        sx[tid] = (ii >= 0 && ii < NE && jj >= 0 && jj < NE)
                  ? g_x[((b*NE + ii)*NE + jj)*3 + c] : 0.f;
    }
    __syncthreads();
    if (tid < FF) {
        float acc = bseg[tid];
        #pragma unroll
        for (int t = 0; t < 27; t++) acc += sx[t] * Wseg[t*FF + tid];
        g_htssh[n*FF + tid] = __float2half_rn(fmaxf(acc, 0.f));
    }
}

// ---------------- standalone hgemm wrapper (Rh/Rt) ----------------
__global__ __launch_bounds__(256) void k_hgemm2(const float* __restrict__ bhead,
                                                const float* __restrict__ btail)
{
    extern __shared__ char dsm[];
    hgemm_body(dsm, blockIdx.x, blockIdx.y, blockIdx.z,
               g_htssh, FF, g_Whb, g_Wtb, FF, bhead, btail, g_Rh, g_Rt, NP, DD, FF);
}

// ---------------- K10: hs,ts -> fp16, k-range split ----------------
__global__ __launch_bounds__(256) void k_hsts(const int* __restrict__ pairs)
{
    int n = blockIdx.x;
    int b = n >> 7;
    int kh = blockIdx.y;
    int kbeg = kh ? 49 : 0;
    int kend = kh ? KK : 49;
    int tid = threadIdx.x;
    __shared__ __align__(16) float sT[2*NM*DD];
    int hi = pairs[n*2], ti = pairs[n*2+1];
    const float* Th = g_Th + (b*NE + hi)*NM*DD;
    const float* Tt = g_Tt + (b*NE + ti)*NM*DD;
    for (int idx = tid; idx < NM*DD; idx += 256) {
        sT[idx]         = Th[idx];
        sT[NM*DD + idx] = Tt[idx];
    }
    float rh[3], rt[3];
    #pragma unroll
    for (int i2 = 0; i2 < 3; i2++) {
        rh[i2] = g_Rh[n*DD + tid + i2*256];
        rt[i2] = g_Rt[n*DD + tid + i2*256];
    }
    __syncthreads();
    const float4* wh4 = (const float4*)(g_w + (size_t)(b*NE + hi)*KK*NM);
    const float4* wt4 = (const float4*)(g_w + (size_t)(b*NE + ti)*KK*NM);
    for (int k = kbeg; k < kend; k++) {
        float4 wh0 = __ldg(&wh4[k*2]),   wh1 = __ldg(&wh4[k*2+1]);
        float4 wt0 = __ldg(&wt4[k*2]),   wt1 = __ldg(&wt4[k*2+1]);
        float whr[NM] = {wh0.x, wh0.y, wh0.z, wh0.w, wh1.x, wh1.y, wh1.z, wh1.w};
        float wtr[NM] = {wt0.x, wt0.y, wt0.z, wt0.w, wt1.x, wt1.y, wt1.z, wt1.w};
        #pragma unroll
        for (int i2 = 0; i2 < 3; i2++) {
            int d = tid + i2*256;
            float ah = rh[i2], at2 = rt[i2];
            #pragma unroll
            for (int m = 0; m < NM; m++) {
                ah  += whr[m] * sT[m*DD + d];
                at2 += wtr[m] * sT[NM*DD + m*DD + d];
            }
            size_t o = (size_t)(n*KK + k)*DD + d;
            g_hsh[o]  = __float2half_rn(fasttanh(ah));
            g_tshi[o] = __float2half_rn(fasttanh(at2));
        }
    }
}

// ================= HMMA bilinear core =================
#define SH_PITCH 132
#define SMEM_DYN (128*SH_PITCH*4 + 128*2*4 + 1024)

__global__ __launch_bounds__(256) void k_bilinear_mma()
{
    extern __shared__ char dsm[];
    char* smem = align1k(dsm);
    uint32_t sbase = (uint32_t)__cvta_generic_to_shared(smem);

    const int k  = blockIdx.y;
    const int nt = blockIdx.x & 3;
    const int dt = blockIdx.x >> 2;
    const int n0 = nt * 128, d0 = dt * 128;
    const int tid = threadIdx.x;
    const int lane = tid & 31, wid = tid >> 5;
    const int wm = (wid & 3) * 32;
    const int wn = (wid >> 2) * 64;

    const __half* Abase = g_tshi + ((size_t)n0 * KK + k) * DD;
    const __half* Bbase = g_Bhi + ((size_t)k * DD + d0) * DD;

    float acc[2][8][4];
    #pragma unroll
    for (int mi = 0; mi < 2; mi++)
        #pragma unroll
        for (int ni = 0; ni < 8; ni++)
            #pragma unroll
            for (int j = 0; j < 4; j++) acc[mi][ni][j] = 0.f;

    auto fill = [&](int it, int buf) {
        int k0 = it * 64;
        uint32_t abase = sbase + buf*2*TILE_BYTES;
        uint32_t bbase = abase + TILE_BYTES;
        #pragma unroll
        for (int j = 0; j < 8; j++) {
            int c = tid + j*256;
            if (c < 1024) {
                int r = c >> 3, q = c & 7;
                cp16(abase + SW128(r*128 + q*16), Abase + (size_t)r*(KK*DD) + k0 + q*8);
            } else {
                int c2 = c - 1024;
                int r = c2 >> 3, q = c2 & 7;
                cp16(bbase + SW128(r*128 + q*16), Bbase + (size_t)r*DD + k0 + q*8);
            }
        }
    };

    fill(0, 0);
    asm volatile("cp.async.commit_group;");

    for (int i = 0; i < 12; i++) {
        if (i + 1 < 12) {
            fill(i + 1, (i + 1) & 1);
            asm volatile("cp.async.commit_group;");
            asm volatile("cp.async.wait_group 1;");
        } else {
            asm volatile("cp.async.wait_group 0;");
        }
        __syncthreads();

        uint32_t abase = sbase + (i & 1)*2*TILE_BYTES;
        uint32_t bbase = abase + TILE_BYTES;
        #pragma unroll
        for (int ks = 0; ks < 4; ks++) {
            uint32_t af[2][4];
            #pragma unroll
            for (int mi = 0; mi < 2; mi++) {
                int row = wm + mi*16 + ((lane >> 3) & 1)*8 + (lane & 7);
                int cb  = ks*32 + (lane >> 4)*16;
                ldm4(af[mi], abase + SW128(row*128 + cb));
            }
            uint32_t bf[8][2];
            #pragma unroll
            for (int q = 0; q < 4; q++) {
                uint32_t r[4];
                int nrow = wn + (2*q + (lane >> 4))*8 + (lane & 7);
                int cb   = ks*32 + ((lane >> 3) & 1)*16;
                ldm4(r, bbase + SW128(nrow*128 + cb));
                bf[2*q+0][0] = r[0]; bf[2*q+0][1] = r[1];
                bf[2*q+1][0] = r[2]; bf[2*q+1][1] = r[3];
            }
            #pragma unroll
            for (int mi = 0; mi < 2; mi++)
                #pragma unroll
                for (int ni = 0; ni < 8; ni++)
                    mma16816(acc[mi][ni], af[mi], bf[ni]);
        }
        __syncthreads();
    }

    float* sH  = (float*)smem;
    float* red = (float*)(smem + 128*SH_PITCH*4);
    for (int idx = tid; idx < 128*16; idx += 256) {
        int r = idx >> 4, c8 = idx & 15;
        const __half2* hp = (const __half2*)(g_hsh + ((size_t)(n0 + r)*KK + k)*DD + d0 + c8*8);
        float* dst = &sH[r*SH_PITCH + c8*8];
        #pragma unroll
        for (int u = 0; u < 4; u++) {
            float2 f = __half22float2(hp[u]);
            dst[u*2+0] = f.x; dst[u*2+1] = f.y;
        }
    }
    __syncthreads();

    float p[2][2] = {{0.f, 0.f}, {0.f, 0.f}};
    #pragma unroll
    for (int mi = 0; mi < 2; mi++) {
        int r0 = wm + mi*16 + (lane >> 2);
        #pragma unroll
        for (int ni = 0; ni < 8; ni++) {
            int cb = wn + ni*8 + (lane & 3)*2;
            p[mi][0] += acc[mi][ni][0]*sH[r0*SH_PITCH + cb]
                      + acc[mi][ni][1]*sH[r0*SH_PITCH + cb + 1];
            p[mi][1] += acc[mi][ni][2]*sH[(r0+8)*SH_PITCH + cb]
                      + acc[mi][ni][3]*sH[(r0+8)*SH_PITCH + cb + 1];
        }
    }
    #pragma unroll
    for (int mi = 0; mi < 2; mi++)
        #pragma unroll
        for (int h = 0; h < 2; h++) {
            p[mi][h] += __shfl_xor_sync(0xffffffffu, p[mi][h], 1);
            p[mi][h] += __shfl_xor_sync(0xffffffffu, p[mi][h], 2);
        }
    if ((lane & 3) == 0) {
        int nw = wid >> 2;
        int rr = lane >> 2;
        #pragma unroll
        for (int mi = 0; mi < 2; mi++) {
            red[(wm + mi*16 + rr)*2 + nw]     = p[mi][0];
            red[(wm + mi*16 + rr + 8)*2 + nw] = p[mi][1];
        }
    }
    __syncthreads();
    if (tid < 128)
        g_part[((size_t)dt*NP + n0 + tid)*KK + k] = red[tid*2] + red[tid*2+1];
}

// ---------------- K13: finalize ----------------
__global__ void k_final(const float* __restrict__ bilb, float* __restrict__ out)
{
    int idx = blockIdx.x*256 + threadIdx.x;
    if (idx >= NP*KK) return;
    int k = idx % KK;
    float s = bilb[k];
    #pragma unroll
    for (int t = 0; t < 6; t++) s += g_part[t*(NP*KK) + idx];
    out[idx] = s;
}

// ---------------- launch ----------------
extern "C" void kernel_launch(void* const* d_in, const int* in_sizes, int n_in,
                              void* d_out, int out_size)
{
    const float* seq      = (const float*)d_in[0];
    const float* att      = (const float*)d_in[1];
    const float* mask     = (const float*)d_in[2];
    const int*   mpos     = (const int*)  d_in[3];
    const int*   pairs    = (const int*)  d_in[4];
    const float* Wattn    = (const float*)d_in[5];
    const float* battn    = (const float*)d_in[6];
    const float* attn_net = (const float*)d_in[7];
    const float* Wlin     = (const float*)d_in[8];
    const float* blin     = (const float*)d_in[9];
    const float* Wseg     = (const float*)d_in[10];
    const float* bseg     = (const float*)d_in[11];
    const float* Whead    = (const float*)d_in[12];
    const float* bhead    = (const float*)d_in[13];
    const float* Wtail    = (const float*)d_in[14];
    const float* btail    = (const float*)d_in[15];
    const float* bil      = (const float*)d_in[16];
    const float* bilb     = (const float*)d_in[17];
    float* out = (float*)d_out;

    cudaFuncSetAttribute(k_bilinear_mma, cudaFuncAttributeMaxDynamicSharedMemorySize, SMEM_DYN);
    cudaFuncSetAttribute(k_combo1, cudaFuncAttributeMaxDynamicSharedMemorySize, HG_SMEM);
    cudaFuncSetAttribute(k_hgemm2, cudaFuncAttributeMaxDynamicSharedMemorySize, HG_SMEM);

    // 1. fused prep (gather | as | antr | S3 | pad | weight fp16 convert)
    k_prep<<<PREP_BLKS, 256>>>(seq, att, mask, mpos, attn_net, Wlin, Whead, Wtail);
    // 2. combo1: hgemm Th/Tt | t1 | htx + bconv
    k_combo1<<<C1_BLKS, 256, HG_SMEM>>>(Wattn, battn, blin, bil);
    // 3. combo2: scsm | htss
    k_combo2<<<BBS*NE + NP, 512>>>(mask, pairs, Wseg, bseg);
    // 4. Rh / Rt via fp16 HMMA
    k_hgemm2<<<dim3(DD/128, NP/128, 2), 256, HG_SMEM>>>(bhead, btail);
    // 5. hs,ts fp16 (k-range split x2)
    k_hsts<<<dim3(NP, 2), 256>>>(pairs);
    // 6. HMMA bilinear
    k_bilinear_mma<<<dim3(24, 97), 256, SMEM_DYN>>>();
    // 7. finalize
    k_final<<<(NP*KK + 255)/256, 256>>>(bilb, out);
}